// round 4
// baseline (speedup 1.0000x reference)
#include <cuda_runtime.h>
#include <math.h>

// PSLoss: 0.5*MSE + 0.5*avg(structural patch loss)
// B=64, T=336, F=321. 20544 series of length 336 (stride F in memory).
// Spectrum: Cooley-Tukey 336 = 16 x 21 (real-input symmetry).
// Patch stats: fp32 cumsum with jax lax.associative_scan tree bracketing,
// segment sums as cs[e]-cs[s], exactly matching the reference arithmetic.

#define TT      336
#define FDIM    321
#define BDIM    64
#define NBIN    168
#define SP      17        // series pitch (16 + 1)
#define NTHREADS 512
#define FTILES  21        // ceil(321/16)
#define TASKP   80        // 5 quantities x 16 series

// float-index smem offsets
#define OFF_TG    0                    // 336*17 = 5712
#define OFF_FC    5712                 // 5712
#define OFF_U     11424                // union: FFT scratch (8840) / pyramid (26640)
#define OFF_TW336 38064                // 336 float2 = 672
#define OFF_TW21  38736                // 24 float2 = 48
#define OFF_PP    38784                // 48 ints
#define OFF_FLAG  38832                // 16 ints
#define OFF_REDD  38848                // 2 doubles
#define OFF_REDC  38852                // 1 u64
#define SMEM_FLOATS 38856
#define SMEM_BYTES  (SMEM_FLOATS * 4)

__device__ double g_loss;
__device__ double g_mse;
__device__ unsigned long long g_cnt;

__global__ void ps_init() { g_loss = 0.0; g_mse = 0.0; g_cnt = 0ull; }

__global__ void ps_final(float* out) {
    double mse = g_mse / (double)((long long)BDIM * TT * FDIM);
    double avg = (g_cnt > 0ull) ? (g_loss / (double)g_cnt) : 0.0;
    out[0] = (float)(0.5 * mse + 0.5 * avg);
}

__device__ __forceinline__ float prodq(float a, float v, int q) {
    switch (q) {
        case 0:  return a;
        case 1:  return v;
        case 2:  return __fmul_rn(a, a);
        case 3:  return __fmul_rn(v, v);
        default: return __fmul_rn(a, v);
    }
}

__global__ void __launch_bounds__(NTHREADS, 1)
ps_main(const float* __restrict__ fc, const float* __restrict__ tg) {
    extern __shared__ float sm[];
    float*  tgS   = sm + OFF_TG;
    float*  fcS   = sm + OFF_FC;
    float*  Pyr   = sm + OFF_U;                 // pyramid levels 1..8 (333 rows x 80)
    float2* yS    = (float2*)(sm + OFF_U);      // FFT scratch (overlaid, earlier phase)
    float*  ampS  = sm + OFF_U + 5984;
    float2* tw336 = (float2*)(sm + OFF_TW336);
    float2* tw21  = (float2*)(sm + OFF_TW21);
    int*    pP    = (int*)(sm + OFF_PP);
    int*    flagS = (int*)(sm + OFF_FLAG);
    double* redD  = (double*)(sm + OFF_REDD);
    unsigned long long* redC = (unsigned long long*)(sm + OFF_REDC);

    const int tid = threadIdx.x;
    const int b   = blockIdx.x / FTILES;
    const int f0  = (blockIdx.x % FTILES) * 16;

    if (tid == 0) { redD[0] = 0.0; redD[1] = 0.0; redC[0] = 0ull; }

    for (int i = tid; i < TT; i += NTHREADS) {
        double a = 6.283185307179586476925287 * (double)i / (double)TT;
        tw336[i] = make_float2((float)cos(a), (float)sin(a));
    }
    if (tid < 21) {
        double a = 6.283185307179586476925287 * (double)tid / 21.0;
        tw21[tid] = make_float2((float)cos(a), (float)sin(a));
    }

    // ---- Load tile + MSE partial ----
    float mseAcc = 0.f;
    {
        const size_t base = (size_t)b * TT * FDIM + f0;
        for (int i = tid; i < TT * 16; i += NTHREADS) {
            int t = i >> 4, l = i & 15;
            float av = 0.f, bv = 0.f;
            if (f0 + l < FDIM) {
                size_t g = base + (size_t)t * FDIM + l;
                av = tg[g]; bv = fc[g];
                float d = bv - av;
                mseAcc = fmaf(d, d, mseAcc);
            }
            tgS[t * SP + l] = av;
            fcS[t * SP + l] = bv;
        }
    }
    __syncthreads();

    // ---- Stage A: 21-pt DFT. tid -> (s, t1, half-of-r-range) ----
    {
        int s = tid & 15, t1 = (tid >> 4) & 15, half = tid >> 8;
        int r0 = half ? 6 : 0, nr = half ? 5 : 6;
        float yre[6], yim[6];
#pragma unroll
        for (int r = 0; r < 6; r++) { yre[r] = 0.f; yim[r] = 0.f; }
        for (int t2 = 0; t2 < 21; t2++) {
            float xv = tgS[(t1 + 16 * t2) * SP + s];
            int rt = (t2 * r0) % 21;
            for (int r = 0; r < nr; r++) {
                float2 w = tw21[rt];
                yre[r] = fmaf(xv,  w.x, yre[r]);
                yim[r] = fmaf(-xv, w.y, yim[r]);
                rt += t2; if (rt >= 21) rt -= 21;
            }
        }
        for (int r = 0; r < nr; r++)
            yS[(t1 * 11 + r0 + r) * SP + s] = make_float2(yre[r], yim[r]);
    }
    __syncthreads();

    // ---- Stage B: combine 16 subseries; store |X|^2 ----
    {
        int s = tid & 15, g = tid >> 4;
        for (int f = 1 + g; f <= NBIN; f += 32) {
            int r = f % 21;
            float sgn = 1.f; int r2 = r;
            if (r > 10) { r2 = 21 - r; sgn = -1.f; }
            float xre = 0.f, xim = 0.f;
            int idx = 0;
#pragma unroll
            for (int t1 = 0; t1 < 16; t1++) {
                float2 y = yS[(t1 * 11 + r2) * SP + s];
                float yi = y.y * sgn;
                float2 w = tw336[idx];
                xre = fmaf(y.x, w.x, fmaf(yi,  w.y, xre));
                xim = fmaf(yi,  w.x, fmaf(-y.x, w.y, xim));
                idx += f; if (idx >= TT) idx -= TT;
            }
            ampS[(f - 1) * SP + s] = xre * xre + xim * xim;
        }
    }
    __syncthreads();

    // ---- Top-3 + period metadata (16 threads) ----
    if (tid < 16) {
        int s = tid;
        float a1 = -1.f, a2 = -1.f, a3 = -1.f;
        int f1 = 1, f2 = 1, f3 = 1;
        for (int f = 1; f <= NBIN; f++) {
            float a = ampS[(f - 1) * SP + s];
            if (a > a1)      { a3 = a2; f3 = f2; a2 = a1; f2 = f1; a1 = a; f1 = f; }
            else if (a > a2) { a3 = a2; f3 = f2; a2 = a;  f2 = f; }
            else if (a > a3) { a3 = a;  f3 = f; }
        }
        int pp[3] = { TT / f1, TT / f2, TT / f3 };
        bool active = (f0 + s) < FDIM;
        bool valid[3];
        valid[0] = active && pp[0] >= 5;
        valid[1] = active && pp[1] >= 5 && pp[1] != pp[0];
        valid[2] = active && pp[2] >= 5 && pp[2] != pp[0] && pp[2] != pp[1];
        int ns[3], L[3]; bool remv[3];
#pragma unroll
        for (int k = 0; k < 3; k++) {
            ns[k] = TT / pp[k];
            L[k]  = TT - ns[k] * pp[k];
            remv[k] = valid[k] && (L[k] >= 5);
        }
        int flags = 0;
#pragma unroll
        for (int k = 0; k < 3; k++) {
            if (valid[k]) flags |= (1 << k);
            bool inc = remv[k];
#pragma unroll
            for (int j = 0; j < 3; j++) {
                if (valid[j] && pp[j] == L[k] && (TT % pp[j]) == 0) inc = false;
                if (j < k && remv[j] && L[j] == L[k]) inc = false;
            }
            if (inc) flags |= (8 << k);
        }
        if (active && !(valid[0] || valid[1] || valid[2])) flags |= 64;
#pragma unroll
        for (int k = 0; k < 3; k++) pP[k * 16 + s] = pp[k];
        flagS[s] = flags;
    }
    __syncthreads();

    // ---- Upsweep: pair-sum pyramid (associative_scan tree), 5 q x 16 s ----
    // Level offsets in Pyr: L1=0(168) L2=168(84) L3=252(42) L4=294(21)
    //                       L5=315(10) L6=325(5) L7=330(2) L8=332(1)
    for (int i = tid; i < 168 * TASKP; i += NTHREADS) {
        int j = i / TASKP, task = i - j * TASKP;
        int q = task >> 4, s = task & 15;
        int u = 2 * j;
        float x0 = prodq(tgS[u * SP + s],       fcS[u * SP + s],       q);
        float x1 = prodq(tgS[(u + 1) * SP + s], fcS[(u + 1) * SP + s], q);
        Pyr[i] = __fadd_rn(x0, x1);
    }
    __syncthreads();
    {
        const int srcO[7] = { 0, 168, 252, 294, 315, 325, 330 };
        const int dstO[7] = { 168, 252, 294, 315, 325, 330, 332 };
        const int lenL[7] = { 84, 42, 21, 10, 5, 2, 1 };
        for (int L = 0; L < 7; L++) {
            for (int i = tid; i < lenL[L] * TASKP; i += NTHREADS) {
                int j = i / TASKP, task = i - j * TASKP;
                Pyr[(dstO[L] + j) * TASKP + task] =
                    __fadd_rn(Pyr[(srcO[L] + 2 * j) * TASKP + task],
                              Pyr[(srcO[L] + 2 * j + 1) * TASKP + task]);
            }
            __syncthreads();
        }
    }
    // ---- Downsweep (in place): level arrays become inclusive scans ----
    {
        const int dstO[7] = { 330, 325, 315, 294, 252, 168, 0 };
        const int parO[7] = { 332, 330, 325, 315, 294, 252, 168 };
        const int lenL[7] = { 2, 5, 10, 21, 42, 84, 168 };
        for (int L = 0; L < 7; L++) {
            for (int i = tid; i < lenL[L] * TASKP; i += NTHREADS) {
                int j = i / TASKP, task = i - j * TASKP;
                if (j == 0) continue;  // scan[0] = elem[0], already in place
                float v;
                if (j & 1)
                    v = Pyr[(parO[L] + ((j - 1) >> 1)) * TASKP + task];
                else
                    v = __fadd_rn(Pyr[(parO[L] + (j >> 1) - 1) * TASKP + task],
                                  Pyr[(dstO[L] + j) * TASKP + task]);
                Pyr[(dstO[L] + j) * TASKP + task] = v;
            }
            __syncthreads();
        }
    }

    // ---- Walk: patch losses via cs[e]-cs[s] with reference arithmetic ----
    double lossAcc = 0.0; unsigned int cnt = 0u;
    {
        int s = tid & 15, slot = (tid >> 4) & 3, sub = tid >> 6;
        int flags = flagS[s];

        // inclusive scan value at position u (cs[u+1]); -1 -> 0
        auto s0v = [&](int q, int u) -> float {
            if (u < 0) return 0.f;
            if (u & 1) return Pyr[((u - 1) >> 1) * TASKP + (q << 4) + s];
            float x = prodq(tgS[u * SP + s], fcS[u * SP + s], q);
            if (u == 0) return x;
            return __fadd_rn(Pyr[(((u >> 1) - 1)) * TASKP + (q << 4) + s], x);
        };
        auto accum = [&](int s0, int e0) {
            float n   = (float)(e0 - s0);
            float St  = __fsub_rn(s0v(0, e0 - 1), s0v(0, s0 - 1));
            float Sf  = __fsub_rn(s0v(1, e0 - 1), s0v(1, s0 - 1));
            float Stt = __fsub_rn(s0v(2, e0 - 1), s0v(2, s0 - 1));
            float Sff = __fsub_rn(s0v(3, e0 - 1), s0v(3, s0 - 1));
            float Stf = __fsub_rn(s0v(4, e0 - 1), s0v(4, s0 - 1));
            float mt  = __fdiv_rn(St, n);
            float mf  = __fdiv_rn(Sf, n);
            float tvs = fmaxf(__fsub_rn(Stt, __fmul_rn(__fmul_rn(n, mt), mt)), 0.f);
            float fvs = fmaxf(__fsub_rn(Sff, __fmul_rn(__fmul_rn(n, mf), mf)), 0.f);
            float num = __fsub_rn(Stf, __fmul_rn(__fmul_rn(n, mt), mf));
            float den = __fadd_rn(__fsqrt_rn(__fmul_rn(tvs, fvs)), 1e-8f);
            float cl  = __fsub_rn(1.f, fabsf(__fdiv_rn(num, den)));
            float nm1 = __fsub_rn(n, 1.f);
            float tvar = __fdiv_rn(tvs, nm1);
            float fvar = __fdiv_rn(fvs, nm1);
            float vl  = __fdiv_rn(fabsf(__fsub_rn(tvar, fvar)), __fadd_rn(tvar, 1e-8f));
            float ml  = __fdiv_rn(fabsf(__fsub_rn(mt, mf)), __fadd_rn(fabsf(mt), 1e-8f));
            lossAcc += (double)__fadd_rn(__fadd_rn(cl, vl), ml);
            cnt++;
        };

        if (slot < 3) {
            if ((flags >> slot) & 1) {
                int p = pP[slot * 16 + s], ns = TT / p;
                for (int j = sub; j < ns; j += 8) accum(j * p, j * p + p);
                if (sub == 7 && ((flags >> (3 + slot)) & 1)) accum(ns * p, TT);
            }
        } else {
            if (sub == 0 && (flags & 64)) accum(0, TT);
        }
    }

    // ---- Reduce ----
#pragma unroll
    for (int off = 16; off; off >>= 1) {
        lossAcc += __shfl_down_sync(0xffffffffu, lossAcc, off);
        mseAcc  += __shfl_down_sync(0xffffffffu, mseAcc,  off);
        cnt     += __shfl_down_sync(0xffffffffu, cnt,     off);
    }
    if ((tid & 31) == 0) {
        atomicAdd(&redD[0], lossAcc);
        atomicAdd(&redD[1], (double)mseAcc);
        atomicAdd(redC, (unsigned long long)cnt);
    }
    __syncthreads();
    if (tid == 0) {
        atomicAdd(&g_loss, redD[0]);
        atomicAdd(&g_mse,  redD[1]);
        atomicAdd(&g_cnt,  redC[0]);
    }
}

extern "C" void kernel_launch(void* const* d_in, const int* in_sizes, int n_in,
                              void* d_out, int out_size) {
    const float* forecast = (const float*)d_in[0];
    const float* target   = (const float*)d_in[1];
    float* out = (float*)d_out;

    ps_init<<<1, 1>>>();
    cudaFuncSetAttribute(ps_main, cudaFuncAttributeMaxDynamicSharedMemorySize, SMEM_BYTES);
    ps_main<<<BDIM * FTILES, NTHREADS, SMEM_BYTES>>>(forecast, target);
    ps_final<<<1, 1>>>(out);
}

// round 5
// speedup vs baseline: 1.5091x; 1.5091x over previous
#include <cuda_runtime.h>
#include <math.h>

// PSLoss: 0.5*MSE + 0.5*avg(structural patch loss)
// B=64, T=336, F=321. 20544 series of length 336 (stride F in memory).
// Spectrum: Cooley-Tukey 336 = 16 x 21 (real-input symmetry).
// Patch stats: fp32 cumsum with jax lax.associative_scan tree bracketing,
// segment sums as cs[e]-cs[s], exactly matching the reference arithmetic.
// R4: 8 series/block (2 blocks/SM), warp-parallel top-3, hoisted twiddles,
//     atomic-free per-block partials.

#define TT      336
#define FDIM    321
#define BDIM    64
#define NBIN    168
#define SBLK    8         // series per block
#define SP      9         // series pitch (8 + 1)
#define NTHREADS 512
#define FTILES  41        // ceil(321/8)
#define NBLK    (BDIM * FTILES)
#define TASKP   40        // 5 quantities x 8 series

// float-index smem offsets
#define OFF_TG    0                    // 336*9 = 3024
#define OFF_FC    3024                 // 3024
#define OFF_U     6048                 // union: FFT scratch / pyramid (13320)
#define OFF_TW336 19368                // 336 float2 = 672
#define OFF_TW21  20040                // 24 float2 = 48
#define OFF_PP    20088                // 24 ints (3 x 8)
#define OFF_FLAG  20112                // 8 ints
#define OFF_RED   20120                // 16 dbl + 16 dbl + 16 uint = 80 floats
#define SMEM_FLOATS 20200
#define SMEM_BYTES  (SMEM_FLOATS * 4)

__device__ float2 g_tw336[TT];
__device__ float2 g_tw21[24];
__device__ double g_partL[NBLK];
__device__ double g_partM[NBLK];
__device__ unsigned int g_partC[NBLK];

__global__ void ps_tw() {
    int i = threadIdx.x;
    if (i < TT) {
        double a = 6.283185307179586476925287 * (double)i / (double)TT;
        g_tw336[i] = make_float2((float)cos(a), (float)sin(a));
    }
    if (i < 21) {
        double a = 6.283185307179586476925287 * (double)i / 21.0;
        g_tw21[i] = make_float2((float)cos(a), (float)sin(a));
    }
}

__global__ void __launch_bounds__(512) ps_final(float* out) {
    int tid = threadIdx.x, lane = tid & 31, warp = tid >> 5;
    __shared__ double sL[16], sM[16];
    __shared__ unsigned long long sC[16];
    double L = 0.0, M = 0.0; unsigned long long C = 0ull;
    for (int i = tid; i < NBLK; i += 512) {
        L += g_partL[i]; M += g_partM[i]; C += (unsigned long long)g_partC[i];
    }
#pragma unroll
    for (int off = 16; off; off >>= 1) {
        L += __shfl_down_sync(0xffffffffu, L, off);
        M += __shfl_down_sync(0xffffffffu, M, off);
        C += __shfl_down_sync(0xffffffffu, C, off);
    }
    if (lane == 0) { sL[warp] = L; sM[warp] = M; sC[warp] = C; }
    __syncthreads();
    if (tid == 0) {
        double tL = 0.0, tM = 0.0; unsigned long long tC = 0ull;
        for (int w = 0; w < 16; w++) { tL += sL[w]; tM += sM[w]; tC += sC[w]; }
        double mse = tM / (double)((long long)BDIM * TT * FDIM);
        double avg = (tC > 0ull) ? (tL / (double)tC) : 0.0;
        out[0] = (float)(0.5 * mse + 0.5 * avg);
    }
}

__device__ __forceinline__ float prodq(float a, float v, int q) {
    switch (q) {
        case 0:  return a;
        case 1:  return v;
        case 2:  return __fmul_rn(a, a);
        case 3:  return __fmul_rn(v, v);
        default: return __fmul_rn(a, v);
    }
}

__global__ void __launch_bounds__(NTHREADS, 2)
ps_main(const float* __restrict__ fc, const float* __restrict__ tg) {
    extern __shared__ float sm[];
    float*  tgS   = sm + OFF_TG;
    float*  fcS   = sm + OFF_FC;
    float*  Pyr   = sm + OFF_U;                 // pyramid levels 1..8 (333 x 40)
    float2* yS    = (float2*)(sm + OFF_U);      // FFT scratch (overlaid earlier)
    float*  ampS  = sm + OFF_U + 3168;          // 168*9 floats (overlaid earlier)
    float2* tw336 = (float2*)(sm + OFF_TW336);
    float2* tw21  = (float2*)(sm + OFF_TW21);
    int*    pP    = (int*)(sm + OFF_PP);
    int*    flagS = (int*)(sm + OFF_FLAG);
    double* redL  = (double*)(sm + OFF_RED);
    double* redM  = redL + 16;
    unsigned int* redCt = (unsigned int*)(redM + 16);

    const int tid  = threadIdx.x;
    const int lane = tid & 31;
    const int warp = tid >> 5;
    const int b    = blockIdx.x / FTILES;
    const int f0   = (blockIdx.x % FTILES) * SBLK;

    // twiddles: global -> smem
    if (tid < TT)  tw336[tid] = g_tw336[tid];
    if (tid >= 480) tw21[tid - 480] = g_tw21[(tid - 480) < 21 ? (tid - 480) : 0];

    // ---- Load tile + MSE partial ----
    float mseAcc = 0.f;
    {
        const size_t base = (size_t)b * TT * FDIM + f0;
        for (int i = tid; i < TT * SBLK; i += NTHREADS) {
            int t = i >> 3, l = i & 7;
            float av = 0.f, bv = 0.f;
            if (f0 + l < FDIM) {
                size_t g = base + (size_t)t * FDIM + l;
                av = tg[g]; bv = fc[g];
                float d = bv - av;
                mseAcc = fmaf(d, d, mseAcc);
            }
            tgS[t * SP + l] = av;
            fcS[t * SP + l] = bv;
        }
    }
    __syncthreads();

    // ---- Stage A: 21-pt DFT. tid -> (s, t1, quarter of r-range) ----
    {
        int s = tid & 7, t1 = (tid >> 3) & 15, quarter = tid >> 7;
        int r0 = quarter * 3, nr = (quarter == 3) ? 2 : 3;
        float yre[3], yim[3];
#pragma unroll
        for (int r = 0; r < 3; r++) { yre[r] = 0.f; yim[r] = 0.f; }
        for (int t2 = 0; t2 < 21; t2++) {
            float xv = tgS[(t1 + 16 * t2) * SP + s];
            int rt = (t2 * r0) % 21;
            for (int r = 0; r < nr; r++) {
                float2 w = tw21[rt];
                yre[r] = fmaf(xv,  w.x, yre[r]);
                yim[r] = fmaf(-xv, w.y, yim[r]);
                rt += t2; if (rt >= 21) rt -= 21;
            }
        }
        for (int r = 0; r < nr; r++)
            yS[(t1 * 11 + r0 + r) * SP + s] = make_float2(yre[r], yim[r]);
    }
    __syncthreads();

    // ---- Stage B: combine 16 subseries; store |X|^2 ----
    {
        int s = tid & 7, g = tid >> 3;
        for (int f = 1 + g; f <= NBIN; f += 64) {
            int r = f % 21;
            float sgn = 1.f; int r2 = r;
            if (r > 10) { r2 = 21 - r; sgn = -1.f; }
            float xre = 0.f, xim = 0.f;
            int idx = 0;
#pragma unroll
            for (int t1 = 0; t1 < 16; t1++) {
                float2 y = yS[(t1 * 11 + r2) * SP + s];
                float yi = y.y * sgn;
                float2 w = tw336[idx];
                xre = fmaf(y.x, w.x, fmaf(yi,  w.y, xre));
                xim = fmaf(yi,  w.x, fmaf(-y.x, w.y, xim));
                idx += f; if (idx >= TT) idx -= TT;
            }
            ampS[(f - 1) * SP + s] = xre * xre + xim * xim;
        }
    }
    __syncthreads();

    // ---- Top-3 (warp-parallel): warp w owns series w ----
    if (warp < SBLK) {
        const int s = warp;
        unsigned long long k1 = 0ull, k2 = 0ull, k3 = 0ull;
        for (int f = 1 + lane; f <= NBIN; f += 32) {
            float a = ampS[(f - 1) * SP + s];
            unsigned long long kk =
                ((unsigned long long)__float_as_uint(a) << 32) |
                (unsigned long long)(0xFFFFFFFFu - (unsigned)f);
            if (kk > k1)      { k3 = k2; k2 = k1; k1 = kk; }
            else if (kk > k2) { k3 = k2; k2 = kk; }
            else if (kk > k3) { k3 = kk; }
        }
        int fsel[3];
#pragma unroll
        for (int rnd = 0; rnd < 3; rnd++) {
            unsigned long long best = k1;
#pragma unroll
            for (int off = 16; off; off >>= 1) {
                unsigned long long o = __shfl_xor_sync(0xffffffffu, best, off);
                if (o > best) best = o;
            }
            fsel[rnd] = (int)(0xFFFFFFFFu - (unsigned)(best & 0xFFFFFFFFull));
            if (k1 == best) { k1 = k2; k2 = k3; k3 = 0ull; }
        }
        if (lane == 0) {
            int pp[3] = { TT / fsel[0], TT / fsel[1], TT / fsel[2] };
            bool active = (f0 + s) < FDIM;
            bool valid[3];
            valid[0] = active && pp[0] >= 5;
            valid[1] = active && pp[1] >= 5 && pp[1] != pp[0];
            valid[2] = active && pp[2] >= 5 && pp[2] != pp[0] && pp[2] != pp[1];
            int ns[3], L[3]; bool remv[3];
#pragma unroll
            for (int k = 0; k < 3; k++) {
                ns[k] = TT / pp[k];
                L[k]  = TT - ns[k] * pp[k];
                remv[k] = valid[k] && (L[k] >= 5);
            }
            int flags = 0;
#pragma unroll
            for (int k = 0; k < 3; k++) {
                if (valid[k]) flags |= (1 << k);
                bool inc = remv[k];
#pragma unroll
                for (int j = 0; j < 3; j++) {
                    if (valid[j] && pp[j] == L[k] && (TT % pp[j]) == 0) inc = false;
                    if (j < k && remv[j] && L[j] == L[k]) inc = false;
                }
                if (inc) flags |= (8 << k);
            }
            if (active && !(valid[0] || valid[1] || valid[2])) flags |= 64;
#pragma unroll
            for (int k = 0; k < 3; k++) pP[k * SBLK + s] = pp[k];
            flagS[s] = flags;
        }
    }
    __syncthreads();

    // ---- Upsweep: pair-sum pyramid (associative_scan tree), 5 q x 8 s ----
    // Level row offsets: L1=0(168) L2=168(84) L3=252(42) L4=294(21)
    //                    L5=315(10) L6=325(5) L7=330(2) L8=332(1)
    for (int i = tid; i < 168 * TASKP; i += NTHREADS) {
        int j = i / TASKP, task = i - j * TASKP;
        int q = task >> 3, s = task & 7;
        int u = 2 * j;
        float x0 = prodq(tgS[u * SP + s],       fcS[u * SP + s],       q);
        float x1 = prodq(tgS[(u + 1) * SP + s], fcS[(u + 1) * SP + s], q);
        Pyr[i] = __fadd_rn(x0, x1);
    }
    __syncthreads();
    {
        const int srcO[7] = { 0, 168, 252, 294, 315, 325, 330 };
        const int dstO[7] = { 168, 252, 294, 315, 325, 330, 332 };
        const int lenL[7] = { 84, 42, 21, 10, 5, 2, 1 };
        for (int L = 0; L < 7; L++) {
            for (int i = tid; i < lenL[L] * TASKP; i += NTHREADS) {
                int j = i / TASKP, task = i - j * TASKP;
                Pyr[(dstO[L] + j) * TASKP + task] =
                    __fadd_rn(Pyr[(srcO[L] + 2 * j) * TASKP + task],
                              Pyr[(srcO[L] + 2 * j + 1) * TASKP + task]);
            }
            __syncthreads();
        }
    }
    // ---- Downsweep (in place): level arrays become inclusive scans ----
    {
        const int dstO[7] = { 330, 325, 315, 294, 252, 168, 0 };
        const int parO[7] = { 332, 330, 325, 315, 294, 252, 168 };
        const int lenL[7] = { 2, 5, 10, 21, 42, 84, 168 };
        for (int L = 0; L < 7; L++) {
            for (int i = tid; i < lenL[L] * TASKP; i += NTHREADS) {
                int j = i / TASKP, task = i - j * TASKP;
                if (j == 0) continue;  // scan[0] = elem[0]
                float v;
                if (j & 1)
                    v = Pyr[(parO[L] + ((j - 1) >> 1)) * TASKP + task];
                else
                    v = __fadd_rn(Pyr[(parO[L] + (j >> 1) - 1) * TASKP + task],
                                  Pyr[(dstO[L] + j) * TASKP + task]);
                Pyr[(dstO[L] + j) * TASKP + task] = v;
            }
            __syncthreads();
        }
    }

    // ---- Walk: patch losses via cs[e]-cs[s] with reference arithmetic ----
    double lossAcc = 0.0; unsigned int cnt = 0u;
    {
        int s = tid & 7, slot = (tid >> 3) & 3, sub = tid >> 5;
        int flags = flagS[s];

        // inclusive scan value at position u (cs[u+1]); -1 -> 0
        auto s0v = [&](int q, int u) -> float {
            if (u < 0) return 0.f;
            if (u & 1) return Pyr[((u - 1) >> 1) * TASKP + (q << 3) + s];
            float x = prodq(tgS[u * SP + s], fcS[u * SP + s], q);
            if (u == 0) return x;
            return __fadd_rn(Pyr[(((u >> 1) - 1)) * TASKP + (q << 3) + s], x);
        };
        auto accum = [&](int s0, int e0) {
            float n   = (float)(e0 - s0);
            float St  = __fsub_rn(s0v(0, e0 - 1), s0v(0, s0 - 1));
            float Sf  = __fsub_rn(s0v(1, e0 - 1), s0v(1, s0 - 1));
            float Stt = __fsub_rn(s0v(2, e0 - 1), s0v(2, s0 - 1));
            float Sff = __fsub_rn(s0v(3, e0 - 1), s0v(3, s0 - 1));
            float Stf = __fsub_rn(s0v(4, e0 - 1), s0v(4, s0 - 1));
            float mt  = __fdiv_rn(St, n);
            float mf  = __fdiv_rn(Sf, n);
            float tvs = fmaxf(__fsub_rn(Stt, __fmul_rn(__fmul_rn(n, mt), mt)), 0.f);
            float fvs = fmaxf(__fsub_rn(Sff, __fmul_rn(__fmul_rn(n, mf), mf)), 0.f);
            float num = __fsub_rn(Stf, __fmul_rn(__fmul_rn(n, mt), mf));
            float den = __fadd_rn(__fsqrt_rn(__fmul_rn(tvs, fvs)), 1e-8f);
            float cl  = __fsub_rn(1.f, fabsf(__fdiv_rn(num, den)));
            float nm1 = __fsub_rn(n, 1.f);
            float tvar = __fdiv_rn(tvs, nm1);
            float fvar = __fdiv_rn(fvs, nm1);
            float vl  = __fdiv_rn(fabsf(__fsub_rn(tvar, fvar)), __fadd_rn(tvar, 1e-8f));
            float ml  = __fdiv_rn(fabsf(__fsub_rn(mt, mf)), __fadd_rn(fabsf(mt), 1e-8f));
            lossAcc += (double)__fadd_rn(__fadd_rn(cl, vl), ml);
            cnt++;
        };

        if (slot < 3) {
            if ((flags >> slot) & 1) {
                int p = pP[slot * SBLK + s], ns = TT / p;
                for (int j = sub; j < ns; j += 16) accum(j * p, j * p + p);
                if (sub == 15 && ((flags >> (3 + slot)) & 1)) accum(ns * p, TT);
            }
        } else {
            if (sub == 0 && (flags & 64)) accum(0, TT);
        }
    }

    // ---- Block reduce -> per-block partial slot (deterministic) ----
#pragma unroll
    for (int off = 16; off; off >>= 1) {
        lossAcc += __shfl_down_sync(0xffffffffu, lossAcc, off);
        mseAcc  += __shfl_down_sync(0xffffffffu, mseAcc,  off);
        cnt     += __shfl_down_sync(0xffffffffu, cnt,     off);
    }
    if (lane == 0) {
        redL[warp] = lossAcc; redM[warp] = (double)mseAcc; redCt[warp] = cnt;
    }
    __syncthreads();
    if (tid == 0) {
        double tL = 0.0, tM = 0.0; unsigned int tC = 0u;
#pragma unroll
        for (int w = 0; w < 16; w++) { tL += redL[w]; tM += redM[w]; tC += redCt[w]; }
        g_partL[blockIdx.x] = tL;
        g_partM[blockIdx.x] = tM;
        g_partC[blockIdx.x] = tC;
    }
}

extern "C" void kernel_launch(void* const* d_in, const int* in_sizes, int n_in,
                              void* d_out, int out_size) {
    const float* forecast = (const float*)d_in[0];
    const float* target   = (const float*)d_in[1];
    float* out = (float*)d_out;

    ps_tw<<<1, 512>>>();
    cudaFuncSetAttribute(ps_main, cudaFuncAttributeMaxDynamicSharedMemorySize, SMEM_BYTES);
    ps_main<<<NBLK, NTHREADS, SMEM_BYTES>>>(forecast, target);
    ps_final<<<1, 512>>>(out);
}

// round 8
// speedup vs baseline: 1.7578x; 1.1647x over previous
#include <cuda_runtime.h>
#include <math.h>

// PSLoss: 0.5*MSE + 0.5*avg(structural patch loss)
// B=64, T=336, F=321. 20544 series of length 336 (stride F in memory).
// Spectrum: Cooley-Tukey 336 = 16 x 21 (real-input symmetry).
// Patch stats: fp32 cumsum with jax lax.associative_scan tree bracketing,
// segment sums as cs[e]-cs[s], exactly matching the reference arithmetic.
// R5: 3 blocks/SM (smem 75.4KB), last-block final reduction, tw336 via L1.

#define TT      336
#define FDIM    321
#define BDIM    64
#define NBIN    168
#define SBLK    8         // series per block
#define SP      8         // series pitch
#define AP      9         // amp pitch (odd -> conflict-free lane-strided scan)
#define NTHREADS 512
#define FTILES  41        // ceil(321/8)
#define NBLK    (BDIM * FTILES)
#define TASKP   40        // 5 quantities x 8 series

// float-index smem offsets
#define OFF_TG    0                      // 336*8 = 2688
#define OFF_FC    2688                   // 2688
#define OFF_U     5376                   // union: FFT scratch / pyramid 13320
#define OFF_AMP   (OFF_U + 2816)         // amp 168*9 = 1512 (inside union)
#define OFF_TW21  (OFF_U + 13320)        // 24 float2 = 48 floats
#define OFF_PP    (OFF_TW21 + 48)        // 24 ints
#define OFF_FLAG  (OFF_PP + 24)          // 8 ints
#define OFF_RED   (OFF_FLAG + 8)         // 16 dbl + 16 dbl + 16 uint = 80 floats
#define SMEM_FLOATS (OFF_RED + 80)
#define SMEM_BYTES  (SMEM_FLOATS * 4)    // 75424 bytes -> 3 blocks/SM

__device__ float2 g_tw336[TT];
__device__ float2 g_tw21[24];
__device__ double g_partL[NBLK];
__device__ double g_partM[NBLK];
__device__ unsigned int g_partC[NBLK];
__device__ unsigned int g_done = 0u;

__global__ void ps_tw() {
    int i = threadIdx.x;
    if (i < TT) {
        double a = 6.283185307179586476925287 * (double)i / (double)TT;
        g_tw336[i] = make_float2((float)cos(a), (float)sin(a));
    }
    if (i < 21) {
        double a = 6.283185307179586476925287 * (double)i / 21.0;
        g_tw21[i] = make_float2((float)cos(a), (float)sin(a));
    }
}

__device__ __forceinline__ float prodq(float a, float v, int q) {
    switch (q) {
        case 0:  return a;
        case 1:  return v;
        case 2:  return __fmul_rn(a, a);
        case 3:  return __fmul_rn(v, v);
        default: return __fmul_rn(a, v);
    }
}

__global__ void __launch_bounds__(NTHREADS, 3)
ps_main(const float* __restrict__ fc, const float* __restrict__ tg,
        float* __restrict__ out) {
    extern __shared__ float sm[];
    float*  tgS   = sm + OFF_TG;
    float*  fcS   = sm + OFF_FC;
    float*  Pyr   = sm + OFF_U;                 // pyramid levels 1..8 (333 x 40)
    float2* yS    = (float2*)(sm + OFF_U);      // FFT scratch (overlaid earlier)
    float*  ampS  = sm + OFF_AMP;               // 168*9 (overlaid earlier)
    float2* tw21  = (float2*)(sm + OFF_TW21);
    int*    pP    = (int*)(sm + OFF_PP);
    int*    flagS = (int*)(sm + OFF_FLAG);
    double* redL  = (double*)(sm + OFF_RED);
    double* redM  = redL + 16;
    unsigned int* redCt = (unsigned int*)(redM + 16);

    const int tid  = threadIdx.x;
    const int lane = tid & 31;
    const int warp = tid >> 5;
    const int b    = blockIdx.x / FTILES;
    const int f0   = (blockIdx.x % FTILES) * SBLK;

    if (tid < 24) tw21[tid] = g_tw21[tid < 21 ? tid : 0];

    // ---- Load tile + MSE partial ----
    float mseAcc = 0.f;
    {
        const size_t base = (size_t)b * TT * FDIM + f0;
        for (int i = tid; i < TT * SBLK; i += NTHREADS) {
            int t = i >> 3, l = i & 7;
            float av = 0.f, bv = 0.f;
            if (f0 + l < FDIM) {
                size_t g = base + (size_t)t * FDIM + l;
                av = tg[g]; bv = fc[g];
                float d = bv - av;
                mseAcc = fmaf(d, d, mseAcc);
            }
            tgS[t * SP + l] = av;
            fcS[t * SP + l] = bv;
        }
    }
    __syncthreads();

    // ---- Stage A: 21-pt DFT. tid -> (s, t1, quarter of r-range) ----
    {
        int s = tid & 7, t1 = (tid >> 3) & 15, quarter = tid >> 7;
        int r0 = quarter * 3, nr = (quarter == 3) ? 2 : 3;
        float yre[3], yim[3];
#pragma unroll
        for (int r = 0; r < 3; r++) { yre[r] = 0.f; yim[r] = 0.f; }
        for (int t2 = 0; t2 < 21; t2++) {
            float xv = tgS[(t1 + 16 * t2) * SP + s];
            int rt = (t2 * r0) % 21;
            for (int r = 0; r < nr; r++) {
                float2 w = tw21[rt];
                yre[r] = fmaf(xv,  w.x, yre[r]);
                yim[r] = fmaf(-xv, w.y, yim[r]);
                rt += t2; if (rt >= 21) rt -= 21;
            }
        }
        for (int r = 0; r < nr; r++)
            yS[(t1 * 11 + r0 + r) * SP + s] = make_float2(yre[r], yim[r]);
    }
    __syncthreads();

    // ---- Stage B: combine 16 subseries; store |X|^2 ----
    {
        int s = tid & 7, g = tid >> 3;
        for (int f = 1 + g; f <= NBIN; f += 64) {
            int r = f % 21;
            float sgn = 1.f; int r2 = r;
            if (r > 10) { r2 = 21 - r; sgn = -1.f; }
            float xre = 0.f, xim = 0.f;
            int idx = 0;
#pragma unroll
            for (int t1 = 0; t1 < 16; t1++) {
                float2 y = yS[(t1 * 11 + r2) * SP + s];
                float yi = y.y * sgn;
                float2 w = __ldg(&g_tw336[idx]);
                xre = fmaf(y.x, w.x, fmaf(yi,  w.y, xre));
                xim = fmaf(yi,  w.x, fmaf(-y.x, w.y, xim));
                idx += f; if (idx >= TT) idx -= TT;
            }
            ampS[(f - 1) * AP + s] = xre * xre + xim * xim;
        }
    }
    __syncthreads();

    // ---- Top-3 (warp-parallel): warp w owns series w ----
    if (warp < SBLK) {
        const int s = warp;
        unsigned long long k1 = 0ull, k2 = 0ull, k3 = 0ull;
        for (int f = 1 + lane; f <= NBIN; f += 32) {
            float a = ampS[(f - 1) * AP + s];
            unsigned long long kk =
                ((unsigned long long)__float_as_uint(a) << 32) |
                (unsigned long long)(0xFFFFFFFFu - (unsigned)f);
            if (kk > k1)      { k3 = k2; k2 = k1; k1 = kk; }
            else if (kk > k2) { k3 = k2; k2 = kk; }
            else if (kk > k3) { k3 = kk; }
        }
        int fsel[3];
#pragma unroll
        for (int rnd = 0; rnd < 3; rnd++) {
            unsigned long long best = k1;
#pragma unroll
            for (int off = 16; off; off >>= 1) {
                unsigned long long o = __shfl_xor_sync(0xffffffffu, best, off);
                if (o > best) best = o;
            }
            fsel[rnd] = (int)(0xFFFFFFFFu - (unsigned)(best & 0xFFFFFFFFull));
            if (k1 == best) { k1 = k2; k2 = k3; k3 = 0ull; }
        }
        if (lane == 0) {
            int pp[3] = { TT / fsel[0], TT / fsel[1], TT / fsel[2] };
            bool active = (f0 + s) < FDIM;
            bool valid[3];
            valid[0] = active && pp[0] >= 5;
            valid[1] = active && pp[1] >= 5 && pp[1] != pp[0];
            valid[2] = active && pp[2] >= 5 && pp[2] != pp[0] && pp[2] != pp[1];
            int ns[3], L[3]; bool remv[3];
#pragma unroll
            for (int k = 0; k < 3; k++) {
                ns[k] = TT / pp[k];
                L[k]  = TT - ns[k] * pp[k];
                remv[k] = valid[k] && (L[k] >= 5);
            }
            int flags = 0;
#pragma unroll
            for (int k = 0; k < 3; k++) {
                if (valid[k]) flags |= (1 << k);
                bool inc = remv[k];
#pragma unroll
                for (int j = 0; j < 3; j++) {
                    if (valid[j] && pp[j] == L[k] && (TT % pp[j]) == 0) inc = false;
                    if (j < k && remv[j] && L[j] == L[k]) inc = false;
                }
                if (inc) flags |= (8 << k);
            }
            if (active && !(valid[0] || valid[1] || valid[2])) flags |= 64;
#pragma unroll
            for (int k = 0; k < 3; k++) pP[k * SBLK + s] = pp[k];
            flagS[s] = flags;
        }
    }
    __syncthreads();

    // ---- Upsweep: pair-sum pyramid (associative_scan tree), 5 q x 8 s ----
    // Level row offsets: L1=0(168) L2=168(84) L3=252(42) L4=294(21)
    //                    L5=315(10) L6=325(5) L7=330(2) L8=332(1)
    for (int i = tid; i < 168 * TASKP; i += NTHREADS) {
        int j = i / TASKP, task = i - j * TASKP;
        int q = task >> 3, s = task & 7;
        int u = 2 * j;
        float x0 = prodq(tgS[u * SP + s],       fcS[u * SP + s],       q);
        float x1 = prodq(tgS[(u + 1) * SP + s], fcS[(u + 1) * SP + s], q);
        Pyr[i] = __fadd_rn(x0, x1);
    }
    __syncthreads();
    {
        const int srcO[7] = { 0, 168, 252, 294, 315, 325, 330 };
        const int dstO[7] = { 168, 252, 294, 315, 325, 330, 332 };
        const int lenL[7] = { 84, 42, 21, 10, 5, 2, 1 };
        for (int L = 0; L < 7; L++) {
            for (int i = tid; i < lenL[L] * TASKP; i += NTHREADS) {
                int j = i / TASKP, task = i - j * TASKP;
                Pyr[(dstO[L] + j) * TASKP + task] =
                    __fadd_rn(Pyr[(srcO[L] + 2 * j) * TASKP + task],
                              Pyr[(srcO[L] + 2 * j + 1) * TASKP + task]);
            }
            __syncthreads();
        }
    }
    // ---- Downsweep (in place): level arrays become inclusive scans ----
    {
        const int dstO[7] = { 330, 325, 315, 294, 252, 168, 0 };
        const int parO[7] = { 332, 330, 325, 315, 294, 252, 168 };
        const int lenL[7] = { 2, 5, 10, 21, 42, 84, 168 };
        for (int L = 0; L < 7; L++) {
            for (int i = tid; i < lenL[L] * TASKP; i += NTHREADS) {
                int j = i / TASKP, task = i - j * TASKP;
                if (j == 0) continue;  // scan[0] = elem[0]
                float v;
                if (j & 1)
                    v = Pyr[(parO[L] + ((j - 1) >> 1)) * TASKP + task];
                else
                    v = __fadd_rn(Pyr[(parO[L] + (j >> 1) - 1) * TASKP + task],
                                  Pyr[(dstO[L] + j) * TASKP + task]);
                Pyr[(dstO[L] + j) * TASKP + task] = v;
            }
            __syncthreads();
        }
    }

    // ---- Walk: patch losses via cs[e]-cs[s] with reference arithmetic ----
    double lossAcc = 0.0; unsigned int cnt = 0u;
    {
        int s = tid & 7, slot = (tid >> 3) & 3, sub = tid >> 5;
        int flags = flagS[s];

        // inclusive scan value at position u (cs[u+1]); -1 -> 0
        auto s0v = [&](int q, int u) -> float {
            if (u < 0) return 0.f;
            if (u & 1) return Pyr[((u - 1) >> 1) * TASKP + (q << 3) + s];
            float x = prodq(tgS[u * SP + s], fcS[u * SP + s], q);
            if (u == 0) return x;
            return __fadd_rn(Pyr[(((u >> 1) - 1)) * TASKP + (q << 3) + s], x);
        };
        auto accum = [&](int s0, int e0) {
            float n   = (float)(e0 - s0);
            float St  = __fsub_rn(s0v(0, e0 - 1), s0v(0, s0 - 1));
            float Sf  = __fsub_rn(s0v(1, e0 - 1), s0v(1, s0 - 1));
            float Stt = __fsub_rn(s0v(2, e0 - 1), s0v(2, s0 - 1));
            float Sff = __fsub_rn(s0v(3, e0 - 1), s0v(3, s0 - 1));
            float Stf = __fsub_rn(s0v(4, e0 - 1), s0v(4, s0 - 1));
            float mt  = __fdiv_rn(St, n);
            float mf  = __fdiv_rn(Sf, n);
            float tvs = fmaxf(__fsub_rn(Stt, __fmul_rn(__fmul_rn(n, mt), mt)), 0.f);
            float fvs = fmaxf(__fsub_rn(Sff, __fmul_rn(__fmul_rn(n, mf), mf)), 0.f);
            float num = __fsub_rn(Stf, __fmul_rn(__fmul_rn(n, mt), mf));
            float den = __fadd_rn(__fsqrt_rn(__fmul_rn(tvs, fvs)), 1e-8f);
            float cl  = __fsub_rn(1.f, fabsf(__fdiv_rn(num, den)));
            float nm1 = __fsub_rn(n, 1.f);
            float tvar = __fdiv_rn(tvs, nm1);
            float fvar = __fdiv_rn(fvs, nm1);
            float vl  = __fdiv_rn(fabsf(__fsub_rn(tvar, fvar)), __fadd_rn(tvar, 1e-8f));
            float ml  = __fdiv_rn(fabsf(__fsub_rn(mt, mf)), __fadd_rn(fabsf(mt), 1e-8f));
            lossAcc += (double)__fadd_rn(__fadd_rn(cl, vl), ml);
            cnt++;
        };

        if (slot < 3) {
            if ((flags >> slot) & 1) {
                int p = pP[slot * SBLK + s], ns = TT / p;
                for (int j = sub; j < ns; j += 16) accum(j * p, j * p + p);
                if (sub == 15 && ((flags >> (3 + slot)) & 1)) accum(ns * p, TT);
            }
        } else {
            if (sub == 0 && (flags & 64)) accum(0, TT);
        }
    }

    // ---- Block reduce -> per-block partial slot (deterministic) ----
#pragma unroll
    for (int off = 16; off; off >>= 1) {
        lossAcc += __shfl_down_sync(0xffffffffu, lossAcc, off);
        mseAcc  += __shfl_down_sync(0xffffffffu, mseAcc,  off);
        cnt     += __shfl_down_sync(0xffffffffu, cnt,     off);
    }
    if (lane == 0) {
        redL[warp] = lossAcc; redM[warp] = (double)mseAcc; redCt[warp] = cnt;
    }
    __syncthreads();

    __shared__ unsigned int sLast;
    if (tid == 0) {
        double tL = 0.0, tM = 0.0; unsigned int tC = 0u;
#pragma unroll
        for (int w = 0; w < 16; w++) { tL += redL[w]; tM += redM[w]; tC += redCt[w]; }
        g_partL[blockIdx.x] = tL;
        g_partM[blockIdx.x] = tM;
        g_partC[blockIdx.x] = tC;
        __threadfence();
        sLast = (atomicAdd(&g_done, 1u) == (unsigned)(NBLK - 1));
    }
    __syncthreads();

    // ---- Last block: deterministic grand reduction ----
    if (sLast) {
        __threadfence();
        double L = 0.0, M = 0.0; unsigned long long C = 0ull;
        for (int i = tid; i < NBLK; i += NTHREADS) {
            L += g_partL[i]; M += g_partM[i]; C += (unsigned long long)g_partC[i];
        }
#pragma unroll
        for (int off = 16; off; off >>= 1) {
            L += __shfl_down_sync(0xffffffffu, L, off);
            M += __shfl_down_sync(0xffffffffu, M, off);
            C += __shfl_down_sync(0xffffffffu, C, off);
        }
        if (lane == 0) { redL[warp] = L; redM[warp] = M; ((unsigned long long*)redCt)[0] = 0ull; }
        __syncthreads();
        if (lane == 0 && warp < 1) {
            // serial sum over 16 warp slots in fixed order
        }
        if (tid == 0) {
            // re-gather counts: recompute C across warps via shared doubles
        }
        // store warp partials for C separately
        __shared__ unsigned long long sC[16];
        if (lane == 0) sC[warp] = C;
        __syncthreads();
        if (tid == 0) {
            double tL = 0.0, tM = 0.0; unsigned long long tC = 0ull;
#pragma unroll
            for (int w = 0; w < 16; w++) { tL += redL[w]; tM += redM[w]; tC += sC[w]; }
            double mse = tM / (double)((long long)BDIM * TT * FDIM);
            double avg = (tC > 0ull) ? (tL / (double)tC) : 0.0;
            out[0] = (float)(0.5 * mse + 0.5 * avg);
            g_done = 0u;  // reset for next launch (deterministic)
        }
    }
}

extern "C" void kernel_launch(void* const* d_in, const int* in_sizes, int n_in,
                              void* d_out, int out_size) {
    const float* forecast = (const float*)d_in[0];
    const float* target   = (const float*)d_in[1];
    float* out = (float*)d_out;

    ps_tw<<<1, 512>>>();
    cudaFuncSetAttribute(ps_main, cudaFuncAttributeMaxDynamicSharedMemorySize, SMEM_BYTES);
    ps_main<<<NBLK, NTHREADS, SMEM_BYTES>>>(forecast, target, out);
}

// round 9
// speedup vs baseline: 2.0650x; 1.1748x over previous
#include <cuda_runtime.h>
#include <math.h>

// PSLoss: 0.5*MSE + 0.5*avg(structural patch loss)
// B=64, T=336, F=321. 20544 series of length 336 (stride F in memory).
// Spectrum: Cooley-Tukey 336 = 16 x 21; stage B as twiddle + 16-pt radix-4 FFT.
// Patch stats: fp32 cumsum with jax lax.associative_scan tree bracketing,
// segment sums as cs[e]-cs[s], exactly matching the reference arithmetic.
// R9: FFT16 stage B, div-free pyramid loops, rebalanced walk, cheap ps_tw.

#define TT      336
#define FDIM    321
#define BDIM    64
#define NBIN    168
#define SBLK    8         // series per block
#define SP      8         // tg/fc pitch
#define AP      9         // amp pitch
#define SPY     9         // yS (float2) pitch
#define NTHREADS 512
#define FTILES  41        // ceil(321/8)
#define NBLK    (BDIM * FTILES)
#define TASKP   40        // 5 quantities x 8 series
#define NJ      (NTHREADS / TASKP)   // 12
#define NACT    (NJ * TASKP)         // 480

// float-index smem offsets
#define OFF_TG    0                      // 336*8 = 2688
#define OFF_FC    2688                   // 2688
#define OFF_U     5376                   // union: FFT scratch / pyramid 13320
#define OFF_AMP   (OFF_U + 3168)         // amp 168*9 = 1512 (inside union)
#define OFF_TW21  (OFF_U + 13320)        // 24 float2 = 48 floats
#define OFF_PP    (OFF_TW21 + 48)        // 24 ints
#define OFF_FLAG  (OFF_PP + 24)          // 8 ints
#define OFF_RED   (OFF_FLAG + 8)         // 16 dbl + 16 dbl + 16 uint = 80 floats
#define SMEM_FLOATS (OFF_RED + 80)
#define SMEM_BYTES  (SMEM_FLOATS * 4)    // 75424 bytes -> 3 blocks/SM

__device__ float2 g_tw336[TT];
__device__ float2 g_tw21[24];
__device__ double g_partL[NBLK];
__device__ double g_partM[NBLK];
__device__ unsigned int g_partC[NBLK];
__device__ unsigned int g_done = 0u;

__global__ void ps_tw() {
    int i = threadIdx.x;
    if (i <= 84) {
        double s, c;
        sincospi((double)i / 168.0, &s, &c);
        g_tw336[i] = make_float2((float)c, (float)s);
    }
    __syncthreads();
    if (i >= 85 && i < TT) {
        float2 q;
        if (i <= 168)      { q = g_tw336[168 - i]; g_tw336[i] = make_float2(-q.x,  q.y); }
        else if (i <= 252) { q = g_tw336[i - 168]; g_tw336[i] = make_float2(-q.x, -q.y); }
        else               { q = g_tw336[336 - i]; g_tw336[i] = make_float2( q.x, -q.y); }
    }
    __syncthreads();
    if (i < 24) g_tw21[i] = g_tw336[(i < 21) ? 16 * i : 0];
}

__device__ __forceinline__ float prodq(float a, float v, int q) {
    switch (q) {
        case 0:  return a;
        case 1:  return v;
        case 2:  return __fmul_rn(a, a);
        case 3:  return __fmul_rn(v, v);
        default: return __fmul_rn(a, v);
    }
}

__device__ __forceinline__ float2 cmulc(float2 z, float2 w) {
    // z * (w.x - i*w.y)
    return make_float2(fmaf(z.y, w.y, z.x * w.x), fmaf(z.y, w.x, -z.x * w.y));
}
__device__ __forceinline__ float2 cadd(float2 a, float2 b) {
    return make_float2(a.x + b.x, a.y + b.y);
}
__device__ __forceinline__ float2 csub(float2 a, float2 b) {
    return make_float2(a.x - b.x, a.y - b.y);
}

__global__ void __launch_bounds__(NTHREADS, 3)
ps_main(const float* __restrict__ fc, const float* __restrict__ tg,
        float* __restrict__ out) {
    extern __shared__ float sm[];
    float*  tgS   = sm + OFF_TG;
    float*  fcS   = sm + OFF_FC;
    float*  Pyr   = sm + OFF_U;                 // pyramid levels 1..8 (333 x 40)
    float2* yS    = (float2*)(sm + OFF_U);      // FFT scratch (overlaid earlier)
    float*  ampS  = sm + OFF_AMP;               // 168*9 (overlaid earlier)
    float2* tw21  = (float2*)(sm + OFF_TW21);
    int*    pP    = (int*)(sm + OFF_PP);
    int*    flagS = (int*)(sm + OFF_FLAG);
    double* redL  = (double*)(sm + OFF_RED);
    double* redM  = redL + 16;
    unsigned int* redCt = (unsigned int*)(redM + 16);

    const int tid  = threadIdx.x;
    const int lane = tid & 31;
    const int warp = tid >> 5;
    const int b    = blockIdx.x / FTILES;
    const int f0   = (blockIdx.x % FTILES) * SBLK;

    if (tid < 24) tw21[tid] = g_tw21[tid];

    // ---- Load tile + MSE partial ----
    float mseAcc = 0.f;
    {
        const int base = b * TT * FDIM + f0;
        for (int i = tid; i < TT * SBLK; i += NTHREADS) {
            int t = i >> 3, l = i & 7;
            float av = 0.f, bv = 0.f;
            if (f0 + l < FDIM) {
                int g = base + t * FDIM + l;
                av = tg[g]; bv = fc[g];
                float d = bv - av;
                mseAcc = fmaf(d, d, mseAcc);
            }
            tgS[t * SP + l] = av;
            fcS[t * SP + l] = bv;
        }
    }
    __syncthreads();

    // ---- Stage A: 21-pt DFT. tid -> (s, t1, quarter of r-range) ----
    {
        int s = tid & 7, t1 = (tid >> 3) & 15, quarter = tid >> 7;
        int r0 = quarter * 3, nr = (quarter == 3) ? 2 : 3;
        float yre[3], yim[3];
#pragma unroll
        for (int r = 0; r < 3; r++) { yre[r] = 0.f; yim[r] = 0.f; }
        for (int t2 = 0; t2 < 21; t2++) {
            float xv = tgS[(t1 + 16 * t2) * SP + s];
            int rt = (t2 * r0) % 21;
            for (int r = 0; r < nr; r++) {
                float2 w = tw21[rt];
                yre[r] = fmaf(xv,  w.x, yre[r]);
                yim[r] = fmaf(-xv, w.y, yim[r]);
                rt += t2; if (rt >= 21) rt -= 21;
            }
        }
        for (int r = 0; r < nr; r++)
            yS[(t1 * 11 + r0 + r) * SPY + s] = make_float2(yre[r], yim[r]);
    }
    __syncthreads();

    // ---- Stage B: per (s, r) residue class, twiddle + 16-pt FFT ----
    // f = r + 21m. Two threads (h=0,1) per class; h owns b = {2h,2h+1} in
    // stage 1 (DFT4 over a, t1 = 4a+b) and d = {2h,2h+1} in stage 2.
    if (tid < 336) {
        const unsigned mask = (tid < 320) ? 0xFFFFFFFFu : 0x0000FFFFu;
        const int h = tid & 1, pair = tid >> 1;
        const int s = pair & 7, r = pair >> 3;            // r in 0..20
        const int r2 = (r <= 10) ? r : 21 - r;
        const float sgn = (r <= 10) ? 1.f : -1.f;

        float2 Z[4][2];
#pragma unroll
        for (int bi = 0; bi < 2; bi++) {
            int bb = 2 * h + bi;
#pragma unroll
            for (int a = 0; a < 4; a++) {
                int t1 = 4 * a + bb;
                float2 y = yS[(t1 * 11 + r2) * SPY + s];
                y.y *= sgn;
                float2 w = __ldg(&g_tw336[r * t1]);
                Z[a][bi] = cmulc(y, w);
            }
        }
        // stage 1: DFT4 over a -> G[d][bi]
        float2 G[4][2];
#pragma unroll
        for (int bi = 0; bi < 2; bi++) {
            float2 t0 = cadd(Z[0][bi], Z[2][bi]);
            float2 t1 = csub(Z[0][bi], Z[2][bi]);
            float2 t2 = cadd(Z[1][bi], Z[3][bi]);
            float2 t3 = csub(Z[1][bi], Z[3][bi]);
            G[0][bi] = cadd(t0, t2);
            G[2][bi] = csub(t0, t2);
            G[1][bi] = make_float2(t1.x + t3.y, t1.y - t3.x);
            G[3][bi] = make_float2(t1.x - t3.y, t1.y + t3.x);
        }
        // twiddle by W16^{d*b}, b = 2h+bi
        const float C1 = 0.9238795325112867f, S1 = 0.3826834323650898f;
        const float C2 = 0.7071067811865476f;
        {
            float2 w;
            w = h ? make_float2(C2, C2)   : make_float2(1.f, 0.f);  // d1,b=2h
            G[1][0] = cmulc(G[1][0], w);
            w = h ? make_float2(S1, C1)   : make_float2(C1, S1);    // d1,b=2h+1
            G[1][1] = cmulc(G[1][1], w);
            w = h ? make_float2(0.f, 1.f) : make_float2(1.f, 0.f);  // d2,b=2h
            G[2][0] = cmulc(G[2][0], w);
            w = h ? make_float2(-C2, C2)  : make_float2(C2, C2);    // d2,b=2h+1
            G[2][1] = cmulc(G[2][1], w);
            w = h ? make_float2(-C2, C2)  : make_float2(1.f, 0.f);  // d3,b=2h
            G[3][0] = cmulc(G[3][0], w);
            w = h ? make_float2(-C1, -S1) : make_float2(S1, C1);    // d3,b=2h+1
            G[3][1] = cmulc(G[3][1], w);
        }
        // exchange with partner (xor 1): send other-d, receive my-d other-b
        float2 sA0 = h ? G[0][0] : G[2][0];
        float2 sA1 = h ? G[0][1] : G[2][1];
        float2 sB0 = h ? G[1][0] : G[3][0];
        float2 sB1 = h ? G[1][1] : G[3][1];
        float2 rA0, rA1, rB0, rB1;
        rA0.x = __shfl_xor_sync(mask, sA0.x, 1); rA0.y = __shfl_xor_sync(mask, sA0.y, 1);
        rA1.x = __shfl_xor_sync(mask, sA1.x, 1); rA1.y = __shfl_xor_sync(mask, sA1.y, 1);
        rB0.x = __shfl_xor_sync(mask, sB0.x, 1); rB0.y = __shfl_xor_sync(mask, sB0.y, 1);
        rB1.x = __shfl_xor_sync(mask, sB1.x, 1); rB1.y = __shfl_xor_sync(mask, sB1.y, 1);
        float2 kA0 = h ? G[2][0] : G[0][0];
        float2 kA1 = h ? G[2][1] : G[0][1];
        float2 kB0 = h ? G[3][0] : G[1][0];
        float2 kB1 = h ? G[3][1] : G[1][1];
        // H arrays ordered by b = 0..3
        float2 HA0 = h ? rA0 : kA0, HA1 = h ? rA1 : kA1;
        float2 HA2 = h ? kA0 : rA0, HA3 = h ? kA1 : rA1;
        float2 HB0 = h ? rB0 : kB0, HB1 = h ? rB1 : kB1;
        float2 HB2 = h ? kB0 : rB0, HB3 = h ? kB1 : rB1;

        // stage 2: DFT4 over b for d = 2h (A) and d = 2h+1 (B)
#pragma unroll
        for (int part = 0; part < 2; part++) {
            float2 u0 = part ? HB0 : HA0, u1 = part ? HB1 : HA1;
            float2 u2 = part ? HB2 : HA2, u3 = part ? HB3 : HA3;
            int d = 2 * h + part;
            float2 t0 = cadd(u0, u2), t1 = csub(u0, u2);
            float2 t2 = cadd(u1, u3), t3 = csub(u1, u3);
            float2 X[4];
            X[0] = cadd(t0, t2);
            X[2] = csub(t0, t2);
            X[1] = make_float2(t1.x + t3.y, t1.y - t3.x);
            X[3] = make_float2(t1.x - t3.y, t1.y + t3.x);
#pragma unroll
            for (int c = 0; c < 4; c++) {
                int m = 4 * c + d;
                bool ok = (r == 0) ? (m >= 1 && m <= 8) : (m <= 7);
                if (ok) {
                    int f = r + 21 * m;
                    ampS[(f - 1) * AP + s] = fmaf(X[c].x, X[c].x, X[c].y * X[c].y);
                }
            }
        }
    }
    __syncthreads();

    // ---- Top-3 (warp-parallel): warp w owns series w ----
    if (warp < SBLK) {
        const int s = warp;
        unsigned long long k1 = 0ull, k2 = 0ull, k3 = 0ull;
        for (int f = 1 + lane; f <= NBIN; f += 32) {
            float a = ampS[(f - 1) * AP + s];
            unsigned long long kk =
                ((unsigned long long)__float_as_uint(a) << 32) |
                (unsigned long long)(0xFFFFFFFFu - (unsigned)f);
            if (kk > k1)      { k3 = k2; k2 = k1; k1 = kk; }
            else if (kk > k2) { k3 = k2; k2 = kk; }
            else if (kk > k3) { k3 = kk; }
        }
        int fsel[3];
#pragma unroll
        for (int rnd = 0; rnd < 3; rnd++) {
            unsigned long long best = k1;
#pragma unroll
            for (int off = 16; off; off >>= 1) {
                unsigned long long o = __shfl_xor_sync(0xffffffffu, best, off);
                if (o > best) best = o;
            }
            fsel[rnd] = (int)(0xFFFFFFFFu - (unsigned)(best & 0xFFFFFFFFull));
            if (k1 == best) { k1 = k2; k2 = k3; k3 = 0ull; }
        }
        if (lane == 0) {
            int pp[3] = { TT / fsel[0], TT / fsel[1], TT / fsel[2] };
            bool active = (f0 + s) < FDIM;
            bool valid[3];
            valid[0] = active && pp[0] >= 5;
            valid[1] = active && pp[1] >= 5 && pp[1] != pp[0];
            valid[2] = active && pp[2] >= 5 && pp[2] != pp[0] && pp[2] != pp[1];
            int ns[3], L[3]; bool remv[3];
#pragma unroll
            for (int k = 0; k < 3; k++) {
                ns[k] = TT / pp[k];
                L[k]  = TT - ns[k] * pp[k];
                remv[k] = valid[k] && (L[k] >= 5);
            }
            int flags = 0;
#pragma unroll
            for (int k = 0; k < 3; k++) {
                if (valid[k]) flags |= (1 << k);
                bool inc = remv[k];
#pragma unroll
                for (int j = 0; j < 3; j++) {
                    if (valid[j] && pp[j] == L[k] && (TT % pp[j]) == 0) inc = false;
                    if (j < k && remv[j] && L[j] == L[k]) inc = false;
                }
                if (inc) flags |= (8 << k);
            }
            if (active && !(valid[0] || valid[1] || valid[2])) flags |= 64;
#pragma unroll
            for (int k = 0; k < 3; k++) pP[k * SBLK + s] = pp[k];
            flagS[s] = flags;
        }
    }
    __syncthreads();

    // ---- Upsweep: pair-sum pyramid (associative_scan tree), 5 q x 8 s ----
    // Level row offsets: L1=0(168) L2=168(84) L3=252(42) L4=294(21)
    //                    L5=315(10) L6=325(5) L7=330(2) L8=332(1)
    const int task = tid % TASKP;
    const int j0   = tid / TASKP;     // 0..12 (tid<480 active)
    if (tid < NACT) {
        int q = task >> 3, s = task & 7;
        for (int j = j0; j < 168; j += NJ) {
            int u = 2 * j;
            float x0 = prodq(tgS[u * SP + s],       fcS[u * SP + s],       q);
            float x1 = prodq(tgS[(u + 1) * SP + s], fcS[(u + 1) * SP + s], q);
            Pyr[j * TASKP + task] = __fadd_rn(x0, x1);
        }
    }
    __syncthreads();
    {
        const int srcO[7] = { 0, 168, 252, 294, 315, 325, 330 };
        const int dstO[7] = { 168, 252, 294, 315, 325, 330, 332 };
        const int lenL[7] = { 84, 42, 21, 10, 5, 2, 1 };
#pragma unroll
        for (int L = 0; L < 7; L++) {
            if (tid < NACT) {
                for (int j = j0; j < lenL[L]; j += NJ) {
                    Pyr[(dstO[L] + j) * TASKP + task] =
                        __fadd_rn(Pyr[(srcO[L] + 2 * j) * TASKP + task],
                                  Pyr[(srcO[L] + 2 * j + 1) * TASKP + task]);
                }
            }
            __syncthreads();
        }
    }
    // ---- Downsweep (in place): level arrays become inclusive scans ----
    {
        const int dstO[7] = { 330, 325, 315, 294, 252, 168, 0 };
        const int parO[7] = { 332, 330, 325, 315, 294, 252, 168 };
        const int lenL[7] = { 2, 5, 10, 21, 42, 84, 168 };
#pragma unroll
        for (int L = 0; L < 7; L++) {
            if (tid < NACT) {
                for (int j = j0; j < lenL[L]; j += NJ) {
                    if (j == 0) continue;  // scan[0] = elem[0]
                    float v;
                    if (j & 1)
                        v = Pyr[(parO[L] + ((j - 1) >> 1)) * TASKP + task];
                    else
                        v = __fadd_rn(Pyr[(parO[L] + (j >> 1) - 1) * TASKP + task],
                                      Pyr[(dstO[L] + j) * TASKP + task]);
                    Pyr[(dstO[L] + j) * TASKP + task] = v;
                }
            }
            __syncthreads();
        }
    }

    // ---- Walk: patch losses via cs[e]-cs[s] with reference arithmetic ----
    double lossAcc = 0.0; unsigned int cnt = 0u;
    {
        int s = tid & 7, w = tid >> 3;   // w in 0..63
        int slot, sub;
        if (w < 21)      { slot = 0; sub = w; }
        else if (w < 42) { slot = 1; sub = w - 21; }
        else if (w < 63) { slot = 2; sub = w - 42; }
        else             { slot = 3; sub = 0; }
        int flags = flagS[s];

        // inclusive scan value at position u (cs[u+1]); -1 -> 0
        auto s0v = [&](int q, int u) -> float {
            if (u < 0) return 0.f;
            if (u & 1) return Pyr[((u - 1) >> 1) * TASKP + (q << 3) + s];
            float x = prodq(tgS[u * SP + s], fcS[u * SP + s], q);
            if (u == 0) return x;
            return __fadd_rn(Pyr[(((u >> 1) - 1)) * TASKP + (q << 3) + s], x);
        };
        auto accum = [&](int s0, int e0) {
            float n   = (float)(e0 - s0);
            float St  = __fsub_rn(s0v(0, e0 - 1), s0v(0, s0 - 1));
            float Sf  = __fsub_rn(s0v(1, e0 - 1), s0v(1, s0 - 1));
            float Stt = __fsub_rn(s0v(2, e0 - 1), s0v(2, s0 - 1));
            float Sff = __fsub_rn(s0v(3, e0 - 1), s0v(3, s0 - 1));
            float Stf = __fsub_rn(s0v(4, e0 - 1), s0v(4, s0 - 1));
            float mt  = __fdiv_rn(St, n);
            float mf  = __fdiv_rn(Sf, n);
            float tvs = fmaxf(__fsub_rn(Stt, __fmul_rn(__fmul_rn(n, mt), mt)), 0.f);
            float fvs = fmaxf(__fsub_rn(Sff, __fmul_rn(__fmul_rn(n, mf), mf)), 0.f);
            float num = __fsub_rn(Stf, __fmul_rn(__fmul_rn(n, mt), mf));
            float den = __fadd_rn(__fsqrt_rn(__fmul_rn(tvs, fvs)), 1e-8f);
            float cl  = __fsub_rn(1.f, fabsf(__fdiv_rn(num, den)));
            float nm1 = __fsub_rn(n, 1.f);
            float tvar = __fdiv_rn(tvs, nm1);
            float fvar = __fdiv_rn(fvs, nm1);
            float vl  = __fdiv_rn(fabsf(__fsub_rn(tvar, fvar)), __fadd_rn(tvar, 1e-8f));
            float ml  = __fdiv_rn(fabsf(__fsub_rn(mt, mf)), __fadd_rn(fabsf(mt), 1e-8f));
            lossAcc += (double)__fadd_rn(__fadd_rn(cl, vl), ml);
            cnt++;
        };

        if (slot < 3) {
            if ((flags >> slot) & 1) {
                int p = pP[slot * SBLK + s], ns = TT / p;
                for (int j = sub; j < ns; j += 21) accum(j * p, j * p + p);
                if (sub == 20 && ((flags >> (3 + slot)) & 1)) accum(ns * p, TT);
            }
        } else {
            if (flags & 64) accum(0, TT);
        }
    }

    // ---- Block reduce -> per-block partial slot (deterministic) ----
#pragma unroll
    for (int off = 16; off; off >>= 1) {
        lossAcc += __shfl_down_sync(0xffffffffu, lossAcc, off);
        mseAcc  += __shfl_down_sync(0xffffffffu, mseAcc,  off);
        cnt     += __shfl_down_sync(0xffffffffu, cnt,     off);
    }
    if (lane == 0) {
        redL[warp] = lossAcc; redM[warp] = (double)mseAcc; redCt[warp] = cnt;
    }
    __syncthreads();

    __shared__ unsigned int sLast;
    if (tid == 0) {
        double tL = 0.0, tM = 0.0; unsigned int tC = 0u;
#pragma unroll
        for (int w = 0; w < 16; w++) { tL += redL[w]; tM += redM[w]; tC += redCt[w]; }
        g_partL[blockIdx.x] = tL;
        g_partM[blockIdx.x] = tM;
        g_partC[blockIdx.x] = tC;
        __threadfence();
        sLast = (atomicAdd(&g_done, 1u) == (unsigned)(NBLK - 1));
    }
    __syncthreads();

    // ---- Last block: deterministic grand reduction ----
    if (sLast) {
        __threadfence();
        double L = 0.0, M = 0.0; unsigned long long C = 0ull;
        for (int i = tid; i < NBLK; i += NTHREADS) {
            L += g_partL[i]; M += g_partM[i]; C += (unsigned long long)g_partC[i];
        }
#pragma unroll
        for (int off = 16; off; off >>= 1) {
            L += __shfl_down_sync(0xffffffffu, L, off);
            M += __shfl_down_sync(0xffffffffu, M, off);
            C += __shfl_down_sync(0xffffffffu, C, off);
        }
        unsigned long long* sC = (unsigned long long*)(sm + OFF_U);  // reuse scratch
        if (lane == 0) { redL[warp] = L; redM[warp] = M; sC[warp] = C; }
        __syncthreads();
        if (tid == 0) {
            double tL = 0.0, tM = 0.0; unsigned long long tC = 0ull;
#pragma unroll
            for (int w = 0; w < 16; w++) { tL += redL[w]; tM += redM[w]; tC += sC[w]; }
            double mse = tM / (double)((long long)BDIM * TT * FDIM);
            double avg = (tC > 0ull) ? (tL / (double)tC) : 0.0;
            out[0] = (float)(0.5 * mse + 0.5 * avg);
            g_done = 0u;  // reset for next replay
        }
    }
}

extern "C" void kernel_launch(void* const* d_in, const int* in_sizes, int n_in,
                              void* d_out, int out_size) {
    const float* forecast = (const float*)d_in[0];
    const float* target   = (const float*)d_in[1];
    float* out = (float*)d_out;

    ps_tw<<<1, 512>>>();
    cudaFuncSetAttribute(ps_main, cudaFuncAttributeMaxDynamicSharedMemorySize, SMEM_BYTES);
    ps_main<<<NBLK, NTHREADS, SMEM_BYTES>>>(forecast, target, out);
}

// round 10
// speedup vs baseline: 2.5456x; 1.2327x over previous
#include <cuda_runtime.h>
#include <math.h>

// PSLoss: 0.5*MSE + 0.5*avg(structural patch loss)
// B=64, T=336, F=321. 20544 series of length 336 (stride F in memory).
// Spectrum: Cooley-Tukey 336 = 16 x 21; stage B as twiddle + 16-pt radix-4 FFT.
// Patch stats: fp32 cumsum with jax lax.associative_scan tree bracketing,
// segment sums as cs[e]-cs[s], exactly matching the reference arithmetic.
// R10: float2 pyramid, merged tiny tree levels (serial column phase),
//      top-3 overlapped with scan init, 13 barriers instead of 21.

#define TT      336
#define FDIM    321
#define BDIM    64
#define NBIN    168
#define SBLK    8         // series per block
#define SP      8         // tg/fc pitch
#define AP      9         // amp pitch
#define SPY     9         // yS (float2) pitch
#define NTHREADS 512
#define FTILES  41        // ceil(321/8)
#define NBLK    (BDIM * FTILES)
#define TASKP   40        // 5 quantities x 8 series
#define NPAIR   20        // task pairs (float2)

// float-index smem offsets
#define OFF_TG    0                      // 336*8 = 2688
#define OFF_FC    2688                   // 2688
#define OFF_U     5376                   // union: FFT scratch / pyramid 13320
#define OFF_AMP   (OFF_U + 10080)        // amp 168*9=1512 (L3/L4 rows, dead later)
#define OFF_TW21  (OFF_U + 13320)        // 24 float2 = 48 floats
#define OFF_PP    (OFF_TW21 + 48)        // 24 ints
#define OFF_FLAG  (OFF_PP + 24)          // 8 ints
#define OFF_RED   (OFF_FLAG + 8)         // 16 dbl + 16 dbl + 16 uint = 80 floats
#define SMEM_FLOATS (OFF_RED + 80)
#define SMEM_BYTES  (SMEM_FLOATS * 4)    // 75424 bytes -> 3 blocks/SM

__device__ float2 g_tw336[TT];
__device__ float2 g_tw21[24];
__device__ double g_partL[NBLK];
__device__ double g_partM[NBLK];
__device__ unsigned int g_partC[NBLK];
__device__ unsigned int g_done = 0u;

__global__ void ps_tw() {
    int i = threadIdx.x;
    if (i <= 84) {
        double s, c;
        sincospi((double)i / 168.0, &s, &c);
        g_tw336[i] = make_float2((float)c, (float)s);
    }
    __syncthreads();
    if (i >= 85 && i < TT) {
        float2 q;
        if (i <= 168)      { q = g_tw336[168 - i]; g_tw336[i] = make_float2(-q.x,  q.y); }
        else if (i <= 252) { q = g_tw336[i - 168]; g_tw336[i] = make_float2(-q.x, -q.y); }
        else               { q = g_tw336[336 - i]; g_tw336[i] = make_float2( q.x, -q.y); }
    }
    __syncthreads();
    if (i < 24) g_tw21[i] = g_tw336[(i < 21) ? 16 * i : 0];
}

__device__ __forceinline__ float prodq(float a, float v, int q) {
    switch (q) {
        case 0:  return a;
        case 1:  return v;
        case 2:  return __fmul_rn(a, a);
        case 3:  return __fmul_rn(v, v);
        default: return __fmul_rn(a, v);
    }
}

__device__ __forceinline__ float2 cmulc(float2 z, float2 w) {
    // z * (w.x - i*w.y)
    return make_float2(fmaf(z.y, w.y, z.x * w.x), fmaf(z.y, w.x, -z.x * w.y));
}
__device__ __forceinline__ float2 cadd(float2 a, float2 b) {
    return make_float2(a.x + b.x, a.y + b.y);
}
__device__ __forceinline__ float2 csub(float2 a, float2 b) {
    return make_float2(a.x - b.x, a.y - b.y);
}
__device__ __forceinline__ float2 fadd2(float2 a, float2 b) {
    return make_float2(__fadd_rn(a.x, b.x), __fadd_rn(a.y, b.y));
}

__global__ void __launch_bounds__(NTHREADS, 3)
ps_main(const float* __restrict__ fc, const float* __restrict__ tg,
        float* __restrict__ out) {
    extern __shared__ float sm[];
    float*  tgS   = sm + OFF_TG;
    float*  fcS   = sm + OFF_FC;
    float*  Pyr   = sm + OFF_U;                 // pyramid levels 1..8 (333 x 40)
    float2* yS    = (float2*)(sm + OFF_U);      // FFT scratch (overlaid earlier)
    float*  ampS  = sm + OFF_AMP;               // 168*9 (in L3/L4 rows)
    float2* tw21  = (float2*)(sm + OFF_TW21);
    int*    pP    = (int*)(sm + OFF_PP);
    int*    flagS = (int*)(sm + OFF_FLAG);
    double* redL  = (double*)(sm + OFF_RED);
    double* redM  = redL + 16;
    unsigned int* redCt = (unsigned int*)(redM + 16);

    const int tid  = threadIdx.x;
    const int lane = tid & 31;
    const int warp = tid >> 5;
    const int b    = blockIdx.x / FTILES;
    const int f0   = (blockIdx.x % FTILES) * SBLK;

    if (tid < 24) tw21[tid] = g_tw21[tid];

    // ---- Load tile + MSE partial ----
    float mseAcc = 0.f;
    {
        const int base = b * TT * FDIM + f0;
        for (int i = tid; i < TT * SBLK; i += NTHREADS) {
            int t = i >> 3, l = i & 7;
            float av = 0.f, bv = 0.f;
            if (f0 + l < FDIM) {
                int g = base + t * FDIM + l;
                av = tg[g]; bv = fc[g];
                float d = bv - av;
                mseAcc = fmaf(d, d, mseAcc);
            }
            tgS[t * SP + l] = av;
            fcS[t * SP + l] = bv;
        }
    }
    __syncthreads();

    // ---- Stage A: 21-pt DFT. tid -> (s, t1, quarter of r-range) ----
    {
        int s = tid & 7, t1 = (tid >> 3) & 15, quarter = tid >> 7;
        int r0 = quarter * 3, nr = (quarter == 3) ? 2 : 3;
        float yre[3], yim[3];
#pragma unroll
        for (int r = 0; r < 3; r++) { yre[r] = 0.f; yim[r] = 0.f; }
        for (int t2 = 0; t2 < 21; t2++) {
            float xv = tgS[(t1 + 16 * t2) * SP + s];
            int rt = (t2 * r0) % 21;
            for (int r = 0; r < nr; r++) {
                float2 w = tw21[rt];
                yre[r] = fmaf(xv,  w.x, yre[r]);
                yim[r] = fmaf(-xv, w.y, yim[r]);
                rt += t2; if (rt >= 21) rt -= 21;
            }
        }
        for (int r = 0; r < nr; r++)
            yS[(t1 * 11 + r0 + r) * SPY + s] = make_float2(yre[r], yim[r]);
    }
    __syncthreads();

    // ---- Stage B: per (s, r) residue class, twiddle + 16-pt FFT ----
    if (tid < 336) {
        const unsigned mask = (tid < 320) ? 0xFFFFFFFFu : 0x0000FFFFu;
        const int h = tid & 1, pair = tid >> 1;
        const int s = pair & 7, r = pair >> 3;            // r in 0..20
        const int r2 = (r <= 10) ? r : 21 - r;
        const float sgn = (r <= 10) ? 1.f : -1.f;

        float2 Z[4][2];
#pragma unroll
        for (int bi = 0; bi < 2; bi++) {
            int bb = 2 * h + bi;
#pragma unroll
            for (int a = 0; a < 4; a++) {
                int t1 = 4 * a + bb;
                float2 y = yS[(t1 * 11 + r2) * SPY + s];
                y.y *= sgn;
                float2 w = __ldg(&g_tw336[r * t1]);
                Z[a][bi] = cmulc(y, w);
            }
        }
        float2 G[4][2];
#pragma unroll
        for (int bi = 0; bi < 2; bi++) {
            float2 t0 = cadd(Z[0][bi], Z[2][bi]);
            float2 t1 = csub(Z[0][bi], Z[2][bi]);
            float2 t2 = cadd(Z[1][bi], Z[3][bi]);
            float2 t3 = csub(Z[1][bi], Z[3][bi]);
            G[0][bi] = cadd(t0, t2);
            G[2][bi] = csub(t0, t2);
            G[1][bi] = make_float2(t1.x + t3.y, t1.y - t3.x);
            G[3][bi] = make_float2(t1.x - t3.y, t1.y + t3.x);
        }
        const float C1 = 0.9238795325112867f, S1 = 0.3826834323650898f;
        const float C2 = 0.7071067811865476f;
        {
            float2 w;
            w = h ? make_float2(C2, C2)   : make_float2(1.f, 0.f);
            G[1][0] = cmulc(G[1][0], w);
            w = h ? make_float2(S1, C1)   : make_float2(C1, S1);
            G[1][1] = cmulc(G[1][1], w);
            w = h ? make_float2(0.f, 1.f) : make_float2(1.f, 0.f);
            G[2][0] = cmulc(G[2][0], w);
            w = h ? make_float2(-C2, C2)  : make_float2(C2, C2);
            G[2][1] = cmulc(G[2][1], w);
            w = h ? make_float2(-C2, C2)  : make_float2(1.f, 0.f);
            G[3][0] = cmulc(G[3][0], w);
            w = h ? make_float2(-C1, -S1) : make_float2(S1, C1);
            G[3][1] = cmulc(G[3][1], w);
        }
        float2 sA0 = h ? G[0][0] : G[2][0];
        float2 sA1 = h ? G[0][1] : G[2][1];
        float2 sB0 = h ? G[1][0] : G[3][0];
        float2 sB1 = h ? G[1][1] : G[3][1];
        float2 rA0, rA1, rB0, rB1;
        rA0.x = __shfl_xor_sync(mask, sA0.x, 1); rA0.y = __shfl_xor_sync(mask, sA0.y, 1);
        rA1.x = __shfl_xor_sync(mask, sA1.x, 1); rA1.y = __shfl_xor_sync(mask, sA1.y, 1);
        rB0.x = __shfl_xor_sync(mask, sB0.x, 1); rB0.y = __shfl_xor_sync(mask, sB0.y, 1);
        rB1.x = __shfl_xor_sync(mask, sB1.x, 1); rB1.y = __shfl_xor_sync(mask, sB1.y, 1);
        float2 kA0 = h ? G[2][0] : G[0][0];
        float2 kA1 = h ? G[2][1] : G[0][1];
        float2 kB0 = h ? G[3][0] : G[1][0];
        float2 kB1 = h ? G[3][1] : G[1][1];
        float2 HA0 = h ? rA0 : kA0, HA1 = h ? rA1 : kA1;
        float2 HA2 = h ? kA0 : rA0, HA3 = h ? kA1 : rA1;
        float2 HB0 = h ? rB0 : kB0, HB1 = h ? rB1 : kB1;
        float2 HB2 = h ? kB0 : rB0, HB3 = h ? kB1 : rB1;

#pragma unroll
        for (int part = 0; part < 2; part++) {
            float2 u0 = part ? HB0 : HA0, u1 = part ? HB1 : HA1;
            float2 u2 = part ? HB2 : HA2, u3 = part ? HB3 : HA3;
            int d = 2 * h + part;
            float2 t0 = cadd(u0, u2), t1 = csub(u0, u2);
            float2 t2 = cadd(u1, u3), t3 = csub(u1, u3);
            float2 X[4];
            X[0] = cadd(t0, t2);
            X[2] = csub(t0, t2);
            X[1] = make_float2(t1.x + t3.y, t1.y - t3.x);
            X[3] = make_float2(t1.x - t3.y, t1.y + t3.x);
#pragma unroll
            for (int c = 0; c < 4; c++) {
                int m = 4 * c + d;
                bool ok = (r == 0) ? (m >= 1 && m <= 8) : (m <= 7);
                if (ok) {
                    int f = r + 21 * m;
                    ampS[(f - 1) * AP + s] = fmaf(X[c].x, X[c].x, X[c].y * X[c].y);
                }
            }
        }
    }
    __syncthreads();

    // ---- Parallel phase: warps 0-7 top-3; warps 8-15 pyramid level-1 ----
    if (warp < SBLK) {
        const int s = warp;
        unsigned long long k1 = 0ull, k2 = 0ull, k3 = 0ull;
        for (int f = 1 + lane; f <= NBIN; f += 32) {
            float a = ampS[(f - 1) * AP + s];
            unsigned long long kk =
                ((unsigned long long)__float_as_uint(a) << 32) |
                (unsigned long long)(0xFFFFFFFFu - (unsigned)f);
            if (kk > k1)      { k3 = k2; k2 = k1; k1 = kk; }
            else if (kk > k2) { k3 = k2; k2 = kk; }
            else if (kk > k3) { k3 = kk; }
        }
        int fsel[3];
#pragma unroll
        for (int rnd = 0; rnd < 3; rnd++) {
            unsigned long long best = k1;
#pragma unroll
            for (int off = 16; off; off >>= 1) {
                unsigned long long o = __shfl_xor_sync(0xffffffffu, best, off);
                if (o > best) best = o;
            }
            fsel[rnd] = (int)(0xFFFFFFFFu - (unsigned)(best & 0xFFFFFFFFull));
            if (k1 == best) { k1 = k2; k2 = k3; k3 = 0ull; }
        }
        if (lane == 0) {
            int pp[3] = { TT / fsel[0], TT / fsel[1], TT / fsel[2] };
            bool active = (f0 + s) < FDIM;
            bool valid[3];
            valid[0] = active && pp[0] >= 5;
            valid[1] = active && pp[1] >= 5 && pp[1] != pp[0];
            valid[2] = active && pp[2] >= 5 && pp[2] != pp[0] && pp[2] != pp[1];
            int ns[3], L[3]; bool remv[3];
#pragma unroll
            for (int k = 0; k < 3; k++) {
                ns[k] = TT / pp[k];
                L[k]  = TT - ns[k] * pp[k];
                remv[k] = valid[k] && (L[k] >= 5);
            }
            int flags = 0;
#pragma unroll
            for (int k = 0; k < 3; k++) {
                if (valid[k]) flags |= (1 << k);
                bool inc = remv[k];
#pragma unroll
                for (int j = 0; j < 3; j++) {
                    if (valid[j] && pp[j] == L[k] && (TT % pp[j]) == 0) inc = false;
                    if (j < k && remv[j] && L[j] == L[k]) inc = false;
                }
                if (inc) flags |= (8 << k);
            }
            if (active && !(valid[0] || valid[1] || valid[2])) flags |= 64;
#pragma unroll
            for (int k = 0; k < 3; k++) pP[k * SBLK + s] = pp[k];
            flagS[s] = flags;
        }
    } else {
        // pyramid level 1: 168 rows x 20 pairs, float2
        for (int i = tid - 256; i < 168 * NPAIR; i += 256) {
            int j = i / NPAIR, pr = i - j * NPAIR;
            int q = pr >> 2, sb = (pr & 3) << 1;   // pair = tasks {q*8+sb, +1}
            int u = 2 * j;
            float2 a0 = *(const float2*)&tgS[u * SP + sb];
            float2 v0 = *(const float2*)&fcS[u * SP + sb];
            float2 a1 = *(const float2*)&tgS[(u + 1) * SP + sb];
            float2 v1 = *(const float2*)&fcS[(u + 1) * SP + sb];
            float2 x0 = make_float2(prodq(a0.x, v0.x, q), prodq(a0.y, v0.y, q));
            float2 x1 = make_float2(prodq(a1.x, v1.x, q), prodq(a1.y, v1.y, q));
            *(float2*)&Pyr[j * TASKP + 2 * pr] = fadd2(x0, x1);
        }
    }
    __syncthreads();

    // ---- Upsweep levels 2..4 (float2 over pairs) ----
    // Level row offsets: L1=0(168) L2=168(84) L3=252(42) L4=294(21)
    //                    L5=315(10) L6=325(5) L7=330(2) L8=332(1)
    const int pr  = tid % NPAIR;
    const int j0  = tid / NPAIR;      // 0..25 (tid<500 active)
    const int pc  = 2 * pr;
    {
        const int srcO[3] = { 0, 168, 252 };
        const int dstO[3] = { 168, 252, 294 };
        const int lenL[3] = { 84, 42, 21 };
#pragma unroll
        for (int L = 0; L < 3; L++) {
            if (tid < 500) {
                for (int j = j0; j < lenL[L]; j += 25) {
                    float2 a = *(const float2*)&Pyr[(srcO[L] + 2 * j) * TASKP + pc];
                    float2 c = *(const float2*)&Pyr[(srcO[L] + 2 * j + 1) * TASKP + pc];
                    *(float2*)&Pyr[(dstO[L] + j) * TASKP + pc] = fadd2(a, c);
                }
            }
            __syncthreads();
        }
    }

    // ---- Serial column phase: up levels {10,5,2,1} + down scans {2,5,10,21} ----
    if (tid < TASKP) {
        const int c = tid;
        for (int j = 0; j < 10; j++)
            Pyr[(315 + j) * TASKP + c] =
                __fadd_rn(Pyr[(294 + 2 * j) * TASKP + c], Pyr[(294 + 2 * j + 1) * TASKP + c]);
        for (int j = 0; j < 5; j++)
            Pyr[(325 + j) * TASKP + c] =
                __fadd_rn(Pyr[(315 + 2 * j) * TASKP + c], Pyr[(315 + 2 * j + 1) * TASKP + c]);
        for (int j = 0; j < 2; j++)
            Pyr[(330 + j) * TASKP + c] =
                __fadd_rn(Pyr[(325 + 2 * j) * TASKP + c], Pyr[(325 + 2 * j + 1) * TASKP + c]);
        Pyr[332 * TASKP + c] =
            __fadd_rn(Pyr[330 * TASKP + c], Pyr[331 * TASKP + c]);
        // downsweep (in place): dst becomes inclusive scan
        const int dO[4] = { 330, 325, 315, 294 };
        const int pO[4] = { 332, 330, 325, 315 };
        const int lL[4] = { 2, 5, 10, 21 };
#pragma unroll
        for (int L = 0; L < 4; L++) {
            for (int j = 1; j < lL[L]; j++) {
                float v;
                if (j & 1)
                    v = Pyr[(pO[L] + ((j - 1) >> 1)) * TASKP + c];
                else
                    v = __fadd_rn(Pyr[(pO[L] + (j >> 1) - 1) * TASKP + c],
                                  Pyr[(dO[L] + j) * TASKP + c]);
                Pyr[(dO[L] + j) * TASKP + c] = v;
            }
        }
    }
    __syncthreads();

    // ---- Downsweep levels 42, 84, 168 (float2 over pairs) ----
    {
        const int dstO[3] = { 252, 168, 0 };
        const int parO[3] = { 294, 252, 168 };
        const int lenL[3] = { 42, 84, 168 };
#pragma unroll
        for (int L = 0; L < 3; L++) {
            if (tid < 500) {
                for (int j = j0; j < lenL[L]; j += 25) {
                    if (j == 0) continue;  // scan[0] = elem[0]
                    float2 v;
                    if (j & 1) {
                        v = *(const float2*)&Pyr[(parO[L] + ((j - 1) >> 1)) * TASKP + pc];
                    } else {
                        float2 pv = *(const float2*)&Pyr[(parO[L] + (j >> 1) - 1) * TASKP + pc];
                        float2 cv = *(const float2*)&Pyr[(dstO[L] + j) * TASKP + pc];
                        v = fadd2(pv, cv);
                    }
                    *(float2*)&Pyr[(dstO[L] + j) * TASKP + pc] = v;
                }
            }
            __syncthreads();
        }
    }

    // ---- Walk: patch losses via cs[e]-cs[s] with reference arithmetic ----
    double lossAcc = 0.0; unsigned int cnt = 0u;
    {
        int s = tid & 7, w = tid >> 3;   // w in 0..63
        int slot, sub;
        if (w < 21)      { slot = 0; sub = w; }
        else if (w < 42) { slot = 1; sub = w - 21; }
        else if (w < 63) { slot = 2; sub = w - 42; }
        else             { slot = 3; sub = 0; }
        int flags = flagS[s];

        auto s0v = [&](int q, int u) -> float {
            if (u < 0) return 0.f;
            if (u & 1) return Pyr[((u - 1) >> 1) * TASKP + (q << 3) + s];
            float x = prodq(tgS[u * SP + s], fcS[u * SP + s], q);
            if (u == 0) return x;
            return __fadd_rn(Pyr[(((u >> 1) - 1)) * TASKP + (q << 3) + s], x);
        };
        auto accum = [&](int s0, int e0) {
            float n   = (float)(e0 - s0);
            float St  = __fsub_rn(s0v(0, e0 - 1), s0v(0, s0 - 1));
            float Sf  = __fsub_rn(s0v(1, e0 - 1), s0v(1, s0 - 1));
            float Stt = __fsub_rn(s0v(2, e0 - 1), s0v(2, s0 - 1));
            float Sff = __fsub_rn(s0v(3, e0 - 1), s0v(3, s0 - 1));
            float Stf = __fsub_rn(s0v(4, e0 - 1), s0v(4, s0 - 1));
            float mt  = __fdiv_rn(St, n);
            float mf  = __fdiv_rn(Sf, n);
            float tvs = fmaxf(__fsub_rn(Stt, __fmul_rn(__fmul_rn(n, mt), mt)), 0.f);
            float fvs = fmaxf(__fsub_rn(Sff, __fmul_rn(__fmul_rn(n, mf), mf)), 0.f);
            float num = __fsub_rn(Stf, __fmul_rn(__fmul_rn(n, mt), mf));
            float den = __fadd_rn(__fsqrt_rn(__fmul_rn(tvs, fvs)), 1e-8f);
            float cl  = __fsub_rn(1.f, fabsf(__fdiv_rn(num, den)));
            float nm1 = __fsub_rn(n, 1.f);
            float tvar = __fdiv_rn(tvs, nm1);
            float fvar = __fdiv_rn(fvs, nm1);
            float vl  = __fdiv_rn(fabsf(__fsub_rn(tvar, fvar)), __fadd_rn(tvar, 1e-8f));
            float ml  = __fdiv_rn(fabsf(__fsub_rn(mt, mf)), __fadd_rn(fabsf(mt), 1e-8f));
            lossAcc += (double)__fadd_rn(__fadd_rn(cl, vl), ml);
            cnt++;
        };

        if (slot < 3) {
            if ((flags >> slot) & 1) {
                int p = pP[slot * SBLK + s], ns = TT / p;
                for (int j = sub; j < ns; j += 21) accum(j * p, j * p + p);
                if (sub == 20 && ((flags >> (3 + slot)) & 1)) accum(ns * p, TT);
            }
        } else {
            if (flags & 64) accum(0, TT);
        }
    }

    // ---- Block reduce -> per-block partial slot (deterministic) ----
#pragma unroll
    for (int off = 16; off; off >>= 1) {
        lossAcc += __shfl_down_sync(0xffffffffu, lossAcc, off);
        mseAcc  += __shfl_down_sync(0xffffffffu, mseAcc,  off);
        cnt     += __shfl_down_sync(0xffffffffu, cnt,     off);
    }
    if (lane == 0) {
        redL[warp] = lossAcc; redM[warp] = (double)mseAcc; redCt[warp] = cnt;
    }
    __syncthreads();

    __shared__ unsigned int sLast;
    if (tid == 0) {
        double tL = 0.0, tM = 0.0; unsigned int tC = 0u;
#pragma unroll
        for (int w = 0; w < 16; w++) { tL += redL[w]; tM += redM[w]; tC += redCt[w]; }
        g_partL[blockIdx.x] = tL;
        g_partM[blockIdx.x] = tM;
        g_partC[blockIdx.x] = tC;
        __threadfence();
        sLast = (atomicAdd(&g_done, 1u) == (unsigned)(NBLK - 1));
    }
    __syncthreads();

    // ---- Last block: deterministic grand reduction ----
    if (sLast) {
        __threadfence();
        double L = 0.0, M = 0.0; unsigned long long C = 0ull;
        for (int i = tid; i < NBLK; i += NTHREADS) {
            L += g_partL[i]; M += g_partM[i]; C += (unsigned long long)g_partC[i];
        }
#pragma unroll
        for (int off = 16; off; off >>= 1) {
            L += __shfl_down_sync(0xffffffffu, L, off);
            M += __shfl_down_sync(0xffffffffu, M, off);
            C += __shfl_down_sync(0xffffffffu, C, off);
        }
        unsigned long long* sC = (unsigned long long*)(sm + OFF_U);  // reuse scratch
        if (lane == 0) { redL[warp] = L; redM[warp] = M; sC[warp] = C; }
        __syncthreads();
        if (tid == 0) {
            double tL = 0.0, tM = 0.0; unsigned long long tC = 0ull;
#pragma unroll
            for (int w = 0; w < 16; w++) { tL += redL[w]; tM += redM[w]; tC += sC[w]; }
            double mse = tM / (double)((long long)BDIM * TT * FDIM);
            double avg = (tC > 0ull) ? (tL / (double)tC) : 0.0;
            out[0] = (float)(0.5 * mse + 0.5 * avg);
            g_done = 0u;  // reset for next replay
        }
    }
}

extern "C" void kernel_launch(void* const* d_in, const int* in_sizes, int n_in,
                              void* d_out, int out_size) {
    const float* forecast = (const float*)d_in[0];
    const float* target   = (const float*)d_in[1];
    float* out = (float*)d_out;

    ps_tw<<<1, 512>>>();
    cudaFuncSetAttribute(ps_main, cudaFuncAttributeMaxDynamicSharedMemorySize, SMEM_BYTES);
    ps_main<<<NBLK, NTHREADS, SMEM_BYTES>>>(forecast, target, out);
}

// round 11
// speedup vs baseline: 2.7149x; 1.0665x over previous
#include <cuda_runtime.h>
#include <math.h>

// PSLoss: 0.5*MSE + 0.5*avg(structural patch loss)
// B=64, T=336, F=321. 20544 series of length 336 (stride F in memory).
// Spectrum: 336 = 16 x 21; 21-pt DFT via PFA 3x7 (literal constants, no
// twiddle tables), then 16-pt radix-4 FFT per residue class.
// Patch stats: fp32 cumsum with jax lax.associative_scan tree bracketing,
// segment sums as cs[e]-cs[s], exactly matching the reference arithmetic.
// R11: PFA stage A (kills tw21 smem loads), rest as R10.

#define TT      336
#define FDIM    321
#define BDIM    64
#define NBIN    168
#define SBLK    8         // series per block
#define SP      8         // tg/fc pitch
#define AP      9         // amp pitch
#define SPY     9         // yS (float2) pitch
#define SPG     9         // G (float2) pitch
#define NTHREADS 512
#define FTILES  41        // ceil(321/8)
#define NBLK    (BDIM * FTILES)
#define TASKP   40        // 5 quantities x 8 series
#define NPAIR   20        // task pairs (float2)

// float-index smem offsets
#define OFF_TG    0                      // 336*8 = 2688
#define OFF_FC    2688                   // 2688
#define OFF_U     5376                   // union: FFT scratch / pyramid 13320
#define OFF_G     (OFF_U + 3168)         // G: 192 rows x 9 float2 = 3456 floats
#define OFF_AMP   (OFF_U + 10080)        // amp 168*9=1512 (L3/L4 rows, dead later)
#define OFF_PP    (OFF_U + 13320)        // 24 ints
#define OFF_FLAG  (OFF_PP + 24)          // 8 ints
#define OFF_RED   (OFF_FLAG + 8)         // 16 dbl + 16 dbl + 16 uint = 80 floats
#define SMEM_FLOATS (OFF_RED + 80)
#define SMEM_BYTES  (SMEM_FLOATS * 4)    // ~75.3KB -> 3 blocks/SM

// 7th-root constants (cos/sin 2*pi*k/7)
#define C7_1  0.6234898018587336f
#define C7_2 -0.2225209339563144f
#define C7_3 -0.9009688679024191f
#define S7_1  0.7818314824680298f
#define S7_2  0.9749279121818236f
#define S7_3  0.4338837391175581f
#define SQ32  0.8660254037844386f

__device__ float2 g_tw336[TT];
__device__ double g_partL[NBLK];
__device__ double g_partM[NBLK];
__device__ unsigned int g_partC[NBLK];
__device__ unsigned int g_done = 0u;

__global__ void ps_tw() {
    int i = threadIdx.x;
    if (i <= 84) {
        double s, c;
        sincospi((double)i / 168.0, &s, &c);
        g_tw336[i] = make_float2((float)c, (float)s);
    }
    __syncthreads();
    if (i >= 85 && i < TT) {
        float2 q;
        if (i <= 168)      { q = g_tw336[168 - i]; g_tw336[i] = make_float2(-q.x,  q.y); }
        else if (i <= 252) { q = g_tw336[i - 168]; g_tw336[i] = make_float2(-q.x, -q.y); }
        else               { q = g_tw336[336 - i]; g_tw336[i] = make_float2( q.x, -q.y); }
    }
}

__device__ __forceinline__ float prodq(float a, float v, int q) {
    switch (q) {
        case 0:  return a;
        case 1:  return v;
        case 2:  return __fmul_rn(a, a);
        case 3:  return __fmul_rn(v, v);
        default: return __fmul_rn(a, v);
    }
}

__device__ __forceinline__ float2 cmulc(float2 z, float2 w) {
    // z * (w.x - i*w.y)
    return make_float2(fmaf(z.y, w.y, z.x * w.x), fmaf(z.y, w.x, -z.x * w.y));
}
__device__ __forceinline__ float2 cadd(float2 a, float2 b) {
    return make_float2(a.x + b.x, a.y + b.y);
}
__device__ __forceinline__ float2 csub(float2 a, float2 b) {
    return make_float2(a.x - b.x, a.y - b.y);
}
__device__ __forceinline__ float2 fadd2(float2 a, float2 b) {
    return make_float2(__fadd_rn(a.x, b.x), __fadd_rn(a.y, b.y));
}
// 3-point combines: Y = A + B*e^{-2pi i k/3} + C*e^{-4pi i k/3}
__device__ __forceinline__ float2 comb_k0(float2 A, float2 B, float2 C) {
    return make_float2(A.x + B.x + C.x, A.y + B.y + C.y);
}
__device__ __forceinline__ float2 comb_k1(float2 A, float2 B, float2 C) {
    return make_float2(A.x - 0.5f * (B.x + C.x) + SQ32 * (B.y - C.y),
                       A.y - 0.5f * (B.y + C.y) - SQ32 * (B.x - C.x));
}
__device__ __forceinline__ float2 comb_k2(float2 A, float2 B, float2 C) {
    return make_float2(A.x - 0.5f * (B.x + C.x) - SQ32 * (B.y - C.y),
                       A.y - 0.5f * (B.y + C.y) + SQ32 * (B.x - C.x));
}

__global__ void __launch_bounds__(NTHREADS, 3)
ps_main(const float* __restrict__ fc, const float* __restrict__ tg,
        float* __restrict__ out) {
    extern __shared__ float sm[];
    float*  tgS   = sm + OFF_TG;
    float*  fcS   = sm + OFF_FC;
    float*  Pyr   = sm + OFF_U;                 // pyramid levels 1..8 (333 x 40)
    float2* yS    = (float2*)(sm + OFF_U);      // FFT scratch (overlaid earlier)
    float2* GS    = (float2*)(sm + OFF_G);      // 7-pt DFT outputs
    float*  ampS  = sm + OFF_AMP;               // 168*9 (in L3/L4 rows)
    int*    pP    = (int*)(sm + OFF_PP);
    int*    flagS = (int*)(sm + OFF_FLAG);
    double* redL  = (double*)(sm + OFF_RED);
    double* redM  = redL + 16;
    unsigned int* redCt = (unsigned int*)(redM + 16);

    const int tid  = threadIdx.x;
    const int lane = tid & 31;
    const int warp = tid >> 5;
    const int b    = blockIdx.x / FTILES;
    const int f0   = (blockIdx.x % FTILES) * SBLK;

    // ---- Load tile + MSE partial ----
    float mseAcc = 0.f;
    {
        const int base = b * TT * FDIM + f0;
        for (int i = tid; i < TT * SBLK; i += NTHREADS) {
            int t = i >> 3, l = i & 7;
            float av = 0.f, bv = 0.f;
            if (f0 + l < FDIM) {
                int g = base + t * FDIM + l;
                av = tg[g]; bv = fc[g];
                float d = bv - av;
                mseAcc = fmaf(d, d, mseAcc);
            }
            tgS[t * SP + l] = av;
            fcS[t * SP + l] = bv;
        }
    }
    __syncthreads();

    // ---- Stage A1: 7-point real DFTs (PFA inner). tid -> (s, t1, t3) ----
    if (tid < 384) {
        int s = tid & 7, t1 = (tid >> 3) & 15, t3 = tid >> 7;
        float xv[7];
#pragma unroll
        for (int t7 = 0; t7 < 7; t7++) {
            int t2 = 7 * t3 + 3 * t7; if (t2 >= 21) t2 -= 21;
            xv[t7] = tgS[(t1 + 16 * t2) * SP + s];
        }
        float s1 = xv[1] + xv[6], d1 = xv[1] - xv[6];
        float s2 = xv[2] + xv[5], d2 = xv[2] - xv[5];
        float s3 = xv[3] + xv[4], d3 = xv[3] - xv[4];
        float2 G0 = make_float2(xv[0] + s1 + s2 + s3, 0.f);
        float2 G1 = make_float2(
            xv[0] + s1 * C7_1 + s2 * C7_2 + s3 * C7_3,
            -(d1 * S7_1 + d2 * S7_2 + d3 * S7_3));
        float2 G2 = make_float2(
            xv[0] + s1 * C7_2 + s2 * C7_3 + s3 * C7_1,
            -d1 * S7_2 + d2 * S7_3 + d3 * S7_1);
        float2 G3 = make_float2(
            xv[0] + s1 * C7_3 + s2 * C7_1 + s3 * C7_2,
            -(d1 * S7_3 - d2 * S7_1 + d3 * S7_2));
        int row = (t1 * 3 + t3) * 4;
        GS[(row + 0) * SPG + s] = G0;
        GS[(row + 1) * SPG + s] = G1;
        GS[(row + 2) * SPG + s] = G2;
        GS[(row + 3) * SPG + s] = G3;
    }
    __syncthreads();

    // ---- Stage A2: 3-point combines (PFA outer). tid -> (s, t1, quarter) ----
    // r = 3*quarter + j, j in {0,1,2} (quarter 3: j in {0,1}); k3 = r mod 3 = j.
    // r7 = r mod 7; r7 > 3 -> conj(G[7-r7]).
    {
        int s = tid & 7, t1 = (tid >> 3) & 15, quarter = tid >> 7;
        // per-quarter G-row select and conj sign for j = 0,1,2
        int rs0 = (quarter == 0) ? 0 : (quarter == 1) ? 3 : (quarter == 2) ? 1 : 2;
        int rs1 = (quarter == 0) ? 1 : (quarter == 1) ? 3 : (quarter == 2) ? 0 : 3;
        int rs2 = (quarter == 0) ? 2 : (quarter == 1) ? 2 : 1;   // q3 unused
        float sg0 = (quarter == 2) ? -1.f : 1.f;
        float sg1 = (quarter == 1) ? -1.f : 1.f;
        float sg2 = (quarter == 1) ? -1.f : 1.f;
        int rowb = t1 * 3 * 4;
        int r0 = 3 * quarter;
        {
            float2 A = GS[(rowb + rs0) * SPG + s];
            float2 Bv = GS[(rowb + 4 + rs0) * SPG + s];
            float2 Cv = GS[(rowb + 8 + rs0) * SPG + s];
            A.y *= sg0; Bv.y *= sg0; Cv.y *= sg0;
            yS[(t1 * 11 + r0) * SPY + s] = comb_k0(A, Bv, Cv);
        }
        {
            float2 A = GS[(rowb + rs1) * SPG + s];
            float2 Bv = GS[(rowb + 4 + rs1) * SPG + s];
            float2 Cv = GS[(rowb + 8 + rs1) * SPG + s];
            A.y *= sg1; Bv.y *= sg1; Cv.y *= sg1;
            yS[(t1 * 11 + r0 + 1) * SPY + s] = comb_k1(A, Bv, Cv);
        }
        if (quarter < 3) {
            float2 A = GS[(rowb + rs2) * SPG + s];
            float2 Bv = GS[(rowb + 4 + rs2) * SPG + s];
            float2 Cv = GS[(rowb + 8 + rs2) * SPG + s];
            A.y *= sg2; Bv.y *= sg2; Cv.y *= sg2;
            yS[(t1 * 11 + r0 + 2) * SPY + s] = comb_k2(A, Bv, Cv);
        }
    }
    __syncthreads();

    // ---- Stage B: per (s, r) residue class, twiddle + 16-pt FFT ----
    if (tid < 336) {
        const unsigned mask = (tid < 320) ? 0xFFFFFFFFu : 0x0000FFFFu;
        const int h = tid & 1, pair = tid >> 1;
        const int s = pair & 7, r = pair >> 3;            // r in 0..20
        const int r2 = (r <= 10) ? r : 21 - r;
        const float sgn = (r <= 10) ? 1.f : -1.f;

        float2 Z[4][2];
#pragma unroll
        for (int bi = 0; bi < 2; bi++) {
            int bb = 2 * h + bi;
#pragma unroll
            for (int a = 0; a < 4; a++) {
                int t1 = 4 * a + bb;
                float2 y = yS[(t1 * 11 + r2) * SPY + s];
                y.y *= sgn;
                float2 w = __ldg(&g_tw336[r * t1]);
                Z[a][bi] = cmulc(y, w);
            }
        }
        float2 G[4][2];
#pragma unroll
        for (int bi = 0; bi < 2; bi++) {
            float2 t0 = cadd(Z[0][bi], Z[2][bi]);
            float2 t1 = csub(Z[0][bi], Z[2][bi]);
            float2 t2 = cadd(Z[1][bi], Z[3][bi]);
            float2 t3 = csub(Z[1][bi], Z[3][bi]);
            G[0][bi] = cadd(t0, t2);
            G[2][bi] = csub(t0, t2);
            G[1][bi] = make_float2(t1.x + t3.y, t1.y - t3.x);
            G[3][bi] = make_float2(t1.x - t3.y, t1.y + t3.x);
        }
        const float C1 = 0.9238795325112867f, S1 = 0.3826834323650898f;
        const float C2 = 0.7071067811865476f;
        {
            float2 w;
            w = h ? make_float2(C2, C2)   : make_float2(1.f, 0.f);
            G[1][0] = cmulc(G[1][0], w);
            w = h ? make_float2(S1, C1)   : make_float2(C1, S1);
            G[1][1] = cmulc(G[1][1], w);
            w = h ? make_float2(0.f, 1.f) : make_float2(1.f, 0.f);
            G[2][0] = cmulc(G[2][0], w);
            w = h ? make_float2(-C2, C2)  : make_float2(C2, C2);
            G[2][1] = cmulc(G[2][1], w);
            w = h ? make_float2(-C2, C2)  : make_float2(1.f, 0.f);
            G[3][0] = cmulc(G[3][0], w);
            w = h ? make_float2(-C1, -S1) : make_float2(S1, C1);
            G[3][1] = cmulc(G[3][1], w);
        }
        float2 sA0 = h ? G[0][0] : G[2][0];
        float2 sA1 = h ? G[0][1] : G[2][1];
        float2 sB0 = h ? G[1][0] : G[3][0];
        float2 sB1 = h ? G[1][1] : G[3][1];
        float2 rA0, rA1, rB0, rB1;
        rA0.x = __shfl_xor_sync(mask, sA0.x, 1); rA0.y = __shfl_xor_sync(mask, sA0.y, 1);
        rA1.x = __shfl_xor_sync(mask, sA1.x, 1); rA1.y = __shfl_xor_sync(mask, sA1.y, 1);
        rB0.x = __shfl_xor_sync(mask, sB0.x, 1); rB0.y = __shfl_xor_sync(mask, sB0.y, 1);
        rB1.x = __shfl_xor_sync(mask, sB1.x, 1); rB1.y = __shfl_xor_sync(mask, sB1.y, 1);
        float2 kA0 = h ? G[2][0] : G[0][0];
        float2 kA1 = h ? G[2][1] : G[0][1];
        float2 kB0 = h ? G[3][0] : G[1][0];
        float2 kB1 = h ? G[3][1] : G[1][1];
        float2 HA0 = h ? rA0 : kA0, HA1 = h ? rA1 : kA1;
        float2 HA2 = h ? kA0 : rA0, HA3 = h ? kA1 : rA1;
        float2 HB0 = h ? rB0 : kB0, HB1 = h ? rB1 : kB1;
        float2 HB2 = h ? kB0 : rB0, HB3 = h ? kB1 : rB1;

#pragma unroll
        for (int part = 0; part < 2; part++) {
            float2 u0 = part ? HB0 : HA0, u1 = part ? HB1 : HA1;
            float2 u2 = part ? HB2 : HA2, u3 = part ? HB3 : HA3;
            int d = 2 * h + part;
            float2 t0 = cadd(u0, u2), t1 = csub(u0, u2);
            float2 t2 = cadd(u1, u3), t3 = csub(u1, u3);
            float2 X[4];
            X[0] = cadd(t0, t2);
            X[2] = csub(t0, t2);
            X[1] = make_float2(t1.x + t3.y, t1.y - t3.x);
            X[3] = make_float2(t1.x - t3.y, t1.y + t3.x);
#pragma unroll
            for (int c = 0; c < 4; c++) {
                int m = 4 * c + d;
                bool ok = (r == 0) ? (m >= 1 && m <= 8) : (m <= 7);
                if (ok) {
                    int f = r + 21 * m;
                    ampS[(f - 1) * AP + s] = fmaf(X[c].x, X[c].x, X[c].y * X[c].y);
                }
            }
        }
    }
    __syncthreads();

    // ---- Parallel phase: warps 0-7 top-3; warps 8-15 pyramid level-1 ----
    if (warp < SBLK) {
        const int s = warp;
        unsigned long long k1 = 0ull, k2 = 0ull, k3 = 0ull;
        for (int f = 1 + lane; f <= NBIN; f += 32) {
            float a = ampS[(f - 1) * AP + s];
            unsigned long long kk =
                ((unsigned long long)__float_as_uint(a) << 32) |
                (unsigned long long)(0xFFFFFFFFu - (unsigned)f);
            if (kk > k1)      { k3 = k2; k2 = k1; k1 = kk; }
            else if (kk > k2) { k3 = k2; k2 = kk; }
            else if (kk > k3) { k3 = kk; }
        }
        int fsel[3];
#pragma unroll
        for (int rnd = 0; rnd < 3; rnd++) {
            unsigned long long best = k1;
#pragma unroll
            for (int off = 16; off; off >>= 1) {
                unsigned long long o = __shfl_xor_sync(0xffffffffu, best, off);
                if (o > best) best = o;
            }
            fsel[rnd] = (int)(0xFFFFFFFFu - (unsigned)(best & 0xFFFFFFFFull));
            if (k1 == best) { k1 = k2; k2 = k3; k3 = 0ull; }
        }
        if (lane == 0) {
            int pp[3] = { TT / fsel[0], TT / fsel[1], TT / fsel[2] };
            bool active = (f0 + s) < FDIM;
            bool valid[3];
            valid[0] = active && pp[0] >= 5;
            valid[1] = active && pp[1] >= 5 && pp[1] != pp[0];
            valid[2] = active && pp[2] >= 5 && pp[2] != pp[0] && pp[2] != pp[1];
            int ns[3], L[3]; bool remv[3];
#pragma unroll
            for (int k = 0; k < 3; k++) {
                ns[k] = TT / pp[k];
                L[k]  = TT - ns[k] * pp[k];
                remv[k] = valid[k] && (L[k] >= 5);
            }
            int flags = 0;
#pragma unroll
            for (int k = 0; k < 3; k++) {
                if (valid[k]) flags |= (1 << k);
                bool inc = remv[k];
#pragma unroll
                for (int j = 0; j < 3; j++) {
                    if (valid[j] && pp[j] == L[k] && (TT % pp[j]) == 0) inc = false;
                    if (j < k && remv[j] && L[j] == L[k]) inc = false;
                }
                if (inc) flags |= (8 << k);
            }
            if (active && !(valid[0] || valid[1] || valid[2])) flags |= 64;
#pragma unroll
            for (int k = 0; k < 3; k++) pP[k * SBLK + s] = pp[k];
            flagS[s] = flags;
        }
    } else {
        // pyramid level 1: 168 rows x 20 pairs, float2
        for (int i = tid - 256; i < 168 * NPAIR; i += 256) {
            int j = i / NPAIR, pr = i - j * NPAIR;
            int q = pr >> 2, sb = (pr & 3) << 1;   // pair = tasks {q*8+sb, +1}
            int u = 2 * j;
            float2 a0 = *(const float2*)&tgS[u * SP + sb];
            float2 v0 = *(const float2*)&fcS[u * SP + sb];
            float2 a1 = *(const float2*)&tgS[(u + 1) * SP + sb];
            float2 v1 = *(const float2*)&fcS[(u + 1) * SP + sb];
            float2 x0 = make_float2(prodq(a0.x, v0.x, q), prodq(a0.y, v0.y, q));
            float2 x1 = make_float2(prodq(a1.x, v1.x, q), prodq(a1.y, v1.y, q));
            *(float2*)&Pyr[j * TASKP + 2 * pr] = fadd2(x0, x1);
        }
    }
    __syncthreads();

    // ---- Upsweep levels 2..4 (float2 over pairs) ----
    // Level row offsets: L1=0(168) L2=168(84) L3=252(42) L4=294(21)
    //                    L5=315(10) L6=325(5) L7=330(2) L8=332(1)
    const int pr  = tid % NPAIR;
    const int j0  = tid / NPAIR;      // 0..25 (tid<500 active)
    const int pc  = 2 * pr;
    {
        const int srcO[3] = { 0, 168, 252 };
        const int dstO[3] = { 168, 252, 294 };
        const int lenL[3] = { 84, 42, 21 };
#pragma unroll
        for (int L = 0; L < 3; L++) {
            if (tid < 500) {
                for (int j = j0; j < lenL[L]; j += 25) {
                    float2 a = *(const float2*)&Pyr[(srcO[L] + 2 * j) * TASKP + pc];
                    float2 c = *(const float2*)&Pyr[(srcO[L] + 2 * j + 1) * TASKP + pc];
                    *(float2*)&Pyr[(dstO[L] + j) * TASKP + pc] = fadd2(a, c);
                }
            }
            __syncthreads();
        }
    }

    // ---- Serial column phase: up levels {10,5,2,1} + down scans {2,5,10,21} ----
    if (tid < TASKP) {
        const int c = tid;
        for (int j = 0; j < 10; j++)
            Pyr[(315 + j) * TASKP + c] =
                __fadd_rn(Pyr[(294 + 2 * j) * TASKP + c], Pyr[(294 + 2 * j + 1) * TASKP + c]);
        for (int j = 0; j < 5; j++)
            Pyr[(325 + j) * TASKP + c] =
                __fadd_rn(Pyr[(315 + 2 * j) * TASKP + c], Pyr[(315 + 2 * j + 1) * TASKP + c]);
        for (int j = 0; j < 2; j++)
            Pyr[(330 + j) * TASKP + c] =
                __fadd_rn(Pyr[(325 + 2 * j) * TASKP + c], Pyr[(325 + 2 * j + 1) * TASKP + c]);
        Pyr[332 * TASKP + c] =
            __fadd_rn(Pyr[330 * TASKP + c], Pyr[331 * TASKP + c]);
        const int dO[4] = { 330, 325, 315, 294 };
        const int pO[4] = { 332, 330, 325, 315 };
        const int lL[4] = { 2, 5, 10, 21 };
#pragma unroll
        for (int L = 0; L < 4; L++) {
            for (int j = 1; j < lL[L]; j++) {
                float v;
                if (j & 1)
                    v = Pyr[(pO[L] + ((j - 1) >> 1)) * TASKP + c];
                else
                    v = __fadd_rn(Pyr[(pO[L] + (j >> 1) - 1) * TASKP + c],
                                  Pyr[(dO[L] + j) * TASKP + c]);
                Pyr[(dO[L] + j) * TASKP + c] = v;
            }
        }
    }
    __syncthreads();

    // ---- Downsweep levels 42, 84, 168 (float2 over pairs) ----
    {
        const int dstO[3] = { 252, 168, 0 };
        const int parO[3] = { 294, 252, 168 };
        const int lenL[3] = { 42, 84, 168 };
#pragma unroll
        for (int L = 0; L < 3; L++) {
            if (tid < 500) {
                for (int j = j0; j < lenL[L]; j += 25) {
                    if (j == 0) continue;  // scan[0] = elem[0]
                    float2 v;
                    if (j & 1) {
                        v = *(const float2*)&Pyr[(parO[L] + ((j - 1) >> 1)) * TASKP + pc];
                    } else {
                        float2 pv = *(const float2*)&Pyr[(parO[L] + (j >> 1) - 1) * TASKP + pc];
                        float2 cv = *(const float2*)&Pyr[(dstO[L] + j) * TASKP + pc];
                        v = fadd2(pv, cv);
                    }
                    *(float2*)&Pyr[(dstO[L] + j) * TASKP + pc] = v;
                }
            }
            __syncthreads();
        }
    }

    // ---- Walk: patch losses via cs[e]-cs[s] with reference arithmetic ----
    double lossAcc = 0.0; unsigned int cnt = 0u;
    {
        int s = tid & 7, w = tid >> 3;   // w in 0..63
        int slot, sub;
        if (w < 21)      { slot = 0; sub = w; }
        else if (w < 42) { slot = 1; sub = w - 21; }
        else if (w < 63) { slot = 2; sub = w - 42; }
        else             { slot = 3; sub = 0; }
        int flags = flagS[s];

        auto s0v = [&](int q, int u) -> float {
            if (u < 0) return 0.f;
            if (u & 1) return Pyr[((u - 1) >> 1) * TASKP + (q << 3) + s];
            float x = prodq(tgS[u * SP + s], fcS[u * SP + s], q);
            if (u == 0) return x;
            return __fadd_rn(Pyr[(((u >> 1) - 1)) * TASKP + (q << 3) + s], x);
        };
        auto accum = [&](int s0, int e0) {
            float n   = (float)(e0 - s0);
            float St  = __fsub_rn(s0v(0, e0 - 1), s0v(0, s0 - 1));
            float Sf  = __fsub_rn(s0v(1, e0 - 1), s0v(1, s0 - 1));
            float Stt = __fsub_rn(s0v(2, e0 - 1), s0v(2, s0 - 1));
            float Sff = __fsub_rn(s0v(3, e0 - 1), s0v(3, s0 - 1));
            float Stf = __fsub_rn(s0v(4, e0 - 1), s0v(4, s0 - 1));
            float mt  = __fdiv_rn(St, n);
            float mf  = __fdiv_rn(Sf, n);
            float tvs = fmaxf(__fsub_rn(Stt, __fmul_rn(__fmul_rn(n, mt), mt)), 0.f);
            float fvs = fmaxf(__fsub_rn(Sff, __fmul_rn(__fmul_rn(n, mf), mf)), 0.f);
            float num = __fsub_rn(Stf, __fmul_rn(__fmul_rn(n, mt), mf));
            float den = __fadd_rn(__fsqrt_rn(__fmul_rn(tvs, fvs)), 1e-8f);
            float cl  = __fsub_rn(1.f, fabsf(__fdiv_rn(num, den)));
            float nm1 = __fsub_rn(n, 1.f);
            float tvar = __fdiv_rn(tvs, nm1);
            float fvar = __fdiv_rn(fvs, nm1);
            float vl  = __fdiv_rn(fabsf(__fsub_rn(tvar, fvar)), __fadd_rn(tvar, 1e-8f));
            float ml  = __fdiv_rn(fabsf(__fsub_rn(mt, mf)), __fadd_rn(fabsf(mt), 1e-8f));
            lossAcc += (double)__fadd_rn(__fadd_rn(cl, vl), ml);
            cnt++;
        };

        if (slot < 3) {
            if ((flags >> slot) & 1) {
                int p = pP[slot * SBLK + s], ns = TT / p;
                for (int j = sub; j < ns; j += 21) accum(j * p, j * p + p);
                if (sub == 20 && ((flags >> (3 + slot)) & 1)) accum(ns * p, TT);
            }
        } else {
            if (flags & 64) accum(0, TT);
        }
    }

    // ---- Block reduce -> per-block partial slot (deterministic) ----
#pragma unroll
    for (int off = 16; off; off >>= 1) {
        lossAcc += __shfl_down_sync(0xffffffffu, lossAcc, off);
        mseAcc  += __shfl_down_sync(0xffffffffu, mseAcc,  off);
        cnt     += __shfl_down_sync(0xffffffffu, cnt,     off);
    }
    if (lane == 0) {
        redL[warp] = lossAcc; redM[warp] = (double)mseAcc; redCt[warp] = cnt;
    }
    __syncthreads();

    __shared__ unsigned int sLast;
    if (tid == 0) {
        double tL = 0.0, tM = 0.0; unsigned int tC = 0u;
#pragma unroll
        for (int w = 0; w < 16; w++) { tL += redL[w]; tM += redM[w]; tC += redCt[w]; }
        g_partL[blockIdx.x] = tL;
        g_partM[blockIdx.x] = tM;
        g_partC[blockIdx.x] = tC;
        __threadfence();
        sLast = (atomicAdd(&g_done, 1u) == (unsigned)(NBLK - 1));
    }
    __syncthreads();

    // ---- Last block: deterministic grand reduction ----
    if (sLast) {
        __threadfence();
        double L = 0.0, M = 0.0; unsigned long long C = 0ull;
        for (int i = tid; i < NBLK; i += NTHREADS) {
            L += g_partL[i]; M += g_partM[i]; C += (unsigned long long)g_partC[i];
        }
#pragma unroll
        for (int off = 16; off; off >>= 1) {
            L += __shfl_down_sync(0xffffffffu, L, off);
            M += __shfl_down_sync(0xffffffffu, M, off);
            C += __shfl_down_sync(0xffffffffu, C, off);
        }
        unsigned long long* sC = (unsigned long long*)(sm + OFF_U);  // reuse scratch
        if (lane == 0) { redL[warp] = L; redM[warp] = M; sC[warp] = C; }
        __syncthreads();
        if (tid == 0) {
            double tL = 0.0, tM = 0.0; unsigned long long tC = 0ull;
#pragma unroll
            for (int w = 0; w < 16; w++) { tL += redL[w]; tM += redM[w]; tC += sC[w]; }
            double mse = tM / (double)((long long)BDIM * TT * FDIM);
            double avg = (tC > 0ull) ? (tL / (double)tC) : 0.0;
            out[0] = (float)(0.5 * mse + 0.5 * avg);
            g_done = 0u;  // reset for next replay
        }
    }
}

extern "C" void kernel_launch(void* const* d_in, const int* in_sizes, int n_in,
                              void* d_out, int out_size) {
    const float* forecast = (const float*)d_in[0];
    const float* target   = (const float*)d_in[1];
    float* out = (float*)d_out;

    ps_tw<<<1, 512>>>();
    cudaFuncSetAttribute(ps_main, cudaFuncAttributeMaxDynamicSharedMemorySize, SMEM_BYTES);
    ps_main<<<NBLK, NTHREADS, SMEM_BYTES>>>(forecast, target, out);
}

// round 12
// speedup vs baseline: 2.7951x; 1.0295x over previous
#include <cuda_runtime.h>
#include <math.h>

// PSLoss: 0.5*MSE + 0.5*avg(structural patch loss)
// B=64, T=336, F=321. 20544 series of length 336 (stride F in memory).
// Spectrum: 336 = 16 x 21; 21-pt DFT via PFA 3x7 (literal constants), then
// 16-pt radix-4 FFT per residue class; twiddles computed in-block (sincospif).
// Patch stats: fp32 cumsum with jax lax.associative_scan tree bracketing,
// segment sums as cs[e]-cs[s], exactly matching the reference arithmetic.
// R12: single-kernel (no ps_tw), warp-shuffle small-level scan.

#define TT      336
#define FDIM    321
#define BDIM    64
#define NBIN    168
#define SBLK    8         // series per block
#define SP      8         // tg/fc pitch
#define AP      9         // amp pitch
#define SPY     9         // yS (float2) pitch
#define SPG     9         // G (float2) pitch
#define NTHREADS 512
#define FTILES  41        // ceil(321/8)
#define NBLK    (BDIM * FTILES)
#define TASKP   40        // 5 quantities x 8 series
#define NPAIR   20        // task pairs (float2)

// float-index smem offsets
#define OFF_TG    0                      // 336*8 = 2688
#define OFF_FC    2688                   // 2688
#define OFF_U     5376                   // union: FFT scratch / pyramid (315x40)
#define OFF_G     (OFF_U + 3168)         // G: 192 rows x 9 float2 = 3456 floats
#define OFF_TW    (OFF_U + 6624)         // tw336: 336 float2 = 672 floats
#define OFF_AMP   (OFF_U + 10080)        // amp 168*9=1512 (rows 252+, dead later)
#define OFF_PP    (OFF_U + 12600)        // 24 ints
#define OFF_FLAG  (OFF_PP + 24)          // 8 ints
#define OFF_RED   (OFF_FLAG + 8)         // 16 dbl + 16 dbl + 16 uint = 80 floats
#define SMEM_FLOATS (OFF_RED + 80)
#define SMEM_BYTES  (SMEM_FLOATS * 4)    // 72448 bytes -> 3 blocks/SM

// 7th-root constants (cos/sin 2*pi*k/7)
#define C7_1  0.6234898018587336f
#define C7_2 -0.2225209339563144f
#define C7_3 -0.9009688679024191f
#define S7_1  0.7818314824680298f
#define S7_2  0.9749279121818236f
#define S7_3  0.4338837391175581f
#define SQ32  0.8660254037844386f

__device__ double g_partL[NBLK];
__device__ double g_partM[NBLK];
__device__ unsigned int g_partC[NBLK];
__device__ unsigned int g_done = 0u;

__device__ __forceinline__ float prodq(float a, float v, int q) {
    switch (q) {
        case 0:  return a;
        case 1:  return v;
        case 2:  return __fmul_rn(a, a);
        case 3:  return __fmul_rn(v, v);
        default: return __fmul_rn(a, v);
    }
}

__device__ __forceinline__ float2 cmulc(float2 z, float2 w) {
    // z * (w.x - i*w.y)
    return make_float2(fmaf(z.y, w.y, z.x * w.x), fmaf(z.y, w.x, -z.x * w.y));
}
__device__ __forceinline__ float2 cadd(float2 a, float2 b) {
    return make_float2(a.x + b.x, a.y + b.y);
}
__device__ __forceinline__ float2 csub(float2 a, float2 b) {
    return make_float2(a.x - b.x, a.y - b.y);
}
__device__ __forceinline__ float2 fadd2(float2 a, float2 b) {
    return make_float2(__fadd_rn(a.x, b.x), __fadd_rn(a.y, b.y));
}
// 3-point combines: Y = A + B*e^{-2pi i k/3} + C*e^{-4pi i k/3}
__device__ __forceinline__ float2 comb_k0(float2 A, float2 B, float2 C) {
    return make_float2(A.x + B.x + C.x, A.y + B.y + C.y);
}
__device__ __forceinline__ float2 comb_k1(float2 A, float2 B, float2 C) {
    return make_float2(A.x - 0.5f * (B.x + C.x) + SQ32 * (B.y - C.y),
                       A.y - 0.5f * (B.y + C.y) - SQ32 * (B.x - C.x));
}
__device__ __forceinline__ float2 comb_k2(float2 A, float2 B, float2 C) {
    return make_float2(A.x - 0.5f * (B.x + C.x) - SQ32 * (B.y - C.y),
                       A.y - 0.5f * (B.y + C.y) + SQ32 * (B.x - C.x));
}

__global__ void __launch_bounds__(NTHREADS, 3)
ps_main(const float* __restrict__ fc, const float* __restrict__ tg,
        float* __restrict__ out) {
    extern __shared__ float sm[];
    float*  tgS   = sm + OFF_TG;
    float*  fcS   = sm + OFF_FC;
    float*  Pyr   = sm + OFF_U;                 // pyramid rows 0..314 x 40
    float2* yS    = (float2*)(sm + OFF_U);      // FFT scratch (overlaid earlier)
    float2* GS    = (float2*)(sm + OFF_G);      // 7-pt DFT outputs
    float2* twS   = (float2*)(sm + OFF_TW);     // twiddles (dead after stage B)
    float*  ampS  = sm + OFF_AMP;               // 168*9 (rows 252+)
    int*    pP    = (int*)(sm + OFF_PP);
    int*    flagS = (int*)(sm + OFF_FLAG);
    double* redL  = (double*)(sm + OFF_RED);
    double* redM  = redL + 16;
    unsigned int* redCt = (unsigned int*)(redM + 16);

    const int tid  = threadIdx.x;
    const int lane = tid & 31;
    const int warp = tid >> 5;
    const int b    = blockIdx.x / FTILES;
    const int f0   = (blockIdx.x % FTILES) * SBLK;

    // ---- Twiddles (in-block, float): tw[i] = (cos, sin)(2*pi*i/336) ----
    if (tid < TT) {
        float sv, cv;
        sincospif((float)tid * (1.0f / 168.0f), &sv, &cv);
        twS[tid] = make_float2(cv, sv);
    }

    // ---- Load tile + MSE partial ----
    float mseAcc = 0.f;
    {
        const int base = b * TT * FDIM + f0;
        for (int i = tid; i < TT * SBLK; i += NTHREADS) {
            int t = i >> 3, l = i & 7;
            float av = 0.f, bv = 0.f;
            if (f0 + l < FDIM) {
                int g = base + t * FDIM + l;
                av = tg[g]; bv = fc[g];
                float d = bv - av;
                mseAcc = fmaf(d, d, mseAcc);
            }
            tgS[t * SP + l] = av;
            fcS[t * SP + l] = bv;
        }
    }
    __syncthreads();

    // ---- Stage A1: 7-point real DFTs (PFA inner). tid -> (s, t1, t3) ----
    if (tid < 384) {
        int s = tid & 7, t1 = (tid >> 3) & 15, t3 = tid >> 7;
        float xv[7];
#pragma unroll
        for (int t7 = 0; t7 < 7; t7++) {
            int t2 = 7 * t3 + 3 * t7; if (t2 >= 21) t2 -= 21;
            xv[t7] = tgS[(t1 + 16 * t2) * SP + s];
        }
        float s1 = xv[1] + xv[6], d1 = xv[1] - xv[6];
        float s2 = xv[2] + xv[5], d2 = xv[2] - xv[5];
        float s3 = xv[3] + xv[4], d3 = xv[3] - xv[4];
        float2 G0 = make_float2(xv[0] + s1 + s2 + s3, 0.f);
        float2 G1 = make_float2(
            xv[0] + s1 * C7_1 + s2 * C7_2 + s3 * C7_3,
            -(d1 * S7_1 + d2 * S7_2 + d3 * S7_3));
        float2 G2 = make_float2(
            xv[0] + s1 * C7_2 + s2 * C7_3 + s3 * C7_1,
            -d1 * S7_2 + d2 * S7_3 + d3 * S7_1);
        float2 G3 = make_float2(
            xv[0] + s1 * C7_3 + s2 * C7_1 + s3 * C7_2,
            -(d1 * S7_3 - d2 * S7_1 + d3 * S7_2));
        int row = (t1 * 3 + t3) * 4;
        GS[(row + 0) * SPG + s] = G0;
        GS[(row + 1) * SPG + s] = G1;
        GS[(row + 2) * SPG + s] = G2;
        GS[(row + 3) * SPG + s] = G3;
    }
    __syncthreads();

    // ---- Stage A2: 3-point combines (PFA outer). tid -> (s, t1, quarter) ----
    {
        int s = tid & 7, t1 = (tid >> 3) & 15, quarter = tid >> 7;
        int rs0 = (quarter == 0) ? 0 : (quarter == 1) ? 3 : (quarter == 2) ? 1 : 2;
        int rs1 = (quarter == 0) ? 1 : (quarter == 1) ? 3 : (quarter == 2) ? 0 : 3;
        int rs2 = (quarter == 0) ? 2 : (quarter == 1) ? 2 : 1;   // q3 unused
        float sg0 = (quarter == 2) ? -1.f : 1.f;
        float sg1 = (quarter == 1) ? -1.f : 1.f;
        float sg2 = (quarter == 1) ? -1.f : 1.f;
        int rowb = t1 * 3 * 4;
        int r0 = 3 * quarter;
        {
            float2 A = GS[(rowb + rs0) * SPG + s];
            float2 Bv = GS[(rowb + 4 + rs0) * SPG + s];
            float2 Cv = GS[(rowb + 8 + rs0) * SPG + s];
            A.y *= sg0; Bv.y *= sg0; Cv.y *= sg0;
            yS[(t1 * 11 + r0) * SPY + s] = comb_k0(A, Bv, Cv);
        }
        {
            float2 A = GS[(rowb + rs1) * SPG + s];
            float2 Bv = GS[(rowb + 4 + rs1) * SPG + s];
            float2 Cv = GS[(rowb + 8 + rs1) * SPG + s];
            A.y *= sg1; Bv.y *= sg1; Cv.y *= sg1;
            yS[(t1 * 11 + r0 + 1) * SPY + s] = comb_k1(A, Bv, Cv);
        }
        if (quarter < 3) {
            float2 A = GS[(rowb + rs2) * SPG + s];
            float2 Bv = GS[(rowb + 4 + rs2) * SPG + s];
            float2 Cv = GS[(rowb + 8 + rs2) * SPG + s];
            A.y *= sg2; Bv.y *= sg2; Cv.y *= sg2;
            yS[(t1 * 11 + r0 + 2) * SPY + s] = comb_k2(A, Bv, Cv);
        }
    }
    __syncthreads();

    // ---- Stage B: per (s, r) residue class, twiddle + 16-pt FFT ----
    if (tid < 336) {
        const unsigned mask = (tid < 320) ? 0xFFFFFFFFu : 0x0000FFFFu;
        const int h = tid & 1, pair = tid >> 1;
        const int s = pair & 7, r = pair >> 3;            // r in 0..20
        const int r2 = (r <= 10) ? r : 21 - r;
        const float sgn = (r <= 10) ? 1.f : -1.f;

        float2 Z[4][2];
#pragma unroll
        for (int bi = 0; bi < 2; bi++) {
            int bb = 2 * h + bi;
#pragma unroll
            for (int a = 0; a < 4; a++) {
                int t1 = 4 * a + bb;
                float2 y = yS[(t1 * 11 + r2) * SPY + s];
                y.y *= sgn;
                float2 w = twS[r * t1];
                Z[a][bi] = cmulc(y, w);
            }
        }
        float2 G[4][2];
#pragma unroll
        for (int bi = 0; bi < 2; bi++) {
            float2 t0 = cadd(Z[0][bi], Z[2][bi]);
            float2 t1 = csub(Z[0][bi], Z[2][bi]);
            float2 t2 = cadd(Z[1][bi], Z[3][bi]);
            float2 t3 = csub(Z[1][bi], Z[3][bi]);
            G[0][bi] = cadd(t0, t2);
            G[2][bi] = csub(t0, t2);
            G[1][bi] = make_float2(t1.x + t3.y, t1.y - t3.x);
            G[3][bi] = make_float2(t1.x - t3.y, t1.y + t3.x);
        }
        const float C1 = 0.9238795325112867f, S1 = 0.3826834323650898f;
        const float C2 = 0.7071067811865476f;
        {
            float2 w;
            w = h ? make_float2(C2, C2)   : make_float2(1.f, 0.f);
            G[1][0] = cmulc(G[1][0], w);
            w = h ? make_float2(S1, C1)   : make_float2(C1, S1);
            G[1][1] = cmulc(G[1][1], w);
            w = h ? make_float2(0.f, 1.f) : make_float2(1.f, 0.f);
            G[2][0] = cmulc(G[2][0], w);
            w = h ? make_float2(-C2, C2)  : make_float2(C2, C2);
            G[2][1] = cmulc(G[2][1], w);
            w = h ? make_float2(-C2, C2)  : make_float2(1.f, 0.f);
            G[3][0] = cmulc(G[3][0], w);
            w = h ? make_float2(-C1, -S1) : make_float2(S1, C1);
            G[3][1] = cmulc(G[3][1], w);
        }
        float2 sA0 = h ? G[0][0] : G[2][0];
        float2 sA1 = h ? G[0][1] : G[2][1];
        float2 sB0 = h ? G[1][0] : G[3][0];
        float2 sB1 = h ? G[1][1] : G[3][1];
        float2 rA0, rA1, rB0, rB1;
        rA0.x = __shfl_xor_sync(mask, sA0.x, 1); rA0.y = __shfl_xor_sync(mask, sA0.y, 1);
        rA1.x = __shfl_xor_sync(mask, sA1.x, 1); rA1.y = __shfl_xor_sync(mask, sA1.y, 1);
        rB0.x = __shfl_xor_sync(mask, sB0.x, 1); rB0.y = __shfl_xor_sync(mask, sB0.y, 1);
        rB1.x = __shfl_xor_sync(mask, sB1.x, 1); rB1.y = __shfl_xor_sync(mask, sB1.y, 1);
        float2 kA0 = h ? G[2][0] : G[0][0];
        float2 kA1 = h ? G[2][1] : G[0][1];
        float2 kB0 = h ? G[3][0] : G[1][0];
        float2 kB1 = h ? G[3][1] : G[1][1];
        float2 HA0 = h ? rA0 : kA0, HA1 = h ? rA1 : kA1;
        float2 HA2 = h ? kA0 : rA0, HA3 = h ? kA1 : rA1;
        float2 HB0 = h ? rB0 : kB0, HB1 = h ? rB1 : kB1;
        float2 HB2 = h ? kB0 : rB0, HB3 = h ? kB1 : rB1;

#pragma unroll
        for (int part = 0; part < 2; part++) {
            float2 u0 = part ? HB0 : HA0, u1 = part ? HB1 : HA1;
            float2 u2 = part ? HB2 : HA2, u3 = part ? HB3 : HA3;
            int d = 2 * h + part;
            float2 t0 = cadd(u0, u2), t1 = csub(u0, u2);
            float2 t2 = cadd(u1, u3), t3 = csub(u1, u3);
            float2 X[4];
            X[0] = cadd(t0, t2);
            X[2] = csub(t0, t2);
            X[1] = make_float2(t1.x + t3.y, t1.y - t3.x);
            X[3] = make_float2(t1.x - t3.y, t1.y + t3.x);
#pragma unroll
            for (int c = 0; c < 4; c++) {
                int m = 4 * c + d;
                bool ok = (r == 0) ? (m >= 1 && m <= 8) : (m <= 7);
                if (ok) {
                    int f = r + 21 * m;
                    ampS[(f - 1) * AP + s] = fmaf(X[c].x, X[c].x, X[c].y * X[c].y);
                }
            }
        }
    }
    __syncthreads();

    // ---- Parallel phase: warps 0-7 top-3; warps 8-15 pyramid level-1 ----
    if (warp < SBLK) {
        const int s = warp;
        unsigned long long k1 = 0ull, k2 = 0ull, k3 = 0ull;
        for (int f = 1 + lane; f <= NBIN; f += 32) {
            float a = ampS[(f - 1) * AP + s];
            unsigned long long kk =
                ((unsigned long long)__float_as_uint(a) << 32) |
                (unsigned long long)(0xFFFFFFFFu - (unsigned)f);
            if (kk > k1)      { k3 = k2; k2 = k1; k1 = kk; }
            else if (kk > k2) { k3 = k2; k2 = kk; }
            else if (kk > k3) { k3 = kk; }
        }
        int fsel[3];
#pragma unroll
        for (int rnd = 0; rnd < 3; rnd++) {
            unsigned long long best = k1;
#pragma unroll
            for (int off = 16; off; off >>= 1) {
                unsigned long long o = __shfl_xor_sync(0xffffffffu, best, off);
                if (o > best) best = o;
            }
            fsel[rnd] = (int)(0xFFFFFFFFu - (unsigned)(best & 0xFFFFFFFFull));
            if (k1 == best) { k1 = k2; k2 = k3; k3 = 0ull; }
        }
        if (lane == 0) {
            int pp[3] = { TT / fsel[0], TT / fsel[1], TT / fsel[2] };
            bool active = (f0 + s) < FDIM;
            bool valid[3];
            valid[0] = active && pp[0] >= 5;
            valid[1] = active && pp[1] >= 5 && pp[1] != pp[0];
            valid[2] = active && pp[2] >= 5 && pp[2] != pp[0] && pp[2] != pp[1];
            int ns[3], L[3]; bool remv[3];
#pragma unroll
            for (int k = 0; k < 3; k++) {
                ns[k] = TT / pp[k];
                L[k]  = TT - ns[k] * pp[k];
                remv[k] = valid[k] && (L[k] >= 5);
            }
            int flags = 0;
#pragma unroll
            for (int k = 0; k < 3; k++) {
                if (valid[k]) flags |= (1 << k);
                bool inc = remv[k];
#pragma unroll
                for (int j = 0; j < 3; j++) {
                    if (valid[j] && pp[j] == L[k] && (TT % pp[j]) == 0) inc = false;
                    if (j < k && remv[j] && L[j] == L[k]) inc = false;
                }
                if (inc) flags |= (8 << k);
            }
            if (active && !(valid[0] || valid[1] || valid[2])) flags |= 64;
#pragma unroll
            for (int k = 0; k < 3; k++) pP[k * SBLK + s] = pp[k];
            flagS[s] = flags;
        }
    } else {
        // pyramid level 1: 168 rows x 20 pairs, float2
        for (int i = tid - 256; i < 168 * NPAIR; i += 256) {
            int j = i / NPAIR, pr = i - j * NPAIR;
            int q = pr >> 2, sb = (pr & 3) << 1;   // pair = tasks {q*8+sb, +1}
            int u = 2 * j;
            float2 a0 = *(const float2*)&tgS[u * SP + sb];
            float2 v0 = *(const float2*)&fcS[u * SP + sb];
            float2 a1 = *(const float2*)&tgS[(u + 1) * SP + sb];
            float2 v1 = *(const float2*)&fcS[(u + 1) * SP + sb];
            float2 x0 = make_float2(prodq(a0.x, v0.x, q), prodq(a0.y, v0.y, q));
            float2 x1 = make_float2(prodq(a1.x, v1.x, q), prodq(a1.y, v1.y, q));
            *(float2*)&Pyr[j * TASKP + 2 * pr] = fadd2(x0, x1);
        }
    }
    __syncthreads();

    // ---- Upsweep levels 2..4 (float2 over pairs) ----
    // Level row offsets: L1=0(168) L2=168(84) L3=252(42) L4=294(21)
    const int pr  = tid % NPAIR;
    const int j0  = tid / NPAIR;      // 0..25 (tid<500 active)
    const int pc  = 2 * pr;
    {
        const int srcO[3] = { 0, 168, 252 };
        const int dstO[3] = { 168, 252, 294 };
        const int lenL[3] = { 84, 42, 21 };
#pragma unroll
        for (int L = 0; L < 3; L++) {
            if (tid < 500) {
                for (int j = j0; j < lenL[L]; j += 25) {
                    float2 a = *(const float2*)&Pyr[(srcO[L] + 2 * j) * TASKP + pc];
                    float2 c = *(const float2*)&Pyr[(srcO[L] + 2 * j + 1) * TASKP + pc];
                    *(float2*)&Pyr[(dstO[L] + j) * TASKP + pc] = fadd2(a, c);
                }
            }
            __syncthreads();
        }
    }

    // ---- In-warp tree scan of the 21 L4 elements (per column) ----
    // Upsweep 21->10->5->2->1 and 4-level downsweep, all in shuffles with
    // the same __fadd_rn bracketing as the array version.
    {
        for (int c = warp; c < TASKP; c += 16) {
            float e = (lane < 21) ? Pyr[(294 + lane) * TASKP + c] : 0.f;
            float l1 = __fadd_rn(__shfl_sync(0xffffffffu, e, 2 * lane),
                                 __shfl_sync(0xffffffffu, e, 2 * lane + 1));   // lane<10
            float l2 = __fadd_rn(__shfl_sync(0xffffffffu, l1, 2 * lane),
                                 __shfl_sync(0xffffffffu, l1, 2 * lane + 1));  // lane<5
            float l3 = __fadd_rn(__shfl_sync(0xffffffffu, l2, 2 * lane),
                                 __shfl_sync(0xffffffffu, l2, 2 * lane + 1));  // lane<2
            float l4 = __fadd_rn(__shfl_sync(0xffffffffu, l3, 0),
                                 __shfl_sync(0xffffffffu, l3, 1));
            // level-2 scan (2 elems): [l3e0, l4]
            float s3 = (lane == 0) ? l3 : l4;
            // level-5 scan
            float p_odd  = __shfl_sync(0xffffffffu, s3, (lane - 1) >> 1);
            float p_even = __shfl_sync(0xffffffffu, s3, (lane >> 1) - 1);
            float s2 = (lane == 0) ? l2 : ((lane & 1) ? p_odd : __fadd_rn(p_even, l2));
            // level-10 scan
            p_odd  = __shfl_sync(0xffffffffu, s2, (lane - 1) >> 1);
            p_even = __shfl_sync(0xffffffffu, s2, (lane >> 1) - 1);
            float s1 = (lane == 0) ? l1 : ((lane & 1) ? p_odd : __fadd_rn(p_even, l1));
            // level-21 scan
            p_odd  = __shfl_sync(0xffffffffu, s1, (lane - 1) >> 1);
            p_even = __shfl_sync(0xffffffffu, s1, (lane >> 1) - 1);
            float s0 = (lane == 0) ? e : ((lane & 1) ? p_odd : __fadd_rn(p_even, e));
            if (lane < 21) Pyr[(294 + lane) * TASKP + c] = s0;
        }
    }
    __syncthreads();

    // ---- Downsweep levels 42, 84, 168 (float2 over pairs) ----
    {
        const int dstO[3] = { 252, 168, 0 };
        const int parO[3] = { 294, 252, 168 };
        const int lenL[3] = { 42, 84, 168 };
#pragma unroll
        for (int L = 0; L < 3; L++) {
            if (tid < 500) {
                for (int j = j0; j < lenL[L]; j += 25) {
                    if (j == 0) continue;  // scan[0] = elem[0]
                    float2 v;
                    if (j & 1) {
                        v = *(const float2*)&Pyr[(parO[L] + ((j - 1) >> 1)) * TASKP + pc];
                    } else {
                        float2 pv = *(const float2*)&Pyr[(parO[L] + (j >> 1) - 1) * TASKP + pc];
                        float2 cv = *(const float2*)&Pyr[(dstO[L] + j) * TASKP + pc];
                        v = fadd2(pv, cv);
                    }
                    *(float2*)&Pyr[(dstO[L] + j) * TASKP + pc] = v;
                }
            }
            __syncthreads();
        }
    }

    // ---- Walk: patch losses via cs[e]-cs[s] with reference arithmetic ----
    double lossAcc = 0.0; unsigned int cnt = 0u;
    {
        int s = tid & 7, w = tid >> 3;   // w in 0..63
        int slot, sub;
        if (w < 21)      { slot = 0; sub = w; }
        else if (w < 42) { slot = 1; sub = w - 21; }
        else if (w < 63) { slot = 2; sub = w - 42; }
        else             { slot = 3; sub = 0; }
        int flags = flagS[s];

        auto s0v = [&](int q, int u) -> float {
            if (u < 0) return 0.f;
            if (u & 1) return Pyr[((u - 1) >> 1) * TASKP + (q << 3) + s];
            float x = prodq(tgS[u * SP + s], fcS[u * SP + s], q);
            if (u == 0) return x;
            return __fadd_rn(Pyr[(((u >> 1) - 1)) * TASKP + (q << 3) + s], x);
        };
        auto accum = [&](int s0, int e0) {
            float n   = (float)(e0 - s0);
            float St  = __fsub_rn(s0v(0, e0 - 1), s0v(0, s0 - 1));
            float Sf  = __fsub_rn(s0v(1, e0 - 1), s0v(1, s0 - 1));
            float Stt = __fsub_rn(s0v(2, e0 - 1), s0v(2, s0 - 1));
            float Sff = __fsub_rn(s0v(3, e0 - 1), s0v(3, s0 - 1));
            float Stf = __fsub_rn(s0v(4, e0 - 1), s0v(4, s0 - 1));
            float mt  = __fdiv_rn(St, n);
            float mf  = __fdiv_rn(Sf, n);
            float tvs = fmaxf(__fsub_rn(Stt, __fmul_rn(__fmul_rn(n, mt), mt)), 0.f);
            float fvs = fmaxf(__fsub_rn(Sff, __fmul_rn(__fmul_rn(n, mf), mf)), 0.f);
            float num = __fsub_rn(Stf, __fmul_rn(__fmul_rn(n, mt), mf));
            float den = __fadd_rn(__fsqrt_rn(__fmul_rn(tvs, fvs)), 1e-8f);
            float cl  = __fsub_rn(1.f, fabsf(__fdiv_rn(num, den)));
            float nm1 = __fsub_rn(n, 1.f);
            float tvar = __fdiv_rn(tvs, nm1);
            float fvar = __fdiv_rn(fvs, nm1);
            float vl  = __fdiv_rn(fabsf(__fsub_rn(tvar, fvar)), __fadd_rn(tvar, 1e-8f));
            float ml  = __fdiv_rn(fabsf(__fsub_rn(mt, mf)), __fadd_rn(fabsf(mt), 1e-8f));
            lossAcc += (double)__fadd_rn(__fadd_rn(cl, vl), ml);
            cnt++;
        };

        if (slot < 3) {
            if ((flags >> slot) & 1) {
                int p = pP[slot * SBLK + s], ns = TT / p;
                for (int j = sub; j < ns; j += 21) accum(j * p, j * p + p);
                if (sub == 20 && ((flags >> (3 + slot)) & 1)) accum(ns * p, TT);
            }
        } else {
            if (flags & 64) accum(0, TT);
        }
    }

    // ---- Block reduce -> per-block partial slot (deterministic) ----
#pragma unroll
    for (int off = 16; off; off >>= 1) {
        lossAcc += __shfl_down_sync(0xffffffffu, lossAcc, off);
        mseAcc  += __shfl_down_sync(0xffffffffu, mseAcc,  off);
        cnt     += __shfl_down_sync(0xffffffffu, cnt,     off);
    }
    if (lane == 0) {
        redL[warp] = lossAcc; redM[warp] = (double)mseAcc; redCt[warp] = cnt;
    }
    __syncthreads();

    __shared__ unsigned int sLast;
    if (tid == 0) {
        double tL = 0.0, tM = 0.0; unsigned int tC = 0u;
#pragma unroll
        for (int w = 0; w < 16; w++) { tL += redL[w]; tM += redM[w]; tC += redCt[w]; }
        g_partL[blockIdx.x] = tL;
        g_partM[blockIdx.x] = tM;
        g_partC[blockIdx.x] = tC;
        __threadfence();
        sLast = (atomicAdd(&g_done, 1u) == (unsigned)(NBLK - 1));
    }
    __syncthreads();

    // ---- Last block: deterministic grand reduction ----
    if (sLast) {
        __threadfence();
        double L = 0.0, M = 0.0; unsigned long long C = 0ull;
        for (int i = tid; i < NBLK; i += NTHREADS) {
            L += g_partL[i]; M += g_partM[i]; C += (unsigned long long)g_partC[i];
        }
#pragma unroll
        for (int off = 16; off; off >>= 1) {
            L += __shfl_down_sync(0xffffffffu, L, off);
            M += __shfl_down_sync(0xffffffffu, M, off);
            C += __shfl_down_sync(0xffffffffu, C, off);
        }
        unsigned long long* sC = (unsigned long long*)(sm + OFF_U);  // reuse scratch
        if (lane == 0) { redL[warp] = L; redM[warp] = M; sC[warp] = C; }
        __syncthreads();
        if (tid == 0) {
            double tL = 0.0, tM = 0.0; unsigned long long tC = 0ull;
#pragma unroll
            for (int w = 0; w < 16; w++) { tL += redL[w]; tM += redM[w]; tC += sC[w]; }
            double mse = tM / (double)((long long)BDIM * TT * FDIM);
            double avg = (tC > 0ull) ? (tL / (double)tC) : 0.0;
            out[0] = (float)(0.5 * mse + 0.5 * avg);
            g_done = 0u;  // reset for next replay
        }
    }
}

extern "C" void kernel_launch(void* const* d_in, const int* in_sizes, int n_in,
                              void* d_out, int out_size) {
    const float* forecast = (const float*)d_in[0];
    const float* target   = (const float*)d_in[1];
    float* out = (float*)d_out;

    cudaFuncSetAttribute(ps_main, cudaFuncAttributeMaxDynamicSharedMemorySize, SMEM_BYTES);
    ps_main<<<NBLK, NTHREADS, SMEM_BYTES>>>(forecast, target, out);
}

// round 15
// speedup vs baseline: 3.3322x; 1.1922x over previous
#include <cuda_runtime.h>
#include <math.h>

// PSLoss: 0.5*MSE + 0.5*avg(structural patch loss)
// B=64, T=336, F=321. 20544 series of length 336 (stride F in memory).
// Spectrum: 336 = 16 x 21; 21-pt DFT via PFA 3x7 (literal constants), then
// 16-pt radix-4 FFT per residue class; twiddles computed in-block (sincospif).
// Patch stats: fp32 cumsum with jax lax.associative_scan tree bracketing,
// segment sums as cs[e]-cs[s], exactly matching the reference arithmetic.
// R13: interleaved (tg,fc) tile, fused 5-quantity level-1 init, float4
//      up/downsweep, chunked walk with shared boundaries.

#define TT      336
#define FDIM    321
#define BDIM    64
#define NBIN    168
#define SBLK    8         // series per block
#define TFP     16        // interleaved tile pitch (8 series x float2)
#define AP      9         // amp pitch
#define SPY     9         // yS (float2) pitch
#define SPG     9         // G (float2) pitch
#define NTHREADS 512
#define FTILES  41        // ceil(321/8)
#define NBLK    (BDIM * FTILES)
#define TASKP   40        // 5 quantities x 8 series

// float-index smem offsets
#define OFF_TF    0                      // 336*16 = 5376 (tg,fc interleaved)
#define OFF_U     5376                   // union: FFT scratch / pyramid (315x40)
#define OFF_G     (OFF_U + 3168)         // G: 192 rows x 9 float2 = 3456 floats
#define OFF_TW    (OFF_U + 6624)         // tw336: 336 float2 = 672 floats
#define OFF_AMP   (OFF_U + 10080)        // amp 168*9=1512 (rows 252+, dead later)
#define OFF_PP    (OFF_U + 12600)        // 24 ints
#define OFF_FLAG  (OFF_PP + 24)          // 8 ints
#define OFF_RED   (OFF_FLAG + 8)         // 16 dbl + 16 dbl + 16 uint = 80 floats
#define SMEM_FLOATS (OFF_RED + 80)
#define SMEM_BYTES  (SMEM_FLOATS * 4)    // 72448 bytes -> 3 blocks/SM

// 7th-root constants (cos/sin 2*pi*k/7)
#define C7_1  0.6234898018587336f
#define C7_2 -0.2225209339563144f
#define C7_3 -0.9009688679024191f
#define S7_1  0.7818314824680298f
#define S7_2  0.9749279121818236f
#define S7_3  0.4338837391175581f
#define SQ32  0.8660254037844386f

__device__ double g_partL[NBLK];
__device__ double g_partM[NBLK];
__device__ unsigned int g_partC[NBLK];
__device__ unsigned int g_done = 0u;

__device__ __forceinline__ float prodq(float a, float v, int q) {
    switch (q) {
        case 0:  return a;
        case 1:  return v;
        case 2:  return __fmul_rn(a, a);
        case 3:  return __fmul_rn(v, v);
        default: return __fmul_rn(a, v);
    }
}

__device__ __forceinline__ float2 cmulc(float2 z, float2 w) {
    // z * (w.x - i*w.y)
    return make_float2(fmaf(z.y, w.y, z.x * w.x), fmaf(z.y, w.x, -z.x * w.y));
}
__device__ __forceinline__ float2 cadd(float2 a, float2 b) {
    return make_float2(a.x + b.x, a.y + b.y);
}
__device__ __forceinline__ float2 csub(float2 a, float2 b) {
    return make_float2(a.x - b.x, a.y - b.y);
}
__device__ __forceinline__ float4 fadd4(float4 a, float4 b) {
    return make_float4(__fadd_rn(a.x, b.x), __fadd_rn(a.y, b.y),
                       __fadd_rn(a.z, b.z), __fadd_rn(a.w, b.w));
}
// 3-point combines: Y = A + B*e^{-2pi i k/3} + C*e^{-4pi i k/3}
__device__ __forceinline__ float2 comb_k0(float2 A, float2 B, float2 C) {
    return make_float2(A.x + B.x + C.x, A.y + B.y + C.y);
}
__device__ __forceinline__ float2 comb_k1(float2 A, float2 B, float2 C) {
    return make_float2(A.x - 0.5f * (B.x + C.x) + SQ32 * (B.y - C.y),
                       A.y - 0.5f * (B.y + C.y) - SQ32 * (B.x - C.x));
}
__device__ __forceinline__ float2 comb_k2(float2 A, float2 B, float2 C) {
    return make_float2(A.x - 0.5f * (B.x + C.x) - SQ32 * (B.y - C.y),
                       A.y - 0.5f * (B.y + C.y) + SQ32 * (B.x - C.x));
}

__global__ void __launch_bounds__(NTHREADS, 3)
ps_main(const float* __restrict__ fc, const float* __restrict__ tg,
        float* __restrict__ out) {
    extern __shared__ float sm[];
    float*  TF    = sm + OFF_TF;                // interleaved (tg, fc)
    float*  Pyr   = sm + OFF_U;                 // pyramid rows 0..314 x 40
    float2* yS    = (float2*)(sm + OFF_U);      // FFT scratch (overlaid earlier)
    float2* GS    = (float2*)(sm + OFF_G);      // 7-pt DFT outputs
    float2* twS   = (float2*)(sm + OFF_TW);     // twiddles (dead after stage B)
    float*  ampS  = sm + OFF_AMP;               // 168*9 (rows 252+)
    int*    pP    = (int*)(sm + OFF_PP);
    int*    flagS = (int*)(sm + OFF_FLAG);
    double* redL  = (double*)(sm + OFF_RED);
    double* redM  = redL + 16;
    unsigned int* redCt = (unsigned int*)(redM + 16);

    const int tid  = threadIdx.x;
    const int lane = tid & 31;
    const int warp = tid >> 5;
    const int b    = blockIdx.x / FTILES;
    const int f0   = (blockIdx.x % FTILES) * SBLK;

    // ---- Twiddles (in-block, float): tw[i] = (cos, sin)(2*pi*i/336) ----
    if (tid < TT) {
        float sv, cv;
        sincospif((float)tid * (1.0f / 168.0f), &sv, &cv);
        twS[tid] = make_float2(cv, sv);
    }

    // ---- Load tile (interleaved) + MSE partial ----
    float mseAcc = 0.f;
    {
        const int base = b * TT * FDIM + f0;
        for (int i = tid; i < TT * SBLK; i += NTHREADS) {
            int t = i >> 3, l = i & 7;
            float av = 0.f, bv = 0.f;
            if (f0 + l < FDIM) {
                int g = base + t * FDIM + l;
                av = tg[g]; bv = fc[g];
                float d = bv - av;
                mseAcc = fmaf(d, d, mseAcc);
            }
            *(float2*)&TF[t * TFP + 2 * l] = make_float2(av, bv);
        }
    }
    __syncthreads();

    // ---- Stage A1: 7-point real DFTs (PFA inner). tid -> (s, t1, t3) ----
    if (tid < 384) {
        int s = tid & 7, t1 = (tid >> 3) & 15, t3 = tid >> 7;
        float xv[7];
#pragma unroll
        for (int t7 = 0; t7 < 7; t7++) {
            int t2 = 7 * t3 + 3 * t7; if (t2 >= 21) t2 -= 21;
            xv[t7] = TF[(t1 + 16 * t2) * TFP + 2 * s];
        }
        float s1 = xv[1] + xv[6], d1 = xv[1] - xv[6];
        float s2 = xv[2] + xv[5], d2 = xv[2] - xv[5];
        float s3 = xv[3] + xv[4], d3 = xv[3] - xv[4];
        float2 G0 = make_float2(xv[0] + s1 + s2 + s3, 0.f);
        float2 G1 = make_float2(
            xv[0] + s1 * C7_1 + s2 * C7_2 + s3 * C7_3,
            -(d1 * S7_1 + d2 * S7_2 + d3 * S7_3));
        float2 G2 = make_float2(
            xv[0] + s1 * C7_2 + s2 * C7_3 + s3 * C7_1,
            -d1 * S7_2 + d2 * S7_3 + d3 * S7_1);
        float2 G3 = make_float2(
            xv[0] + s1 * C7_3 + s2 * C7_1 + s3 * C7_2,
            -(d1 * S7_3 - d2 * S7_1 + d3 * S7_2));
        int row = (t1 * 3 + t3) * 4;
        GS[(row + 0) * SPG + s] = G0;
        GS[(row + 1) * SPG + s] = G1;
        GS[(row + 2) * SPG + s] = G2;
        GS[(row + 3) * SPG + s] = G3;
    }
    __syncthreads();

    // ---- Stage A2: 3-point combines (PFA outer). tid -> (s, t1, quarter) ----
    {
        int s = tid & 7, t1 = (tid >> 3) & 15, quarter = tid >> 7;
        int rs0 = (quarter == 0) ? 0 : (quarter == 1) ? 3 : (quarter == 2) ? 1 : 2;
        int rs1 = (quarter == 0) ? 1 : (quarter == 1) ? 3 : (quarter == 2) ? 0 : 3;
        int rs2 = (quarter == 0) ? 2 : (quarter == 1) ? 2 : 1;   // q3 unused
        float sg0 = (quarter == 2) ? -1.f : 1.f;
        float sg1 = (quarter == 1) ? -1.f : 1.f;
        float sg2 = (quarter == 1) ? -1.f : 1.f;
        int rowb = t1 * 3 * 4;
        int r0 = 3 * quarter;
        {
            float2 A = GS[(rowb + rs0) * SPG + s];
            float2 Bv = GS[(rowb + 4 + rs0) * SPG + s];
            float2 Cv = GS[(rowb + 8 + rs0) * SPG + s];
            A.y *= sg0; Bv.y *= sg0; Cv.y *= sg0;
            yS[(t1 * 11 + r0) * SPY + s] = comb_k0(A, Bv, Cv);
        }
        {
            float2 A = GS[(rowb + rs1) * SPG + s];
            float2 Bv = GS[(rowb + 4 + rs1) * SPG + s];
            float2 Cv = GS[(rowb + 8 + rs1) * SPG + s];
            A.y *= sg1; Bv.y *= sg1; Cv.y *= sg1;
            yS[(t1 * 11 + r0 + 1) * SPY + s] = comb_k1(A, Bv, Cv);
        }
        if (quarter < 3) {
            float2 A = GS[(rowb + rs2) * SPG + s];
            float2 Bv = GS[(rowb + 4 + rs2) * SPG + s];
            float2 Cv = GS[(rowb + 8 + rs2) * SPG + s];
            A.y *= sg2; Bv.y *= sg2; Cv.y *= sg2;
            yS[(t1 * 11 + r0 + 2) * SPY + s] = comb_k2(A, Bv, Cv);
        }
    }
    __syncthreads();

    // ---- Stage B: per (s, r) residue class, twiddle + 16-pt FFT ----
    if (tid < 336) {
        const unsigned mask = (tid < 320) ? 0xFFFFFFFFu : 0x0000FFFFu;
        const int h = tid & 1, pair = tid >> 1;
        const int s = pair & 7, r = pair >> 3;            // r in 0..20
        const int r2 = (r <= 10) ? r : 21 - r;
        const float sgn = (r <= 10) ? 1.f : -1.f;

        float2 Z[4][2];
#pragma unroll
        for (int bi = 0; bi < 2; bi++) {
            int bb = 2 * h + bi;
#pragma unroll
            for (int a = 0; a < 4; a++) {
                int t1 = 4 * a + bb;
                float2 y = yS[(t1 * 11 + r2) * SPY + s];
                y.y *= sgn;
                float2 w = twS[r * t1];
                Z[a][bi] = cmulc(y, w);
            }
        }
        float2 G[4][2];
#pragma unroll
        for (int bi = 0; bi < 2; bi++) {
            float2 t0 = cadd(Z[0][bi], Z[2][bi]);
            float2 t1 = csub(Z[0][bi], Z[2][bi]);
            float2 t2 = cadd(Z[1][bi], Z[3][bi]);
            float2 t3 = csub(Z[1][bi], Z[3][bi]);
            G[0][bi] = cadd(t0, t2);
            G[2][bi] = csub(t0, t2);
            G[1][bi] = make_float2(t1.x + t3.y, t1.y - t3.x);
            G[3][bi] = make_float2(t1.x - t3.y, t1.y + t3.x);
        }
        const float C1 = 0.9238795325112867f, S1 = 0.3826834323650898f;
        const float C2 = 0.7071067811865476f;
        {
            float2 w;
            w = h ? make_float2(C2, C2)   : make_float2(1.f, 0.f);
            G[1][0] = cmulc(G[1][0], w);
            w = h ? make_float2(S1, C1)   : make_float2(C1, S1);
            G[1][1] = cmulc(G[1][1], w);
            w = h ? make_float2(0.f, 1.f) : make_float2(1.f, 0.f);
            G[2][0] = cmulc(G[2][0], w);
            w = h ? make_float2(-C2, C2)  : make_float2(C2, C2);
            G[2][1] = cmulc(G[2][1], w);
            w = h ? make_float2(-C2, C2)  : make_float2(1.f, 0.f);
            G[3][0] = cmulc(G[3][0], w);
            w = h ? make_float2(-C1, -S1) : make_float2(S1, C1);
            G[3][1] = cmulc(G[3][1], w);
        }
        float2 sA0 = h ? G[0][0] : G[2][0];
        float2 sA1 = h ? G[0][1] : G[2][1];
        float2 sB0 = h ? G[1][0] : G[3][0];
        float2 sB1 = h ? G[1][1] : G[3][1];
        float2 rA0, rA1, rB0, rB1;
        rA0.x = __shfl_xor_sync(mask, sA0.x, 1); rA0.y = __shfl_xor_sync(mask, sA0.y, 1);
        rA1.x = __shfl_xor_sync(mask, sA1.x, 1); rA1.y = __shfl_xor_sync(mask, sA1.y, 1);
        rB0.x = __shfl_xor_sync(mask, sB0.x, 1); rB0.y = __shfl_xor_sync(mask, sB0.y, 1);
        rB1.x = __shfl_xor_sync(mask, sB1.x, 1); rB1.y = __shfl_xor_sync(mask, sB1.y, 1);
        float2 kA0 = h ? G[2][0] : G[0][0];
        float2 kA1 = h ? G[2][1] : G[0][1];
        float2 kB0 = h ? G[3][0] : G[1][0];
        float2 kB1 = h ? G[3][1] : G[1][1];
        float2 HA0 = h ? rA0 : kA0, HA1 = h ? rA1 : kA1;
        float2 HA2 = h ? kA0 : rA0, HA3 = h ? kA1 : rA1;
        float2 HB0 = h ? rB0 : kB0, HB1 = h ? rB1 : kB1;
        float2 HB2 = h ? kB0 : rB0, HB3 = h ? kB1 : rB1;

#pragma unroll
        for (int part = 0; part < 2; part++) {
            float2 u0 = part ? HB0 : HA0, u1 = part ? HB1 : HA1;
            float2 u2 = part ? HB2 : HA2, u3 = part ? HB3 : HA3;
            int d = 2 * h + part;
            float2 t0 = cadd(u0, u2), t1 = csub(u0, u2);
            float2 t2 = cadd(u1, u3), t3 = csub(u1, u3);
            float2 X[4];
            X[0] = cadd(t0, t2);
            X[2] = csub(t0, t2);
            X[1] = make_float2(t1.x + t3.y, t1.y - t3.x);
            X[3] = make_float2(t1.x - t3.y, t1.y + t3.x);
#pragma unroll
            for (int c = 0; c < 4; c++) {
                int m = 4 * c + d;
                bool ok = (r == 0) ? (m >= 1 && m <= 8) : (m <= 7);
                if (ok) {
                    int f = r + 21 * m;
                    ampS[(f - 1) * AP + s] = fmaf(X[c].x, X[c].x, X[c].y * X[c].y);
                }
            }
        }
    }
    __syncthreads();

    // ---- Parallel phase: warps 0-7 top-3; warps 8-15 pyramid level-1 ----
    if (warp < SBLK) {
        const int s = warp;
        unsigned long long k1 = 0ull, k2 = 0ull, k3 = 0ull;
        for (int f = 1 + lane; f <= NBIN; f += 32) {
            float a = ampS[(f - 1) * AP + s];
            unsigned long long kk =
                ((unsigned long long)__float_as_uint(a) << 32) |
                (unsigned long long)(0xFFFFFFFFu - (unsigned)f);
            if (kk > k1)      { k3 = k2; k2 = k1; k1 = kk; }
            else if (kk > k2) { k3 = k2; k2 = kk; }
            else if (kk > k3) { k3 = kk; }
        }
        int fsel[3];
#pragma unroll
        for (int rnd = 0; rnd < 3; rnd++) {
            unsigned long long best = k1;
#pragma unroll
            for (int off = 16; off; off >>= 1) {
                unsigned long long o = __shfl_xor_sync(0xffffffffu, best, off);
                if (o > best) best = o;
            }
            fsel[rnd] = (int)(0xFFFFFFFFu - (unsigned)(best & 0xFFFFFFFFull));
            if (k1 == best) { k1 = k2; k2 = k3; k3 = 0ull; }
        }
        if (lane == 0) {
            int pp[3] = { TT / fsel[0], TT / fsel[1], TT / fsel[2] };
            bool active = (f0 + s) < FDIM;
            bool valid[3];
            valid[0] = active && pp[0] >= 5;
            valid[1] = active && pp[1] >= 5 && pp[1] != pp[0];
            valid[2] = active && pp[2] >= 5 && pp[2] != pp[0] && pp[2] != pp[1];
            int ns[3], L[3]; bool remv[3];
#pragma unroll
            for (int k = 0; k < 3; k++) {
                ns[k] = TT / pp[k];
                L[k]  = TT - ns[k] * pp[k];
                remv[k] = valid[k] && (L[k] >= 5);
            }
            int flags = 0;
#pragma unroll
            for (int k = 0; k < 3; k++) {
                if (valid[k]) flags |= (1 << k);
                bool inc = remv[k];
#pragma unroll
                for (int j = 0; j < 3; j++) {
                    if (valid[j] && pp[j] == L[k] && (TT % pp[j]) == 0) inc = false;
                    if (j < k && remv[j] && L[j] == L[k]) inc = false;
                }
                if (inc) flags |= (8 << k);
            }
            if (active && !(valid[0] || valid[1] || valid[2])) flags |= 64;
#pragma unroll
            for (int k = 0; k < 3; k++) pP[k * SBLK + s] = pp[k];
            flagS[s] = flags;
        }
    } else {
        // pyramid level 1: item = (row-pair j, series-half h); all 5 q at once
        for (int i = tid - 256; i < 336; i += 256) {
            int j = i >> 1, h = i & 1;
            const float4* row0 = (const float4*)&TF[(2 * j) * TFP + 8 * h];
            const float4* row1 = (const float4*)&TF[(2 * j + 1) * TFP + 8 * h];
            float4 r0a = row0[0], r0b = row0[1];
            float4 r1a = row1[0], r1b = row1[1];
#pragma unroll
            for (int q = 0; q < 5; q++) {
                float4 o;
                o.x = __fadd_rn(prodq(r0a.x, r0a.y, q), prodq(r1a.x, r1a.y, q));
                o.y = __fadd_rn(prodq(r0a.z, r0a.w, q), prodq(r1a.z, r1a.w, q));
                o.z = __fadd_rn(prodq(r0b.x, r0b.y, q), prodq(r1b.x, r1b.y, q));
                o.w = __fadd_rn(prodq(r0b.z, r0b.w, q), prodq(r1b.z, r1b.w, q));
                *(float4*)&Pyr[j * TASKP + q * 8 + 4 * h] = o;
            }
        }
    }
    __syncthreads();

    // ---- Upsweep levels 2..4 (float4 quads) ----
    // Level row offsets: L1=0(168) L2=168(84) L3=252(42) L4=294(21)
    const int qc = tid % 10;
    const int jj = tid / 10;          // 0..51 (tid<510 active)
    {
        const int srcO[3] = { 0, 168, 252 };
        const int dstO[3] = { 168, 252, 294 };
        const int lenL[3] = { 84, 42, 21 };
#pragma unroll
        for (int L = 0; L < 3; L++) {
            if (tid < 510) {
                for (int j = jj; j < lenL[L]; j += 51) {
                    float4 a = *(const float4*)&Pyr[(srcO[L] + 2 * j) * TASKP + 4 * qc];
                    float4 c = *(const float4*)&Pyr[(srcO[L] + 2 * j + 1) * TASKP + 4 * qc];
                    *(float4*)&Pyr[(dstO[L] + j) * TASKP + 4 * qc] = fadd4(a, c);
                }
            }
            __syncthreads();
        }
    }

    // ---- In-warp tree scan of the 21 L4 elements (per column) ----
    {
        for (int c = warp; c < TASKP; c += 16) {
            float e = (lane < 21) ? Pyr[(294 + lane) * TASKP + c] : 0.f;
            float l1 = __fadd_rn(__shfl_sync(0xffffffffu, e, 2 * lane),
                                 __shfl_sync(0xffffffffu, e, 2 * lane + 1));   // lane<10
            float l2 = __fadd_rn(__shfl_sync(0xffffffffu, l1, 2 * lane),
                                 __shfl_sync(0xffffffffu, l1, 2 * lane + 1));  // lane<5
            float l3 = __fadd_rn(__shfl_sync(0xffffffffu, l2, 2 * lane),
                                 __shfl_sync(0xffffffffu, l2, 2 * lane + 1));  // lane<2
            float l4 = __fadd_rn(__shfl_sync(0xffffffffu, l3, 0),
                                 __shfl_sync(0xffffffffu, l3, 1));
            float s3 = (lane == 0) ? l3 : l4;
            float p_odd  = __shfl_sync(0xffffffffu, s3, (lane - 1) >> 1);
            float p_even = __shfl_sync(0xffffffffu, s3, (lane >> 1) - 1);
            float s2 = (lane == 0) ? l2 : ((lane & 1) ? p_odd : __fadd_rn(p_even, l2));
            p_odd  = __shfl_sync(0xffffffffu, s2, (lane - 1) >> 1);
            p_even = __shfl_sync(0xffffffffu, s2, (lane >> 1) - 1);
            float s1 = (lane == 0) ? l1 : ((lane & 1) ? p_odd : __fadd_rn(p_even, l1));
            p_odd  = __shfl_sync(0xffffffffu, s1, (lane - 1) >> 1);
            p_even = __shfl_sync(0xffffffffu, s1, (lane >> 1) - 1);
            float s0 = (lane == 0) ? e : ((lane & 1) ? p_odd : __fadd_rn(p_even, e));
            if (lane < 21) Pyr[(294 + lane) * TASKP + c] = s0;
        }
    }
    __syncthreads();

    // ---- Downsweep levels 42, 84, 168 (float4 quads) ----
    {
        const int dstO[3] = { 252, 168, 0 };
        const int parO[3] = { 294, 252, 168 };
        const int lenL[3] = { 42, 84, 168 };
#pragma unroll
        for (int L = 0; L < 3; L++) {
            if (tid < 510) {
                for (int j = jj; j < lenL[L]; j += 51) {
                    if (j == 0) continue;  // scan[0] = elem[0]
                    float4 v;
                    if (j & 1) {
                        v = *(const float4*)&Pyr[(parO[L] + ((j - 1) >> 1)) * TASKP + 4 * qc];
                    } else {
                        float4 pv = *(const float4*)&Pyr[(parO[L] + (j >> 1) - 1) * TASKP + 4 * qc];
                        float4 cv = *(const float4*)&Pyr[(dstO[L] + j) * TASKP + 4 * qc];
                        v = fadd4(pv, cv);
                    }
                    *(float4*)&Pyr[(dstO[L] + j) * TASKP + 4 * qc] = v;
                }
            }
            __syncthreads();
        }
    }

    // ---- Walk: chunked segments, boundaries shared via registers ----
    double lossAcc = 0.0; unsigned int cnt = 0u;
    {
        int s = tid & 7, w = tid >> 3;   // w in 0..63
        int slot, sub;
        if (w < 21)      { slot = 0; sub = w; }
        else if (w < 42) { slot = 1; sub = w - 21; }
        else if (w < 63) { slot = 2; sub = w - 42; }
        else             { slot = 3; sub = 0; }
        int flags = flagS[s];

        // boundary: all 5 inclusive-scan values at position u (cs[u+1]); -1 -> 0
        auto bnd = [&](int u, float* o) {
            if (u < 0) {
#pragma unroll
                for (int q = 0; q < 5; q++) o[q] = 0.f;
            } else if (u & 1) {
                int row = (u - 1) >> 1;
#pragma unroll
                for (int q = 0; q < 5; q++) o[q] = Pyr[row * TASKP + q * 8 + s];
            } else {
                float2 tf = *(const float2*)&TF[u * TFP + 2 * s];
                if (u == 0) {
#pragma unroll
                    for (int q = 0; q < 5; q++) o[q] = prodq(tf.x, tf.y, q);
                } else {
                    int row = (u >> 1) - 1;
#pragma unroll
                    for (int q = 0; q < 5; q++)
                        o[q] = __fadd_rn(Pyr[row * TASKP + q * 8 + s],
                                         prodq(tf.x, tf.y, q));
                }
            }
        };
        auto ploss = [&](int nI, const float* c, const float* e) {
            float n   = (float)nI;
            float St  = __fsub_rn(e[0], c[0]);
            float Sf  = __fsub_rn(e[1], c[1]);
            float Stt = __fsub_rn(e[2], c[2]);
            float Sff = __fsub_rn(e[3], c[3]);
            float Stf = __fsub_rn(e[4], c[4]);
            float mt  = __fdiv_rn(St, n);
            float mf  = __fdiv_rn(Sf, n);
            float tvs = fmaxf(__fsub_rn(Stt, __fmul_rn(__fmul_rn(n, mt), mt)), 0.f);
            float fvs = fmaxf(__fsub_rn(Sff, __fmul_rn(__fmul_rn(n, mf), mf)), 0.f);
            float num = __fsub_rn(Stf, __fmul_rn(__fmul_rn(n, mt), mf));
            float den = __fadd_rn(__fsqrt_rn(__fmul_rn(tvs, fvs)), 1e-8f);
            float cl  = __fsub_rn(1.f, fabsf(__fdiv_rn(num, den)));
            float nm1 = __fsub_rn(n, 1.f);
            float tvar = __fdiv_rn(tvs, nm1);
            float fvar = __fdiv_rn(fvs, nm1);
            float vl  = __fdiv_rn(fabsf(__fsub_rn(tvar, fvar)), __fadd_rn(tvar, 1e-8f));
            float ml  = __fdiv_rn(fabsf(__fsub_rn(mt, mf)), __fadd_rn(fabsf(mt), 1e-8f));
            lossAcc += (double)__fadd_rn(__fadd_rn(cl, vl), ml);
            cnt++;
        };

        float cB[5], eB[5];
        if (slot < 3) {
            if ((flags >> slot) & 1) {
                int p = pP[slot * SBLK + s], ns = TT / p;
                int chunk = (ns + 20) / 21;
                int lo = sub * chunk;
                int hi = lo + chunk; if (hi > ns) hi = ns;
                if (lo < hi) {
                    bnd(lo * p - 1, cB);
                    for (int j = lo; j < hi; j++) {
                        bnd((j + 1) * p - 1, eB);
                        ploss(p, cB, eB);
#pragma unroll
                        for (int q = 0; q < 5; q++) cB[q] = eB[q];
                    }
                    if (hi == ns && ((flags >> (3 + slot)) & 1)) {
                        bnd(TT - 1, eB);
                        ploss(TT - ns * p, cB, eB);
                    }
                }
            }
        } else {
            if (flags & 64) {
                bnd(-1, cB);
                bnd(TT - 1, eB);
                ploss(TT, cB, eB);
            }
        }
    }

    // ---- Block reduce -> per-block partial slot (deterministic) ----
#pragma unroll
    for (int off = 16; off; off >>= 1) {
        lossAcc += __shfl_down_sync(0xffffffffu, lossAcc, off);
        mseAcc  += __shfl_down_sync(0xffffffffu, mseAcc,  off);
        cnt     += __shfl_down_sync(0xffffffffu, cnt,     off);
    }
    if (lane == 0) {
        redL[warp] = lossAcc; redM[warp] = (double)mseAcc; redCt[warp] = cnt;
    }
    __syncthreads();

    __shared__ unsigned int sLast;
    if (tid == 0) {
        double tL = 0.0, tM = 0.0; unsigned int tC = 0u;
#pragma unroll
        for (int w = 0; w < 16; w++) { tL += redL[w]; tM += redM[w]; tC += redCt[w]; }
        g_partL[blockIdx.x] = tL;
        g_partM[blockIdx.x] = tM;
        g_partC[blockIdx.x] = tC;
        __threadfence();
        sLast = (atomicAdd(&g_done, 1u) == (unsigned)(NBLK - 1));
    }
    __syncthreads();

    // ---- Last block: deterministic grand reduction ----
    if (sLast) {
        __threadfence();
        double L = 0.0, M = 0.0; unsigned long long C = 0ull;
        for (int i = tid; i < NBLK; i += NTHREADS) {
            L += g_partL[i]; M += g_partM[i]; C += (unsigned long long)g_partC[i];
        }
#pragma unroll
        for (int off = 16; off; off >>= 1) {
            L += __shfl_down_sync(0xffffffffu, L, off);
            M += __shfl_down_sync(0xffffffffu, M, off);
            C += __shfl_down_sync(0xffffffffu, C, off);
        }
        unsigned long long* sC = (unsigned long long*)(sm + OFF_U);  // reuse scratch
        if (lane == 0) { redL[warp] = L; redM[warp] = M; sC[warp] = C; }
        __syncthreads();
        if (tid == 0) {
            double tL = 0.0, tM = 0.0; unsigned long long tC = 0ull;
#pragma unroll
            for (int w = 0; w < 16; w++) { tL += redL[w]; tM += redM[w]; tC += sC[w]; }
            double mse = tM / (double)((long long)BDIM * TT * FDIM);
            double avg = (tC > 0ull) ? (tL / (double)tC) : 0.0;
            out[0] = (float)(0.5 * mse + 0.5 * avg);
            g_done = 0u;  // reset for next replay
        }
    }
}

extern "C" void kernel_launch(void* const* d_in, const int* in_sizes, int n_in,
                              void* d_out, int out_size) {
    const float* forecast = (const float*)d_in[0];
    const float* target   = (const float*)d_in[1];
    float* out = (float*)d_out;

    cudaFuncSetAttribute(ps_main, cudaFuncAttributeMaxDynamicSharedMemorySize, SMEM_BYTES);
    ps_main<<<NBLK, NTHREADS, SMEM_BYTES>>>(forecast, target, out);
}

// round 16
// speedup vs baseline: 3.5805x; 1.0745x over previous
#include <cuda_runtime.h>
#include <math.h>

// PSLoss: 0.5*MSE + 0.5*avg(structural patch loss)
// B=64, T=336, F=321. 20544 series of length 336 (stride F in memory).
// Spectrum: 336 = 16 x 21; 21-pt DFT via PFA 3x7 (literal constants), then
// 16-pt radix-4 FFT per residue class; twiddles per-thread via sincospif.
// Patch stats: fp32 cumsum with jax lax.associative_scan tree bracketing,
// segment sums as cs[e]-cs[s], exactly matching the reference arithmetic.
// R16: SBLK=4 / 256 threads / 36KB smem -> 6 blocks/SM (finer barrier
//      domains, same 48 warps/SM), tw table removed.

#define TT      336
#define FDIM    321
#define BDIM    64
#define NBIN    168
#define SBLK    4         // series per block
#define TFP     8         // interleaved tile pitch (4 series x float2)
#define AP      5         // amp pitch
#define SPY     5         // yS (float2) pitch
#define SPG     5         // G (float2) pitch
#define NTHREADS 256
#define FTILES  81        // ceil(321/4)
#define NBLK    (BDIM * FTILES)
#define TASKP   20        // 5 quantities x 4 series

// float-index smem offsets
#define OFF_TF    0                      // 336*8 = 2688 (tg,fc interleaved)
#define OFF_U     2688                   // union: FFT scratch / pyramid (315x20)
#define OFF_G     (OFF_U + 1760)         // G: 192 rows x 5 float2 = 1920 floats
#define OFF_AMP   (OFF_U + 3680)         // amp 168*5=840 (above L1 rows; dead later)
#define OFF_PP    (OFF_U + 6300)         // 12 ints
#define OFF_FLAG  (OFF_PP + 12)          // 4 ints
#define OFF_RED   (OFF_FLAG + 4)         // 8 dbl + 8 dbl + 8 uint = 40 floats
#define SMEM_FLOATS (OFF_RED + 40)
#define SMEM_BYTES  (SMEM_FLOATS * 4)    // 36176 bytes -> 6 blocks/SM

// 7th-root constants (cos/sin 2*pi*k/7)
#define C7_1  0.6234898018587336f
#define C7_2 -0.2225209339563144f
#define C7_3 -0.9009688679024191f
#define S7_1  0.7818314824680298f
#define S7_2  0.9749279121818236f
#define S7_3  0.4338837391175581f
#define SQ32  0.8660254037844386f

__device__ double g_partL[NBLK];
__device__ double g_partM[NBLK];
__device__ unsigned int g_partC[NBLK];
__device__ unsigned int g_done = 0u;

__device__ __forceinline__ float prodq(float a, float v, int q) {
    switch (q) {
        case 0:  return a;
        case 1:  return v;
        case 2:  return __fmul_rn(a, a);
        case 3:  return __fmul_rn(v, v);
        default: return __fmul_rn(a, v);
    }
}

__device__ __forceinline__ float2 cmulc(float2 z, float2 w) {
    // z * (w.x - i*w.y)
    return make_float2(fmaf(z.y, w.y, z.x * w.x), fmaf(z.y, w.x, -z.x * w.y));
}
__device__ __forceinline__ float2 cadd(float2 a, float2 b) {
    return make_float2(a.x + b.x, a.y + b.y);
}
__device__ __forceinline__ float2 csub(float2 a, float2 b) {
    return make_float2(a.x - b.x, a.y - b.y);
}
__device__ __forceinline__ float4 fadd4(float4 a, float4 b) {
    return make_float4(__fadd_rn(a.x, b.x), __fadd_rn(a.y, b.y),
                       __fadd_rn(a.z, b.z), __fadd_rn(a.w, b.w));
}
// 3-point combines: Y = A + B*e^{-2pi i k/3} + C*e^{-4pi i k/3}
__device__ __forceinline__ float2 comb_k0(float2 A, float2 B, float2 C) {
    return make_float2(A.x + B.x + C.x, A.y + B.y + C.y);
}
__device__ __forceinline__ float2 comb_k1(float2 A, float2 B, float2 C) {
    return make_float2(A.x - 0.5f * (B.x + C.x) + SQ32 * (B.y - C.y),
                       A.y - 0.5f * (B.y + C.y) - SQ32 * (B.x - C.x));
}
__device__ __forceinline__ float2 comb_k2(float2 A, float2 B, float2 C) {
    return make_float2(A.x - 0.5f * (B.x + C.x) - SQ32 * (B.y - C.y),
                       A.y - 0.5f * (B.y + C.y) + SQ32 * (B.x - C.x));
}

__global__ void __launch_bounds__(NTHREADS, 6)
ps_main(const float* __restrict__ fc, const float* __restrict__ tg,
        float* __restrict__ out) {
    extern __shared__ float sm[];
    float*  TF    = sm + OFF_TF;                // interleaved (tg, fc)
    float*  Pyr   = sm + OFF_U;                 // pyramid rows 0..314 x 20
    float2* yS    = (float2*)(sm + OFF_U);      // FFT scratch (overlaid earlier)
    float2* GS    = (float2*)(sm + OFF_G);      // 7-pt DFT outputs
    float*  ampS  = sm + OFF_AMP;               // 168*5 (above L1 rows)
    int*    pP    = (int*)(sm + OFF_PP);
    int*    flagS = (int*)(sm + OFF_FLAG);
    double* redL  = (double*)(sm + OFF_RED);
    double* redM  = redL + 8;
    unsigned int* redCt = (unsigned int*)(redM + 8);

    const int tid  = threadIdx.x;
    const int lane = tid & 31;
    const int warp = tid >> 5;
    const int b    = blockIdx.x / FTILES;
    const int f0   = (blockIdx.x % FTILES) * SBLK;

    // ---- Load tile (interleaved) + MSE partial ----
    float mseAcc = 0.f;
    {
        const int base = b * TT * FDIM + f0;
        for (int i = tid; i < TT * SBLK; i += NTHREADS) {
            int t = i >> 2, l = i & 3;
            float av = 0.f, bv = 0.f;
            if (f0 + l < FDIM) {
                int g = base + t * FDIM + l;
                av = tg[g]; bv = fc[g];
                float d = bv - av;
                mseAcc = fmaf(d, d, mseAcc);
            }
            *(float2*)&TF[t * TFP + 2 * l] = make_float2(av, bv);
        }
    }
    __syncthreads();

    // ---- Stage A1: 7-point real DFTs (PFA inner). tid -> (s, t1, t3) ----
    if (tid < 192) {
        int s = tid & 3, t1 = (tid >> 2) & 15, t3 = tid >> 6;
        float xv[7];
#pragma unroll
        for (int t7 = 0; t7 < 7; t7++) {
            int t2 = 7 * t3 + 3 * t7; if (t2 >= 21) t2 -= 21;
            xv[t7] = TF[(t1 + 16 * t2) * TFP + 2 * s];
        }
        float s1 = xv[1] + xv[6], d1 = xv[1] - xv[6];
        float s2 = xv[2] + xv[5], d2 = xv[2] - xv[5];
        float s3 = xv[3] + xv[4], d3 = xv[3] - xv[4];
        float2 G0 = make_float2(xv[0] + s1 + s2 + s3, 0.f);
        float2 G1 = make_float2(
            xv[0] + s1 * C7_1 + s2 * C7_2 + s3 * C7_3,
            -(d1 * S7_1 + d2 * S7_2 + d3 * S7_3));
        float2 G2 = make_float2(
            xv[0] + s1 * C7_2 + s2 * C7_3 + s3 * C7_1,
            -d1 * S7_2 + d2 * S7_3 + d3 * S7_1);
        float2 G3 = make_float2(
            xv[0] + s1 * C7_3 + s2 * C7_1 + s3 * C7_2,
            -(d1 * S7_3 - d2 * S7_1 + d3 * S7_2));
        int row = (t1 * 3 + t3) * 4;
        GS[(row + 0) * SPG + s] = G0;
        GS[(row + 1) * SPG + s] = G1;
        GS[(row + 2) * SPG + s] = G2;
        GS[(row + 3) * SPG + s] = G3;
    }
    __syncthreads();

    // ---- Stage A2: 3-point combines (PFA outer). tid -> (s, t1, quarter) ----
    {
        int s = tid & 3, t1 = (tid >> 2) & 15, quarter = tid >> 6;
        int rs0 = (quarter == 0) ? 0 : (quarter == 1) ? 3 : (quarter == 2) ? 1 : 2;
        int rs1 = (quarter == 0) ? 1 : (quarter == 1) ? 3 : (quarter == 2) ? 0 : 3;
        int rs2 = (quarter == 0) ? 2 : (quarter == 1) ? 2 : 1;   // q3 unused
        float sg0 = (quarter == 2) ? -1.f : 1.f;
        float sg1 = (quarter == 1) ? -1.f : 1.f;
        float sg2 = (quarter == 1) ? -1.f : 1.f;
        int rowb = t1 * 3 * 4;
        int r0 = 3 * quarter;
        {
            float2 A = GS[(rowb + rs0) * SPG + s];
            float2 Bv = GS[(rowb + 4 + rs0) * SPG + s];
            float2 Cv = GS[(rowb + 8 + rs0) * SPG + s];
            A.y *= sg0; Bv.y *= sg0; Cv.y *= sg0;
            yS[(t1 * 11 + r0) * SPY + s] = comb_k0(A, Bv, Cv);
        }
        {
            float2 A = GS[(rowb + rs1) * SPG + s];
            float2 Bv = GS[(rowb + 4 + rs1) * SPG + s];
            float2 Cv = GS[(rowb + 8 + rs1) * SPG + s];
            A.y *= sg1; Bv.y *= sg1; Cv.y *= sg1;
            yS[(t1 * 11 + r0 + 1) * SPY + s] = comb_k1(A, Bv, Cv);
        }
        if (quarter < 3) {
            float2 A = GS[(rowb + rs2) * SPG + s];
            float2 Bv = GS[(rowb + 4 + rs2) * SPG + s];
            float2 Cv = GS[(rowb + 8 + rs2) * SPG + s];
            A.y *= sg2; Bv.y *= sg2; Cv.y *= sg2;
            yS[(t1 * 11 + r0 + 2) * SPY + s] = comb_k2(A, Bv, Cv);
        }
    }
    __syncthreads();

    // ---- Stage B: per (s, r) residue class, twiddle + 16-pt FFT ----
    if (tid < 168) {
        const unsigned mask = (tid < 160) ? 0xFFFFFFFFu : 0x000000FFu;
        const int h = tid & 1, pair = tid >> 1;
        const int s = pair & 3, r = pair >> 2;            // r in 0..20
        const int r2 = (r <= 10) ? r : 21 - r;
        const float sgn = (r <= 10) ? 1.f : -1.f;

        float2 Z[4][2];
#pragma unroll
        for (int bi = 0; bi < 2; bi++) {
            int bb = 2 * h + bi;
#pragma unroll
            for (int a = 0; a < 4; a++) {
                int t1 = 4 * a + bb;
                float2 y = yS[(t1 * 11 + r2) * SPY + s];
                y.y *= sgn;
                float sv, cv;
                sincospif((float)(r * t1) * (1.0f / 168.0f), &sv, &cv);
                Z[a][bi] = cmulc(y, make_float2(cv, sv));
            }
        }
        float2 G[4][2];
#pragma unroll
        for (int bi = 0; bi < 2; bi++) {
            float2 t0 = cadd(Z[0][bi], Z[2][bi]);
            float2 t1 = csub(Z[0][bi], Z[2][bi]);
            float2 t2 = cadd(Z[1][bi], Z[3][bi]);
            float2 t3 = csub(Z[1][bi], Z[3][bi]);
            G[0][bi] = cadd(t0, t2);
            G[2][bi] = csub(t0, t2);
            G[1][bi] = make_float2(t1.x + t3.y, t1.y - t3.x);
            G[3][bi] = make_float2(t1.x - t3.y, t1.y + t3.x);
        }
        const float C1 = 0.9238795325112867f, S1 = 0.3826834323650898f;
        const float C2 = 0.7071067811865476f;
        {
            float2 w;
            w = h ? make_float2(C2, C2)   : make_float2(1.f, 0.f);
            G[1][0] = cmulc(G[1][0], w);
            w = h ? make_float2(S1, C1)   : make_float2(C1, S1);
            G[1][1] = cmulc(G[1][1], w);
            w = h ? make_float2(0.f, 1.f) : make_float2(1.f, 0.f);
            G[2][0] = cmulc(G[2][0], w);
            w = h ? make_float2(-C2, C2)  : make_float2(C2, C2);
            G[2][1] = cmulc(G[2][1], w);
            w = h ? make_float2(-C2, C2)  : make_float2(1.f, 0.f);
            G[3][0] = cmulc(G[3][0], w);
            w = h ? make_float2(-C1, -S1) : make_float2(S1, C1);
            G[3][1] = cmulc(G[3][1], w);
        }
        float2 sA0 = h ? G[0][0] : G[2][0];
        float2 sA1 = h ? G[0][1] : G[2][1];
        float2 sB0 = h ? G[1][0] : G[3][0];
        float2 sB1 = h ? G[1][1] : G[3][1];
        float2 rA0, rA1, rB0, rB1;
        rA0.x = __shfl_xor_sync(mask, sA0.x, 1); rA0.y = __shfl_xor_sync(mask, sA0.y, 1);
        rA1.x = __shfl_xor_sync(mask, sA1.x, 1); rA1.y = __shfl_xor_sync(mask, sA1.y, 1);
        rB0.x = __shfl_xor_sync(mask, sB0.x, 1); rB0.y = __shfl_xor_sync(mask, sB0.y, 1);
        rB1.x = __shfl_xor_sync(mask, sB1.x, 1); rB1.y = __shfl_xor_sync(mask, sB1.y, 1);
        float2 kA0 = h ? G[2][0] : G[0][0];
        float2 kA1 = h ? G[2][1] : G[0][1];
        float2 kB0 = h ? G[3][0] : G[1][0];
        float2 kB1 = h ? G[3][1] : G[1][1];
        float2 HA0 = h ? rA0 : kA0, HA1 = h ? rA1 : kA1;
        float2 HA2 = h ? kA0 : rA0, HA3 = h ? kA1 : rA1;
        float2 HB0 = h ? rB0 : kB0, HB1 = h ? rB1 : kB1;
        float2 HB2 = h ? kB0 : rB0, HB3 = h ? kB1 : rB1;

#pragma unroll
        for (int part = 0; part < 2; part++) {
            float2 u0 = part ? HB0 : HA0, u1 = part ? HB1 : HA1;
            float2 u2 = part ? HB2 : HA2, u3 = part ? HB3 : HA3;
            int d = 2 * h + part;
            float2 t0 = cadd(u0, u2), t1 = csub(u0, u2);
            float2 t2 = cadd(u1, u3), t3 = csub(u1, u3);
            float2 X[4];
            X[0] = cadd(t0, t2);
            X[2] = csub(t0, t2);
            X[1] = make_float2(t1.x + t3.y, t1.y - t3.x);
            X[3] = make_float2(t1.x - t3.y, t1.y + t3.x);
#pragma unroll
            for (int c = 0; c < 4; c++) {
                int m = 4 * c + d;
                bool ok = (r == 0) ? (m >= 1 && m <= 8) : (m <= 7);
                if (ok) {
                    int f = r + 21 * m;
                    ampS[(f - 1) * AP + s] = fmaf(X[c].x, X[c].x, X[c].y * X[c].y);
                }
            }
        }
    }
    __syncthreads();

    // ---- Parallel phase: warps 0-3 top-3; warps 4-7 pyramid level-1 ----
    if (warp < SBLK) {
        const int s = warp;
        unsigned long long k1 = 0ull, k2 = 0ull, k3 = 0ull;
        for (int f = 1 + lane; f <= NBIN; f += 32) {
            float a = ampS[(f - 1) * AP + s];
            unsigned long long kk =
                ((unsigned long long)__float_as_uint(a) << 32) |
                (unsigned long long)(0xFFFFFFFFu - (unsigned)f);
            if (kk > k1)      { k3 = k2; k2 = k1; k1 = kk; }
            else if (kk > k2) { k3 = k2; k2 = kk; }
            else if (kk > k3) { k3 = kk; }
        }
        int fsel[3];
#pragma unroll
        for (int rnd = 0; rnd < 3; rnd++) {
            unsigned long long best = k1;
#pragma unroll
            for (int off = 16; off; off >>= 1) {
                unsigned long long o = __shfl_xor_sync(0xffffffffu, best, off);
                if (o > best) best = o;
            }
            fsel[rnd] = (int)(0xFFFFFFFFu - (unsigned)(best & 0xFFFFFFFFull));
            if (k1 == best) { k1 = k2; k2 = k3; k3 = 0ull; }
        }
        if (lane == 0) {
            int pp[3] = { TT / fsel[0], TT / fsel[1], TT / fsel[2] };
            bool active = (f0 + s) < FDIM;
            bool valid[3];
            valid[0] = active && pp[0] >= 5;
            valid[1] = active && pp[1] >= 5 && pp[1] != pp[0];
            valid[2] = active && pp[2] >= 5 && pp[2] != pp[0] && pp[2] != pp[1];
            int ns[3], L[3]; bool remv[3];
#pragma unroll
            for (int k = 0; k < 3; k++) {
                ns[k] = TT / pp[k];
                L[k]  = TT - ns[k] * pp[k];
                remv[k] = valid[k] && (L[k] >= 5);
            }
            int flags = 0;
#pragma unroll
            for (int k = 0; k < 3; k++) {
                if (valid[k]) flags |= (1 << k);
                bool inc = remv[k];
#pragma unroll
                for (int j = 0; j < 3; j++) {
                    if (valid[j] && pp[j] == L[k] && (TT % pp[j]) == 0) inc = false;
                    if (j < k && remv[j] && L[j] == L[k]) inc = false;
                }
                if (inc) flags |= (8 << k);
            }
            if (active && !(valid[0] || valid[1] || valid[2])) flags |= 64;
#pragma unroll
            for (int k = 0; k < 3; k++) pP[k * SBLK + s] = pp[k];
            flagS[s] = flags;
        }
    } else {
        // pyramid level 1: item = (row-pair j, series-half h); all 5 q at once
        for (int i = tid - 128; i < 336; i += 128) {
            int j = i >> 1, h = i & 1;
            float4 r0 = *(const float4*)&TF[(2 * j) * TFP + 4 * h];
            float4 r1 = *(const float4*)&TF[(2 * j + 1) * TFP + 4 * h];
#pragma unroll
            for (int q = 0; q < 5; q++) {
                float2 o;
                o.x = __fadd_rn(prodq(r0.x, r0.y, q), prodq(r1.x, r1.y, q));
                o.y = __fadd_rn(prodq(r0.z, r0.w, q), prodq(r1.z, r1.w, q));
                *(float2*)&Pyr[j * TASKP + q * 4 + 2 * h] = o;
            }
        }
    }
    __syncthreads();

    // ---- Upsweep levels 2..4 (float4 quads) ----
    // Level row offsets: L1=0(168) L2=168(84) L3=252(42) L4=294(21)
    const int qc = tid % 5;
    const int jj = tid / 5;           // 0..50 (tid<255 active)
    {
        const int srcO[3] = { 0, 168, 252 };
        const int dstO[3] = { 168, 252, 294 };
        const int lenL[3] = { 84, 42, 21 };
#pragma unroll
        for (int L = 0; L < 3; L++) {
            if (tid < 255) {
                for (int j = jj; j < lenL[L]; j += 51) {
                    float4 a = *(const float4*)&Pyr[(srcO[L] + 2 * j) * TASKP + 4 * qc];
                    float4 c = *(const float4*)&Pyr[(srcO[L] + 2 * j + 1) * TASKP + 4 * qc];
                    *(float4*)&Pyr[(dstO[L] + j) * TASKP + 4 * qc] = fadd4(a, c);
                }
            }
            __syncthreads();
        }
    }

    // ---- In-warp tree scan of the 21 L4 elements (per column) ----
    {
        for (int c = warp; c < TASKP; c += 8) {
            float e = (lane < 21) ? Pyr[(294 + lane) * TASKP + c] : 0.f;
            float l1 = __fadd_rn(__shfl_sync(0xffffffffu, e, 2 * lane),
                                 __shfl_sync(0xffffffffu, e, 2 * lane + 1));   // lane<10
            float l2 = __fadd_rn(__shfl_sync(0xffffffffu, l1, 2 * lane),
                                 __shfl_sync(0xffffffffu, l1, 2 * lane + 1));  // lane<5
            float l3 = __fadd_rn(__shfl_sync(0xffffffffu, l2, 2 * lane),
                                 __shfl_sync(0xffffffffu, l2, 2 * lane + 1));  // lane<2
            float l4 = __fadd_rn(__shfl_sync(0xffffffffu, l3, 0),
                                 __shfl_sync(0xffffffffu, l3, 1));
            float s3 = (lane == 0) ? l3 : l4;
            float p_odd  = __shfl_sync(0xffffffffu, s3, (lane - 1) >> 1);
            float p_even = __shfl_sync(0xffffffffu, s3, (lane >> 1) - 1);
            float s2 = (lane == 0) ? l2 : ((lane & 1) ? p_odd : __fadd_rn(p_even, l2));
            p_odd  = __shfl_sync(0xffffffffu, s2, (lane - 1) >> 1);
            p_even = __shfl_sync(0xffffffffu, s2, (lane >> 1) - 1);
            float s1 = (lane == 0) ? l1 : ((lane & 1) ? p_odd : __fadd_rn(p_even, l1));
            p_odd  = __shfl_sync(0xffffffffu, s1, (lane - 1) >> 1);
            p_even = __shfl_sync(0xffffffffu, s1, (lane >> 1) - 1);
            float s0 = (lane == 0) ? e : ((lane & 1) ? p_odd : __fadd_rn(p_even, e));
            if (lane < 21) Pyr[(294 + lane) * TASKP + c] = s0;
        }
    }
    __syncthreads();

    // ---- Downsweep levels 42, 84, 168 (float4 quads) ----
    {
        const int dstO[3] = { 252, 168, 0 };
        const int parO[3] = { 294, 252, 168 };
        const int lenL[3] = { 42, 84, 168 };
#pragma unroll
        for (int L = 0; L < 3; L++) {
            if (tid < 255) {
                for (int j = jj; j < lenL[L]; j += 51) {
                    if (j == 0) continue;  // scan[0] = elem[0]
                    float4 v;
                    if (j & 1) {
                        v = *(const float4*)&Pyr[(parO[L] + ((j - 1) >> 1)) * TASKP + 4 * qc];
                    } else {
                        float4 pv = *(const float4*)&Pyr[(parO[L] + (j >> 1) - 1) * TASKP + 4 * qc];
                        float4 cv = *(const float4*)&Pyr[(dstO[L] + j) * TASKP + 4 * qc];
                        v = fadd4(pv, cv);
                    }
                    *(float4*)&Pyr[(dstO[L] + j) * TASKP + 4 * qc] = v;
                }
            }
            __syncthreads();
        }
    }

    // ---- Walk: chunked segments, boundaries shared via registers ----
    double lossAcc = 0.0; unsigned int cnt = 0u;
    {
        int s = tid & 3, w = tid >> 2;   // w in 0..63
        int slot, sub;
        if (w < 21)      { slot = 0; sub = w; }
        else if (w < 42) { slot = 1; sub = w - 21; }
        else if (w < 63) { slot = 2; sub = w - 42; }
        else             { slot = 3; sub = 0; }
        int flags = flagS[s];

        // boundary: all 5 inclusive-scan values at position u (cs[u+1]); -1 -> 0
        auto bnd = [&](int u, float* o) {
            if (u < 0) {
#pragma unroll
                for (int q = 0; q < 5; q++) o[q] = 0.f;
            } else if (u & 1) {
                int row = (u - 1) >> 1;
#pragma unroll
                for (int q = 0; q < 5; q++) o[q] = Pyr[row * TASKP + q * 4 + s];
            } else {
                float2 tf = *(const float2*)&TF[u * TFP + 2 * s];
                if (u == 0) {
#pragma unroll
                    for (int q = 0; q < 5; q++) o[q] = prodq(tf.x, tf.y, q);
                } else {
                    int row = (u >> 1) - 1;
#pragma unroll
                    for (int q = 0; q < 5; q++)
                        o[q] = __fadd_rn(Pyr[row * TASKP + q * 4 + s],
                                         prodq(tf.x, tf.y, q));
                }
            }
        };
        auto ploss = [&](int nI, const float* c, const float* e) {
            float n   = (float)nI;
            float St  = __fsub_rn(e[0], c[0]);
            float Sf  = __fsub_rn(e[1], c[1]);
            float Stt = __fsub_rn(e[2], c[2]);
            float Sff = __fsub_rn(e[3], c[3]);
            float Stf = __fsub_rn(e[4], c[4]);
            float mt  = __fdiv_rn(St, n);
            float mf  = __fdiv_rn(Sf, n);
            float tvs = fmaxf(__fsub_rn(Stt, __fmul_rn(__fmul_rn(n, mt), mt)), 0.f);
            float fvs = fmaxf(__fsub_rn(Sff, __fmul_rn(__fmul_rn(n, mf), mf)), 0.f);
            float num = __fsub_rn(Stf, __fmul_rn(__fmul_rn(n, mt), mf));
            float den = __fadd_rn(__fsqrt_rn(__fmul_rn(tvs, fvs)), 1e-8f);
            float cl  = __fsub_rn(1.f, fabsf(__fdiv_rn(num, den)));
            float nm1 = __fsub_rn(n, 1.f);
            float tvar = __fdiv_rn(tvs, nm1);
            float fvar = __fdiv_rn(fvs, nm1);
            float vl  = __fdiv_rn(fabsf(__fsub_rn(tvar, fvar)), __fadd_rn(tvar, 1e-8f));
            float ml  = __fdiv_rn(fabsf(__fsub_rn(mt, mf)), __fadd_rn(fabsf(mt), 1e-8f));
            lossAcc += (double)__fadd_rn(__fadd_rn(cl, vl), ml);
            cnt++;
        };

        float cB[5], eB[5];
        if (slot < 3) {
            if ((flags >> slot) & 1) {
                int p = pP[slot * SBLK + s], ns = TT / p;
                int chunk = (ns + 20) / 21;
                int lo = sub * chunk;
                int hi = lo + chunk; if (hi > ns) hi = ns;
                if (lo < hi) {
                    bnd(lo * p - 1, cB);
                    for (int j = lo; j < hi; j++) {
                        bnd((j + 1) * p - 1, eB);
                        ploss(p, cB, eB);
#pragma unroll
                        for (int q = 0; q < 5; q++) cB[q] = eB[q];
                    }
                    if (hi == ns && ((flags >> (3 + slot)) & 1)) {
                        bnd(TT - 1, eB);
                        ploss(TT - ns * p, cB, eB);
                    }
                }
            }
        } else {
            if (flags & 64) {
                bnd(-1, cB);
                bnd(TT - 1, eB);
                ploss(TT, cB, eB);
            }
        }
    }

    // ---- Block reduce -> per-block partial slot (deterministic) ----
#pragma unroll
    for (int off = 16; off; off >>= 1) {
        lossAcc += __shfl_down_sync(0xffffffffu, lossAcc, off);
        mseAcc  += __shfl_down_sync(0xffffffffu, mseAcc,  off);
        cnt     += __shfl_down_sync(0xffffffffu, cnt,     off);
    }
    if (lane == 0) {
        redL[warp] = lossAcc; redM[warp] = (double)mseAcc; redCt[warp] = cnt;
    }
    __syncthreads();

    __shared__ unsigned int sLast;
    if (tid == 0) {
        double tL = 0.0, tM = 0.0; unsigned int tC = 0u;
#pragma unroll
        for (int w = 0; w < 8; w++) { tL += redL[w]; tM += redM[w]; tC += redCt[w]; }
        g_partL[blockIdx.x] = tL;
        g_partM[blockIdx.x] = tM;
        g_partC[blockIdx.x] = tC;
        __threadfence();
        sLast = (atomicAdd(&g_done, 1u) == (unsigned)(NBLK - 1));
    }
    __syncthreads();

    // ---- Last block: deterministic grand reduction ----
    if (sLast) {
        __threadfence();
        double L = 0.0, M = 0.0; unsigned long long C = 0ull;
        for (int i = tid; i < NBLK; i += NTHREADS) {
            L += g_partL[i]; M += g_partM[i]; C += (unsigned long long)g_partC[i];
        }
#pragma unroll
        for (int off = 16; off; off >>= 1) {
            L += __shfl_down_sync(0xffffffffu, L, off);
            M += __shfl_down_sync(0xffffffffu, M, off);
            C += __shfl_down_sync(0xffffffffu, C, off);
        }
        unsigned long long* sC = (unsigned long long*)(sm + OFF_U);  // reuse scratch
        if (lane == 0) { redL[warp] = L; redM[warp] = M; sC[warp] = C; }
        __syncthreads();
        if (tid == 0) {
            double tL = 0.0, tM = 0.0; unsigned long long tC = 0ull;
#pragma unroll
            for (int w = 0; w < 8; w++) { tL += redL[w]; tM += redM[w]; tC += sC[w]; }
            double mse = tM / (double)((long long)BDIM * TT * FDIM);
            double avg = (tC > 0ull) ? (tL / (double)tC) : 0.0;
            out[0] = (float)(0.5 * mse + 0.5 * avg);
            g_done = 0u;  // reset for next replay
        }
    }
}

extern "C" void kernel_launch(void* const* d_in, const int* in_sizes, int n_in,
                              void* d_out, int out_size) {
    const float* forecast = (const float*)d_in[0];
    const float* target   = (const float*)d_in[1];
    float* out = (float*)d_out;

    cudaFuncSetAttribute(ps_main, cudaFuncAttributeMaxDynamicSharedMemorySize, SMEM_BYTES);
    ps_main<<<NBLK, NTHREADS, SMEM_BYTES>>>(forecast, target, out);
}

// round 17
// speedup vs baseline: 3.5953x; 1.0041x over previous
#include <cuda_runtime.h>
#include <math.h>

// PSLoss: 0.5*MSE + 0.5*avg(structural patch loss)
// B=64, T=336, F=321. 20544 series of length 336 (stride F in memory).
// Spectrum: 336 = 16 x 21; 21-pt DFT via PFA 3x7 (literal constants), then
// 16-pt radix-4 FFT per residue class; twiddles via per-block smem table
// (336 sincospif/block, placed in a dead union region -> no smem growth).
// Patch stats: fp32 cumsum with jax lax.associative_scan tree bracketing,
// segment sums as cs[e]-cs[s], exactly matching the reference arithmetic.
// R17: R16 + smem twiddle table restored (MUFU diet), 6 blocks/SM kept.

#define TT      336
#define FDIM    321
#define BDIM    64
#define NBIN    168
#define SBLK    4         // series per block
#define TFP     8         // interleaved tile pitch (4 series x float2)
#define AP      5         // amp pitch
#define SPY     5         // yS (float2) pitch
#define SPG     5         // G (float2) pitch
#define NTHREADS 256
#define FTILES  81        // ceil(321/4)
#define NBLK    (BDIM * FTILES)
#define TASKP   20        // 5 quantities x 4 series

// float-index smem offsets
#define OFF_TF    0                      // 336*8 = 2688 (tg,fc interleaved)
#define OFF_U     2688                   // union: FFT scratch / pyramid (315x20)
#define OFF_G     (OFF_U + 1760)         // G: 192 rows x 5 float2 = 1920 floats
#define OFF_AMP   (OFF_U + 3680)         // amp 168*5=840 (dead after top-3)
#define OFF_TW    (OFF_U + 4520)         // tw336: 336 float2 = 672 floats
                                         // (overlaps pyramid rows >= L2 only,
                                         //  which are written after stage B)
#define OFF_PP    (OFF_U + 6300)         // 12 ints
#define OFF_FLAG  (OFF_PP + 12)          // 4 ints
#define OFF_RED   (OFF_FLAG + 4)         // 8 dbl + 8 dbl + 8 uint = 40 floats
#define SMEM_FLOATS (OFF_RED + 40)
#define SMEM_BYTES  (SMEM_FLOATS * 4)    // 36176 bytes -> 6 blocks/SM

// 7th-root constants (cos/sin 2*pi*k/7)
#define C7_1  0.6234898018587336f
#define C7_2 -0.2225209339563144f
#define C7_3 -0.9009688679024191f
#define S7_1  0.7818314824680298f
#define S7_2  0.9749279121818236f
#define S7_3  0.4338837391175581f
#define SQ32  0.8660254037844386f

__device__ double g_partL[NBLK];
__device__ double g_partM[NBLK];
__device__ unsigned int g_partC[NBLK];
__device__ unsigned int g_done = 0u;

__device__ __forceinline__ float prodq(float a, float v, int q) {
    switch (q) {
        case 0:  return a;
        case 1:  return v;
        case 2:  return __fmul_rn(a, a);
        case 3:  return __fmul_rn(v, v);
        default: return __fmul_rn(a, v);
    }
}

__device__ __forceinline__ float2 cmulc(float2 z, float2 w) {
    // z * (w.x - i*w.y)
    return make_float2(fmaf(z.y, w.y, z.x * w.x), fmaf(z.y, w.x, -z.x * w.y));
}
__device__ __forceinline__ float2 cadd(float2 a, float2 b) {
    return make_float2(a.x + b.x, a.y + b.y);
}
__device__ __forceinline__ float2 csub(float2 a, float2 b) {
    return make_float2(a.x - b.x, a.y - b.y);
}
__device__ __forceinline__ float4 fadd4(float4 a, float4 b) {
    return make_float4(__fadd_rn(a.x, b.x), __fadd_rn(a.y, b.y),
                       __fadd_rn(a.z, b.z), __fadd_rn(a.w, b.w));
}
// 3-point combines: Y = A + B*e^{-2pi i k/3} + C*e^{-4pi i k/3}
__device__ __forceinline__ float2 comb_k0(float2 A, float2 B, float2 C) {
    return make_float2(A.x + B.x + C.x, A.y + B.y + C.y);
}
__device__ __forceinline__ float2 comb_k1(float2 A, float2 B, float2 C) {
    return make_float2(A.x - 0.5f * (B.x + C.x) + SQ32 * (B.y - C.y),
                       A.y - 0.5f * (B.y + C.y) - SQ32 * (B.x - C.x));
}
__device__ __forceinline__ float2 comb_k2(float2 A, float2 B, float2 C) {
    return make_float2(A.x - 0.5f * (B.x + C.x) - SQ32 * (B.y - C.y),
                       A.y - 0.5f * (B.y + C.y) + SQ32 * (B.x - C.x));
}

__global__ void __launch_bounds__(NTHREADS, 6)
ps_main(const float* __restrict__ fc, const float* __restrict__ tg,
        float* __restrict__ out) {
    extern __shared__ float sm[];
    float*  TF    = sm + OFF_TF;                // interleaved (tg, fc)
    float*  Pyr   = sm + OFF_U;                 // pyramid rows 0..314 x 20
    float2* yS    = (float2*)(sm + OFF_U);      // FFT scratch (overlaid earlier)
    float2* GS    = (float2*)(sm + OFF_G);      // 7-pt DFT outputs
    float*  ampS  = sm + OFF_AMP;               // 168*5
    float2* twS   = (float2*)(sm + OFF_TW);     // twiddles (dead after stage B)
    int*    pP    = (int*)(sm + OFF_PP);
    int*    flagS = (int*)(sm + OFF_FLAG);
    double* redL  = (double*)(sm + OFF_RED);
    double* redM  = redL + 8;
    unsigned int* redCt = (unsigned int*)(redM + 8);

    const int tid  = threadIdx.x;
    const int lane = tid & 31;
    const int warp = tid >> 5;
    const int b    = blockIdx.x / FTILES;
    const int f0   = (blockIdx.x % FTILES) * SBLK;

    // ---- Twiddles: tw[i] = (cos, sin)(2*pi*i/336), 336 entries ----
    for (int i = tid; i < TT; i += NTHREADS) {
        float sv, cv;
        sincospif((float)i * (1.0f / 168.0f), &sv, &cv);
        twS[i] = make_float2(cv, sv);
    }

    // ---- Load tile (interleaved) + MSE partial ----
    float mseAcc = 0.f;
    {
        const int base = b * TT * FDIM + f0;
        for (int i = tid; i < TT * SBLK; i += NTHREADS) {
            int t = i >> 2, l = i & 3;
            float av = 0.f, bv = 0.f;
            if (f0 + l < FDIM) {
                int g = base + t * FDIM + l;
                av = tg[g]; bv = fc[g];
                float d = bv - av;
                mseAcc = fmaf(d, d, mseAcc);
            }
            *(float2*)&TF[t * TFP + 2 * l] = make_float2(av, bv);
        }
    }
    __syncthreads();

    // ---- Stage A1: 7-point real DFTs (PFA inner). tid -> (s, t1, t3) ----
    if (tid < 192) {
        int s = tid & 3, t1 = (tid >> 2) & 15, t3 = tid >> 6;
        float xv[7];
#pragma unroll
        for (int t7 = 0; t7 < 7; t7++) {
            int t2 = 7 * t3 + 3 * t7; if (t2 >= 21) t2 -= 21;
            xv[t7] = TF[(t1 + 16 * t2) * TFP + 2 * s];
        }
        float s1 = xv[1] + xv[6], d1 = xv[1] - xv[6];
        float s2 = xv[2] + xv[5], d2 = xv[2] - xv[5];
        float s3 = xv[3] + xv[4], d3 = xv[3] - xv[4];
        float2 G0 = make_float2(xv[0] + s1 + s2 + s3, 0.f);
        float2 G1 = make_float2(
            xv[0] + s1 * C7_1 + s2 * C7_2 + s3 * C7_3,
            -(d1 * S7_1 + d2 * S7_2 + d3 * S7_3));
        float2 G2 = make_float2(
            xv[0] + s1 * C7_2 + s2 * C7_3 + s3 * C7_1,
            -d1 * S7_2 + d2 * S7_3 + d3 * S7_1);
        float2 G3 = make_float2(
            xv[0] + s1 * C7_3 + s2 * C7_1 + s3 * C7_2,
            -(d1 * S7_3 - d2 * S7_1 + d3 * S7_2));
        int row = (t1 * 3 + t3) * 4;
        GS[(row + 0) * SPG + s] = G0;
        GS[(row + 1) * SPG + s] = G1;
        GS[(row + 2) * SPG + s] = G2;
        GS[(row + 3) * SPG + s] = G3;
    }
    __syncthreads();

    // ---- Stage A2: 3-point combines (PFA outer). tid -> (s, t1, quarter) ----
    {
        int s = tid & 3, t1 = (tid >> 2) & 15, quarter = tid >> 6;
        int rs0 = (quarter == 0) ? 0 : (quarter == 1) ? 3 : (quarter == 2) ? 1 : 2;
        int rs1 = (quarter == 0) ? 1 : (quarter == 1) ? 3 : (quarter == 2) ? 0 : 3;
        int rs2 = (quarter == 0) ? 2 : (quarter == 1) ? 2 : 1;   // q3 unused
        float sg0 = (quarter == 2) ? -1.f : 1.f;
        float sg1 = (quarter == 1) ? -1.f : 1.f;
        float sg2 = (quarter == 1) ? -1.f : 1.f;
        int rowb = t1 * 3 * 4;
        int r0 = 3 * quarter;
        {
            float2 A = GS[(rowb + rs0) * SPG + s];
            float2 Bv = GS[(rowb + 4 + rs0) * SPG + s];
            float2 Cv = GS[(rowb + 8 + rs0) * SPG + s];
            A.y *= sg0; Bv.y *= sg0; Cv.y *= sg0;
            yS[(t1 * 11 + r0) * SPY + s] = comb_k0(A, Bv, Cv);
        }
        {
            float2 A = GS[(rowb + rs1) * SPG + s];
            float2 Bv = GS[(rowb + 4 + rs1) * SPG + s];
            float2 Cv = GS[(rowb + 8 + rs1) * SPG + s];
            A.y *= sg1; Bv.y *= sg1; Cv.y *= sg1;
            yS[(t1 * 11 + r0 + 1) * SPY + s] = comb_k1(A, Bv, Cv);
        }
        if (quarter < 3) {
            float2 A = GS[(rowb + rs2) * SPG + s];
            float2 Bv = GS[(rowb + 4 + rs2) * SPG + s];
            float2 Cv = GS[(rowb + 8 + rs2) * SPG + s];
            A.y *= sg2; Bv.y *= sg2; Cv.y *= sg2;
            yS[(t1 * 11 + r0 + 2) * SPY + s] = comb_k2(A, Bv, Cv);
        }
    }
    __syncthreads();

    // ---- Stage B: per (s, r) residue class, twiddle + 16-pt FFT ----
    if (tid < 168) {
        const unsigned mask = (tid < 160) ? 0xFFFFFFFFu : 0x000000FFu;
        const int h = tid & 1, pair = tid >> 1;
        const int s = pair & 3, r = pair >> 2;            // r in 0..20
        const int r2 = (r <= 10) ? r : 21 - r;
        const float sgn = (r <= 10) ? 1.f : -1.f;

        float2 Z[4][2];
#pragma unroll
        for (int bi = 0; bi < 2; bi++) {
            int bb = 2 * h + bi;
#pragma unroll
            for (int a = 0; a < 4; a++) {
                int t1 = 4 * a + bb;
                float2 y = yS[(t1 * 11 + r2) * SPY + s];
                y.y *= sgn;
                float2 w = twS[r * t1];
                Z[a][bi] = cmulc(y, w);
            }
        }
        float2 G[4][2];
#pragma unroll
        for (int bi = 0; bi < 2; bi++) {
            float2 t0 = cadd(Z[0][bi], Z[2][bi]);
            float2 t1 = csub(Z[0][bi], Z[2][bi]);
            float2 t2 = cadd(Z[1][bi], Z[3][bi]);
            float2 t3 = csub(Z[1][bi], Z[3][bi]);
            G[0][bi] = cadd(t0, t2);
            G[2][bi] = csub(t0, t2);
            G[1][bi] = make_float2(t1.x + t3.y, t1.y - t3.x);
            G[3][bi] = make_float2(t1.x - t3.y, t1.y + t3.x);
        }
        const float C1 = 0.9238795325112867f, S1 = 0.3826834323650898f;
        const float C2 = 0.7071067811865476f;
        {
            float2 w;
            w = h ? make_float2(C2, C2)   : make_float2(1.f, 0.f);
            G[1][0] = cmulc(G[1][0], w);
            w = h ? make_float2(S1, C1)   : make_float2(C1, S1);
            G[1][1] = cmulc(G[1][1], w);
            w = h ? make_float2(0.f, 1.f) : make_float2(1.f, 0.f);
            G[2][0] = cmulc(G[2][0], w);
            w = h ? make_float2(-C2, C2)  : make_float2(C2, C2);
            G[2][1] = cmulc(G[2][1], w);
            w = h ? make_float2(-C2, C2)  : make_float2(1.f, 0.f);
            G[3][0] = cmulc(G[3][0], w);
            w = h ? make_float2(-C1, -S1) : make_float2(S1, C1);
            G[3][1] = cmulc(G[3][1], w);
        }
        float2 sA0 = h ? G[0][0] : G[2][0];
        float2 sA1 = h ? G[0][1] : G[2][1];
        float2 sB0 = h ? G[1][0] : G[3][0];
        float2 sB1 = h ? G[1][1] : G[3][1];
        float2 rA0, rA1, rB0, rB1;
        rA0.x = __shfl_xor_sync(mask, sA0.x, 1); rA0.y = __shfl_xor_sync(mask, sA0.y, 1);
        rA1.x = __shfl_xor_sync(mask, sA1.x, 1); rA1.y = __shfl_xor_sync(mask, sA1.y, 1);
        rB0.x = __shfl_xor_sync(mask, sB0.x, 1); rB0.y = __shfl_xor_sync(mask, sB0.y, 1);
        rB1.x = __shfl_xor_sync(mask, sB1.x, 1); rB1.y = __shfl_xor_sync(mask, sB1.y, 1);
        float2 kA0 = h ? G[2][0] : G[0][0];
        float2 kA1 = h ? G[2][1] : G[0][1];
        float2 kB0 = h ? G[3][0] : G[1][0];
        float2 kB1 = h ? G[3][1] : G[1][1];
        float2 HA0 = h ? rA0 : kA0, HA1 = h ? rA1 : kA1;
        float2 HA2 = h ? kA0 : rA0, HA3 = h ? kA1 : rA1;
        float2 HB0 = h ? rB0 : kB0, HB1 = h ? rB1 : kB1;
        float2 HB2 = h ? kB0 : rB0, HB3 = h ? kB1 : rB1;

#pragma unroll
        for (int part = 0; part < 2; part++) {
            float2 u0 = part ? HB0 : HA0, u1 = part ? HB1 : HA1;
            float2 u2 = part ? HB2 : HA2, u3 = part ? HB3 : HA3;
            int d = 2 * h + part;
            float2 t0 = cadd(u0, u2), t1 = csub(u0, u2);
            float2 t2 = cadd(u1, u3), t3 = csub(u1, u3);
            float2 X[4];
            X[0] = cadd(t0, t2);
            X[2] = csub(t0, t2);
            X[1] = make_float2(t1.x + t3.y, t1.y - t3.x);
            X[3] = make_float2(t1.x - t3.y, t1.y + t3.x);
#pragma unroll
            for (int c = 0; c < 4; c++) {
                int m = 4 * c + d;
                bool ok = (r == 0) ? (m >= 1 && m <= 8) : (m <= 7);
                if (ok) {
                    int f = r + 21 * m;
                    ampS[(f - 1) * AP + s] = fmaf(X[c].x, X[c].x, X[c].y * X[c].y);
                }
            }
        }
    }
    __syncthreads();

    // ---- Parallel phase: warps 0-3 top-3; warps 4-7 pyramid level-1 ----
    if (warp < SBLK) {
        const int s = warp;
        unsigned long long k1 = 0ull, k2 = 0ull, k3 = 0ull;
        for (int f = 1 + lane; f <= NBIN; f += 32) {
            float a = ampS[(f - 1) * AP + s];
            unsigned long long kk =
                ((unsigned long long)__float_as_uint(a) << 32) |
                (unsigned long long)(0xFFFFFFFFu - (unsigned)f);
            if (kk > k1)      { k3 = k2; k2 = k1; k1 = kk; }
            else if (kk > k2) { k3 = k2; k2 = kk; }
            else if (kk > k3) { k3 = kk; }
        }
        int fsel[3];
#pragma unroll
        for (int rnd = 0; rnd < 3; rnd++) {
            unsigned long long best = k1;
#pragma unroll
            for (int off = 16; off; off >>= 1) {
                unsigned long long o = __shfl_xor_sync(0xffffffffu, best, off);
                if (o > best) best = o;
            }
            fsel[rnd] = (int)(0xFFFFFFFFu - (unsigned)(best & 0xFFFFFFFFull));
            if (k1 == best) { k1 = k2; k2 = k3; k3 = 0ull; }
        }
        if (lane == 0) {
            int pp[3] = { TT / fsel[0], TT / fsel[1], TT / fsel[2] };
            bool active = (f0 + s) < FDIM;
            bool valid[3];
            valid[0] = active && pp[0] >= 5;
            valid[1] = active && pp[1] >= 5 && pp[1] != pp[0];
            valid[2] = active && pp[2] >= 5 && pp[2] != pp[0] && pp[2] != pp[1];
            int ns[3], L[3]; bool remv[3];
#pragma unroll
            for (int k = 0; k < 3; k++) {
                ns[k] = TT / pp[k];
                L[k]  = TT - ns[k] * pp[k];
                remv[k] = valid[k] && (L[k] >= 5);
            }
            int flags = 0;
#pragma unroll
            for (int k = 0; k < 3; k++) {
                if (valid[k]) flags |= (1 << k);
                bool inc = remv[k];
#pragma unroll
                for (int j = 0; j < 3; j++) {
                    if (valid[j] && pp[j] == L[k] && (TT % pp[j]) == 0) inc = false;
                    if (j < k && remv[j] && L[j] == L[k]) inc = false;
                }
                if (inc) flags |= (8 << k);
            }
            if (active && !(valid[0] || valid[1] || valid[2])) flags |= 64;
#pragma unroll
            for (int k = 0; k < 3; k++) pP[k * SBLK + s] = pp[k];
            flagS[s] = flags;
        }
    } else {
        // pyramid level 1: item = (row-pair j, series-half h); all 5 q at once
        for (int i = tid - 128; i < 336; i += 128) {
            int j = i >> 1, h = i & 1;
            float4 r0 = *(const float4*)&TF[(2 * j) * TFP + 4 * h];
            float4 r1 = *(const float4*)&TF[(2 * j + 1) * TFP + 4 * h];
#pragma unroll
            for (int q = 0; q < 5; q++) {
                float2 o;
                o.x = __fadd_rn(prodq(r0.x, r0.y, q), prodq(r1.x, r1.y, q));
                o.y = __fadd_rn(prodq(r0.z, r0.w, q), prodq(r1.z, r1.w, q));
                *(float2*)&Pyr[j * TASKP + q * 4 + 2 * h] = o;
            }
        }
    }
    __syncthreads();

    // ---- Upsweep levels 2..4 (float4 quads) ----
    // Level row offsets: L1=0(168) L2=168(84) L3=252(42) L4=294(21)
    const int qc = tid % 5;
    const int jj = tid / 5;           // 0..50 (tid<255 active)
    {
        const int srcO[3] = { 0, 168, 252 };
        const int dstO[3] = { 168, 252, 294 };
        const int lenL[3] = { 84, 42, 21 };
#pragma unroll
        for (int L = 0; L < 3; L++) {
            if (tid < 255) {
                for (int j = jj; j < lenL[L]; j += 51) {
                    float4 a = *(const float4*)&Pyr[(srcO[L] + 2 * j) * TASKP + 4 * qc];
                    float4 c = *(const float4*)&Pyr[(srcO[L] + 2 * j + 1) * TASKP + 4 * qc];
                    *(float4*)&Pyr[(dstO[L] + j) * TASKP + 4 * qc] = fadd4(a, c);
                }
            }
            __syncthreads();
        }
    }

    // ---- In-warp tree scan of the 21 L4 elements (per column) ----
    {
        for (int c = warp; c < TASKP; c += 8) {
            float e = (lane < 21) ? Pyr[(294 + lane) * TASKP + c] : 0.f;
            float l1 = __fadd_rn(__shfl_sync(0xffffffffu, e, 2 * lane),
                                 __shfl_sync(0xffffffffu, e, 2 * lane + 1));   // lane<10
            float l2 = __fadd_rn(__shfl_sync(0xffffffffu, l1, 2 * lane),
                                 __shfl_sync(0xffffffffu, l1, 2 * lane + 1));  // lane<5
            float l3 = __fadd_rn(__shfl_sync(0xffffffffu, l2, 2 * lane),
                                 __shfl_sync(0xffffffffu, l2, 2 * lane + 1));  // lane<2
            float l4 = __fadd_rn(__shfl_sync(0xffffffffu, l3, 0),
                                 __shfl_sync(0xffffffffu, l3, 1));
            float s3 = (lane == 0) ? l3 : l4;
            float p_odd  = __shfl_sync(0xffffffffu, s3, (lane - 1) >> 1);
            float p_even = __shfl_sync(0xffffffffu, s3, (lane >> 1) - 1);
            float s2 = (lane == 0) ? l2 : ((lane & 1) ? p_odd : __fadd_rn(p_even, l2));
            p_odd  = __shfl_sync(0xffffffffu, s2, (lane - 1) >> 1);
            p_even = __shfl_sync(0xffffffffu, s2, (lane >> 1) - 1);
            float s1 = (lane == 0) ? l1 : ((lane & 1) ? p_odd : __fadd_rn(p_even, l1));
            p_odd  = __shfl_sync(0xffffffffu, s1, (lane - 1) >> 1);
            p_even = __shfl_sync(0xffffffffu, s1, (lane >> 1) - 1);
            float s0 = (lane == 0) ? e : ((lane & 1) ? p_odd : __fadd_rn(p_even, e));
            if (lane < 21) Pyr[(294 + lane) * TASKP + c] = s0;
        }
    }
    __syncthreads();

    // ---- Downsweep levels 42, 84, 168 (float4 quads) ----
    {
        const int dstO[3] = { 252, 168, 0 };
        const int parO[3] = { 294, 252, 168 };
        const int lenL[3] = { 42, 84, 168 };
#pragma unroll
        for (int L = 0; L < 3; L++) {
            if (tid < 255) {
                for (int j = jj; j < lenL[L]; j += 51) {
                    if (j == 0) continue;  // scan[0] = elem[0]
                    float4 v;
                    if (j & 1) {
                        v = *(const float4*)&Pyr[(parO[L] + ((j - 1) >> 1)) * TASKP + 4 * qc];
                    } else {
                        float4 pv = *(const float4*)&Pyr[(parO[L] + (j >> 1) - 1) * TASKP + 4 * qc];
                        float4 cv = *(const float4*)&Pyr[(dstO[L] + j) * TASKP + 4 * qc];
                        v = fadd4(pv, cv);
                    }
                    *(float4*)&Pyr[(dstO[L] + j) * TASKP + 4 * qc] = v;
                }
            }
            __syncthreads();
        }
    }

    // ---- Walk: chunked segments, boundaries shared via registers ----
    double lossAcc = 0.0; unsigned int cnt = 0u;
    {
        int s = tid & 3, w = tid >> 2;   // w in 0..63
        int slot, sub;
        if (w < 21)      { slot = 0; sub = w; }
        else if (w < 42) { slot = 1; sub = w - 21; }
        else if (w < 63) { slot = 2; sub = w - 42; }
        else             { slot = 3; sub = 0; }
        int flags = flagS[s];

        // boundary: all 5 inclusive-scan values at position u (cs[u+1]); -1 -> 0
        auto bnd = [&](int u, float* o) {
            if (u < 0) {
#pragma unroll
                for (int q = 0; q < 5; q++) o[q] = 0.f;
            } else if (u & 1) {
                int row = (u - 1) >> 1;
#pragma unroll
                for (int q = 0; q < 5; q++) o[q] = Pyr[row * TASKP + q * 4 + s];
            } else {
                float2 tf = *(const float2*)&TF[u * TFP + 2 * s];
                if (u == 0) {
#pragma unroll
                    for (int q = 0; q < 5; q++) o[q] = prodq(tf.x, tf.y, q);
                } else {
                    int row = (u >> 1) - 1;
#pragma unroll
                    for (int q = 0; q < 5; q++)
                        o[q] = __fadd_rn(Pyr[row * TASKP + q * 4 + s],
                                         prodq(tf.x, tf.y, q));
                }
            }
        };
        auto ploss = [&](int nI, const float* c, const float* e) {
            float n   = (float)nI;
            float St  = __fsub_rn(e[0], c[0]);
            float Sf  = __fsub_rn(e[1], c[1]);
            float Stt = __fsub_rn(e[2], c[2]);
            float Sff = __fsub_rn(e[3], c[3]);
            float Stf = __fsub_rn(e[4], c[4]);
            float mt  = __fdiv_rn(St, n);
            float mf  = __fdiv_rn(Sf, n);
            float tvs = fmaxf(__fsub_rn(Stt, __fmul_rn(__fmul_rn(n, mt), mt)), 0.f);
            float fvs = fmaxf(__fsub_rn(Sff, __fmul_rn(__fmul_rn(n, mf), mf)), 0.f);
            float num = __fsub_rn(Stf, __fmul_rn(__fmul_rn(n, mt), mf));
            float den = __fadd_rn(__fsqrt_rn(__fmul_rn(tvs, fvs)), 1e-8f);
            float cl  = __fsub_rn(1.f, fabsf(__fdiv_rn(num, den)));
            float nm1 = __fsub_rn(n, 1.f);
            float tvar = __fdiv_rn(tvs, nm1);
            float fvar = __fdiv_rn(fvs, nm1);
            float vl  = __fdiv_rn(fabsf(__fsub_rn(tvar, fvar)), __fadd_rn(tvar, 1e-8f));
            float ml  = __fdiv_rn(fabsf(__fsub_rn(mt, mf)), __fadd_rn(fabsf(mt), 1e-8f));
            lossAcc += (double)__fadd_rn(__fadd_rn(cl, vl), ml);
            cnt++;
        };

        float cB[5], eB[5];
        if (slot < 3) {
            if ((flags >> slot) & 1) {
                int p = pP[slot * SBLK + s], ns = TT / p;
                int chunk = (ns + 20) / 21;
                int lo = sub * chunk;
                int hi = lo + chunk; if (hi > ns) hi = ns;
                if (lo < hi) {
                    bnd(lo * p - 1, cB);
                    for (int j = lo; j < hi; j++) {
                        bnd((j + 1) * p - 1, eB);
                        ploss(p, cB, eB);
#pragma unroll
                        for (int q = 0; q < 5; q++) cB[q] = eB[q];
                    }
                    if (hi == ns && ((flags >> (3 + slot)) & 1)) {
                        bnd(TT - 1, eB);
                        ploss(TT - ns * p, cB, eB);
                    }
                }
            }
        } else {
            if (flags & 64) {
                bnd(-1, cB);
                bnd(TT - 1, eB);
                ploss(TT, cB, eB);
            }
        }
    }

    // ---- Block reduce -> per-block partial slot (deterministic) ----
#pragma unroll
    for (int off = 16; off; off >>= 1) {
        lossAcc += __shfl_down_sync(0xffffffffu, lossAcc, off);
        mseAcc  += __shfl_down_sync(0xffffffffu, mseAcc,  off);
        cnt     += __shfl_down_sync(0xffffffffu, cnt,     off);
    }
    if (lane == 0) {
        redL[warp] = lossAcc; redM[warp] = (double)mseAcc; redCt[warp] = cnt;
    }
    __syncthreads();

    __shared__ unsigned int sLast;
    if (tid == 0) {
        double tL = 0.0, tM = 0.0; unsigned int tC = 0u;
#pragma unroll
        for (int w = 0; w < 8; w++) { tL += redL[w]; tM += redM[w]; tC += redCt[w]; }
        g_partL[blockIdx.x] = tL;
        g_partM[blockIdx.x] = tM;
        g_partC[blockIdx.x] = tC;
        __threadfence();
        sLast = (atomicAdd(&g_done, 1u) == (unsigned)(NBLK - 1));
    }
    __syncthreads();

    // ---- Last block: deterministic grand reduction ----
    if (sLast) {
        __threadfence();
        double L = 0.0, M = 0.0; unsigned long long C = 0ull;
        for (int i = tid; i < NBLK; i += NTHREADS) {
            L += g_partL[i]; M += g_partM[i]; C += (unsigned long long)g_partC[i];
        }
#pragma unroll
        for (int off = 16; off; off >>= 1) {
            L += __shfl_down_sync(0xffffffffu, L, off);
            M += __shfl_down_sync(0xffffffffu, M, off);
            C += __shfl_down_sync(0xffffffffu, C, off);
        }
        unsigned long long* sC = (unsigned long long*)(sm + OFF_U);  // reuse scratch
        if (lane == 0) { redL[warp] = L; redM[warp] = M; sC[warp] = C; }
        __syncthreads();
        if (tid == 0) {
            double tL = 0.0, tM = 0.0; unsigned long long tC = 0ull;
#pragma unroll
            for (int w = 0; w < 8; w++) { tL += redL[w]; tM += redM[w]; tC += sC[w]; }
            double mse = tM / (double)((long long)BDIM * TT * FDIM);
            double avg = (tC > 0ull) ? (tL / (double)tC) : 0.0;
            out[0] = (float)(0.5 * mse + 0.5 * avg);
            g_done = 0u;  // reset for next replay
        }
    }
}

extern "C" void kernel_launch(void* const* d_in, const int* in_sizes, int n_in,
                              void* d_out, int out_size) {
    const float* forecast = (const float*)d_in[0];
    const float* target   = (const float*)d_in[1];
    float* out = (float*)d_out;

    cudaFuncSetAttribute(ps_main, cudaFuncAttributeMaxDynamicSharedMemorySize, SMEM_BYTES);
    ps_main<<<NBLK, NTHREADS, SMEM_BYTES>>>(forecast, target, out);
}